// round 8
// baseline (speedup 1.0000x reference)
#include <cuda_runtime.h>
#include <cuda_bf16.h>
#include <cstdint>

namespace {
constexpr int B = 8;
constexpr int N = 1024;
constexpr int C = 128;
constexpr float SCALEF = 20.0f;
constexpr float EPSF = 1e-12f;
constexpr float LOG2E = 1.4426950408889634f;
constexpr float K2 = 4.808983469629878f;   // log2(e)/0.3
constexpr int SNB = 16;                    // sinkhorn blocks per batch
constexpr int TPAD = 136;                  // NT smem row pad (bf16 elems)
constexpr int TSZ = 128 * TPAD;
constexpr int APAD = 72;                   // NN A-tile row pad
constexpr int VPAD = 136;                  // NN V-tile row pad
constexpr int AH_O = 0;
constexpr int AL_O = 128 * APAD;
constexpr int VH_O = AL_O + 128 * APAD;
constexpr int VL_O = VH_O + 64 * VPAD;
constexpr int NN_ELEMS = VL_O + 64 * VPAD;
constexpr float CONV_EPS = 1e-5f;
}

__device__ float g_scrA[(size_t)B * N * N];
__device__ float g_scrB[(size_t)B * N * N];
__device__ __nv_bfloat16 g_FnH[2 * B * N * C];
__device__ __nv_bfloat16 g_FnL[2 * B * N * C];
__device__ __nv_bfloat16 g_viaH[B * N * C];
__device__ __nv_bfloat16 g_viaL[B * N * C];
__device__ __nv_bfloat16 g_smH[(size_t)B * N * N];
__device__ __nv_bfloat16 g_smL[(size_t)B * N * N];
__device__ float2 g_cp[B * SNB * N];
__device__ float g_cd[B * SNB];
__device__ float g_r[B * N];
__device__ float g_c[B * N];
__device__ unsigned g_bar[B];
__device__ int g_correct;
__device__ float g_pL[B * N], g_pC[B * N], g_pP[B * N];

__device__ __forceinline__ float fex2(float x) {
    float y; asm("ex2.approx.ftz.f32 %0, %1;" : "=f"(y) : "f"(x)); return y;
}
__device__ __forceinline__ float flg2(float x) {
    float y; asm("lg2.approx.ftz.f32 %0, %1;" : "=f"(y) : "f"(x)); return y;
}
__device__ __forceinline__ uint32_t smem_u32(const void* p) {
    uint32_t a;
    asm("{ .reg .u64 t; cvta.to.shared.u64 t, %1; cvt.u32.u64 %0, t; }"
        : "=r"(a) : "l"(p));
    return a;
}
__device__ __forceinline__ void ldm4(uint32_t& r0, uint32_t& r1, uint32_t& r2,
                                     uint32_t& r3, uint32_t addr) {
    asm volatile("ldmatrix.sync.aligned.m8n8.x4.shared.b16 {%0,%1,%2,%3}, [%4];"
                 : "=r"(r0), "=r"(r1), "=r"(r2), "=r"(r3) : "r"(addr));
}
__device__ __forceinline__ void ldm4t(uint32_t& r0, uint32_t& r1, uint32_t& r2,
                                      uint32_t& r3, uint32_t addr) {
    asm volatile("ldmatrix.sync.aligned.m8n8.x4.trans.shared.b16 {%0,%1,%2,%3}, [%4];"
                 : "=r"(r0), "=r"(r1), "=r"(r2), "=r"(r3) : "r"(addr));
}
__device__ __forceinline__ void mma16816(float* c, const uint32_t* a,
                                         uint32_t b0, uint32_t b1) {
    asm volatile(
        "mma.sync.aligned.m16n8k16.row.col.f32.bf16.bf16.f32 "
        "{%0,%1,%2,%3}, {%4,%5,%6,%7}, {%8,%9}, {%0,%1,%2,%3};"
        : "+f"(c[0]), "+f"(c[1]), "+f"(c[2]), "+f"(c[3])
        : "r"(a[0]), "r"(a[1]), "r"(a[2]), "r"(a[3]), "r"(b0), "r"(b1));
}
__device__ __forceinline__ void hilo(float v, __nv_bfloat16& h, __nv_bfloat16& l) {
    h = __float2bfloat16(v);
    l = __float2bfloat16(v - __bfloat162float(h));
}
__device__ __forceinline__ void onl(float& mx, float& s, float x) {
    if (x <= mx) {
        s += fex2(x - mx);
    } else {
        s = fmaf(s, fex2(mx - x), 1.0f);
        mx = x;
    }
}
__device__ __forceinline__ void comb(float& mx, float& s, float m2, float s2) {
    float nm = fmaxf(mx, m2);
    s = s * fex2(mx - nm) + s2 * fex2(m2 - nm);
    mx = nm;
}

// ---------------------------------------------------------------------------
__global__ void k_init() {
    int i = blockIdx.x * blockDim.x + threadIdx.x;
    if (i < B * N) { g_r[i] = 0.f; g_c[i] = 0.f; }
    if (i < B) g_bar[i] = 0u;
    if (i == 0) g_correct = 0;
}

__global__ void __launch_bounds__(128) k_norm(const float* __restrict__ feats) {
    int row = blockIdx.x;
    const float* p = feats + (size_t)row * C;
    float v = p[threadIdx.x];
    float s = v * v;
    #pragma unroll
    for (int o = 16; o; o >>= 1) s += __shfl_xor_sync(0xffffffffu, s, o);
    __shared__ float sh[4];
    if ((threadIdx.x & 31) == 0) sh[threadIdx.x >> 5] = s;
    __syncthreads();
    s = sh[0] + sh[1] + sh[2] + sh[3];
    float scl = SCALEF / fmaxf(sqrtf(s), EPSF);
    float val = v * scl;
    size_t idx = (size_t)row * C + threadIdx.x;
    __nv_bfloat16 h, l;
    hilo(val, h, l);
    g_FnH[idx] = h;
    g_FnL[idx] = l;
}

// ---------------------------------------------------------------------------
// HMMA NT gemm, bf16-split 3 terms: D = AhiBhi^T + AhiBlo^T + AloBhi^T, K=128
__global__ void __launch_bounds__(256) k_hmma_nt(int mode) {
    extern __shared__ __nv_bfloat16 smem[];
    int ia = blockIdx.x, ib = blockIdx.y, b = blockIdx.z;
    int tid = threadIdx.x, wid = tid >> 5, lane = tid & 31;

    const __nv_bfloat16 *aHg, *aLg; float* dst;
    int fsB;
    if (mode == 0) {
        aHg = g_FnH + (size_t)(2 * b) * N * C;
        aLg = g_FnL + (size_t)(2 * b) * N * C;
        fsB = 2 * ((b + 1) & 7);
        dst = g_scrA;
    } else if (mode == 1) {
        aHg = g_viaH + (size_t)b * N * C;
        aLg = g_viaL + (size_t)b * N * C;
        fsB = 2 * b + 1;
        dst = g_scrA;
    } else {
        aHg = g_FnH + (size_t)(2 * b) * N * C;
        aLg = g_FnL + (size_t)(2 * b) * N * C;
        fsB = 2 * b + 1;
        dst = g_scrB;
    }
    const __nv_bfloat16* bHg = g_FnH + (size_t)fsB * N * C;
    const __nv_bfloat16* bLg = g_FnL + (size_t)fsB * N * C;
    aHg += (size_t)ia * 128 * C; aLg += (size_t)ia * 128 * C;
    bHg += (size_t)ib * 128 * C; bLg += (size_t)ib * 128 * C;

    {
        const uint4* src[4] = {(const uint4*)aHg, (const uint4*)aLg,
                               (const uint4*)bHg, (const uint4*)bLg};
        #pragma unroll
        for (int t4 = 0; t4 < 4; t4++) {
            __nv_bfloat16* dtile = smem + t4 * TSZ;
            #pragma unroll
            for (int i = 0; i < 8; i++) {
                int idx = tid + 256 * i;
                int row = idx >> 4, c8 = idx & 15;
                *(uint4*)(dtile + row * TPAD + c8 * 8) = src[t4][idx];
            }
        }
    }
    __syncthreads();

    int wm = wid & 3, wn = wid >> 2;
    float acc[2][8][4];
    #pragma unroll
    for (int mi = 0; mi < 2; mi++)
        #pragma unroll
        for (int nj = 0; nj < 8; nj++)
            #pragma unroll
            for (int q = 0; q < 4; q++) acc[mi][nj][q] = 0.f;

    uint32_t sbase = smem_u32(smem);
    const int selA[3] = {0, 0, 1};
    const int selB[3] = {2, 3, 2};
    int a_r = lane & 15, a_c = (lane >> 4) << 3;
    int b_r = (lane & 7) + ((lane >> 4) << 3);
    int b_c = ((lane >> 3) & 1) << 3;

    #pragma unroll
    for (int t = 0; t < 3; t++) {
        uint32_t aB = sbase + selA[t] * TSZ * 2;
        uint32_t bBs = sbase + selB[t] * TSZ * 2;
        #pragma unroll
        for (int k8 = 0; k8 < 8; k8++) {
            int kc = k8 * 16;
            uint32_t af[2][4];
            #pragma unroll
            for (int mi = 0; mi < 2; mi++) {
                int row = wm * 32 + mi * 16 + a_r;
                ldm4(af[mi][0], af[mi][1], af[mi][2], af[mi][3],
                     aB + (row * TPAD + kc + a_c) * 2);
            }
            uint32_t bf[4][4];
            #pragma unroll
            for (int nj = 0; nj < 4; nj++) {
                int row = wn * 64 + nj * 16 + b_r;
                ldm4(bf[nj][0], bf[nj][1], bf[nj][2], bf[nj][3],
                     bBs + (row * TPAD + kc + b_c) * 2);
            }
            #pragma unroll
            for (int mi = 0; mi < 2; mi++)
                #pragma unroll
                for (int nj = 0; nj < 4; nj++) {
                    mma16816(acc[mi][2 * nj], af[mi], bf[nj][0], bf[nj][1]);
                    mma16816(acc[mi][2 * nj + 1], af[mi], bf[nj][2], bf[nj][3]);
                }
        }
    }

    {
        int rbase = b * 1024 + ia * 128 + wm * 32 + (lane >> 2);
        int cbase = ib * 128 + wn * 64 + 2 * (lane & 3);
        #pragma unroll
        for (int mi = 0; mi < 2; mi++)
            #pragma unroll
            for (int nj = 0; nj < 8; nj++) {
                float* d0 = dst + (size_t)(rbase + mi * 16) * 1024 + cbase + nj * 8;
                *(float2*)d0 = make_float2(acc[mi][nj][0], acc[mi][nj][1]);
                float* d1 = d0 + 8 * 1024;
                *(float2*)d1 = make_float2(acc[mi][nj][2], acc[mi][nj][3]);
            }
    }
}

// ---------------------------------------------------------------------------
// row softmax of corr_1a (fp32 in scrA) -> bf16 hi/lo smcorr
__global__ void __launch_bounds__(256) k_rowsoftmax() {
    size_t row = blockIdx.x;
    const float4* p = (const float4*)(g_scrA + row * N);
    int tid = threadIdx.x, lane = tid & 31;
    float4 v = p[tid];
    float mx = fmaxf(fmaxf(v.x, v.y), fmaxf(v.z, v.w));
    #pragma unroll
    for (int o = 16; o; o >>= 1) mx = fmaxf(mx, __shfl_xor_sync(0xffffffffu, mx, o));
    __shared__ float shm[8], shs[8];
    if (lane == 0) shm[tid >> 5] = mx;
    __syncthreads();
    mx = fmaxf(fmaxf(fmaxf(shm[0], shm[1]), fmaxf(shm[2], shm[3])),
               fmaxf(fmaxf(shm[4], shm[5]), fmaxf(shm[6], shm[7])));
    float4 e;
    e.x = fex2((v.x - mx) * LOG2E);
    e.y = fex2((v.y - mx) * LOG2E);
    e.z = fex2((v.z - mx) * LOG2E);
    e.w = fex2((v.w - mx) * LOG2E);
    float s = e.x + e.y + e.z + e.w;
    #pragma unroll
    for (int o = 16; o; o >>= 1) s += __shfl_xor_sync(0xffffffffu, s, o);
    if (lane == 0) shs[tid >> 5] = s;
    __syncthreads();
    s = shs[0] + shs[1] + shs[2] + shs[3] + shs[4] + shs[5] + shs[6] + shs[7];
    float inv = 1.0f / s;
    float f[4] = {e.x * inv, e.y * inv, e.z * inv, e.w * inv};
    __nv_bfloat16 h[4], l[4];
    #pragma unroll
    for (int q = 0; q < 4; q++) hilo(f[q], h[q], l[q]);
    __nv_bfloat162* dH = (__nv_bfloat162*)(g_smH + row * N + 4 * tid);
    __nv_bfloat162* dL = (__nv_bfloat162*)(g_smL + row * N + 4 * tid);
    dH[0] = __nv_bfloat162{h[0], h[1]};
    dH[1] = __nv_bfloat162{h[2], h[3]};
    dL[0] = __nv_bfloat162{l[0], l[1]};
    dL[1] = __nv_bfloat162{l[2], l[3]};
}

// ---------------------------------------------------------------------------
// HMMA NN gemm: via[b] = smcorr[b] @ fa[b]; out hi/lo
__global__ void __launch_bounds__(256) k_hmma_nn() {
    extern __shared__ __nv_bfloat16 smem[];
    int rb = blockIdx.x, b = blockIdx.y;
    int tid = threadIdx.x, wid = tid >> 5, lane = tid & 31;
    int fs = 2 * ((b + 1) & 7);

    int wm = wid & 3, wn = wid >> 2;
    float acc[2][8][4];
    #pragma unroll
    for (int mi = 0; mi < 2; mi++)
        #pragma unroll
        for (int nj = 0; nj < 8; nj++)
            #pragma unroll
            for (int q = 0; q < 4; q++) acc[mi][nj][q] = 0.f;

    uint32_t sbase = smem_u32(smem);
    const int AOFF[3] = {AH_O, AH_O, AL_O};
    const int VOFF[3] = {VH_O, VL_O, VH_O};
    int a_r = lane & 15, a_c = (lane >> 4) << 3;
    int bt_r = (lane & 7) + (((lane >> 3) & 1) << 3);
    int bt_c = (lane >> 4) << 3;

    for (int kc = 0; kc < 16; kc++) {
        int kb = kc * 64;
        if (kc) __syncthreads();
        #pragma unroll
        for (int i = 0; i < 4; i++) {
            int idx = tid + 256 * i;
            int r = idx >> 3, c8 = idx & 7;
            size_t so = (size_t)(b * 1024 + rb * 128 + r) * 1024 + kb + c8 * 8;
            *(uint4*)(smem + AH_O + r * APAD + c8 * 8) = *(const uint4*)(g_smH + so);
            *(uint4*)(smem + AL_O + r * APAD + c8 * 8) = *(const uint4*)(g_smL + so);
        }
        #pragma unroll
        for (int i = 0; i < 4; i++) {
            int idx = tid + 256 * i;
            int r = idx >> 4, c8 = idx & 15;
            size_t so = (size_t)(fs * 1024 + kb + r) * 128 + c8 * 8;
            *(uint4*)(smem + VH_O + r * VPAD + c8 * 8) = *(const uint4*)(g_FnH + so);
            *(uint4*)(smem + VL_O + r * VPAD + c8 * 8) = *(const uint4*)(g_FnL + so);
        }
        __syncthreads();

        #pragma unroll
        for (int t = 0; t < 3; t++) {
            #pragma unroll
            for (int k16 = 0; k16 < 4; k16++) {
                int kk = k16 * 16;
                uint32_t af[2][4];
                #pragma unroll
                for (int mi = 0; mi < 2; mi++) {
                    int row = wm * 32 + mi * 16 + a_r;
                    ldm4(af[mi][0], af[mi][1], af[mi][2], af[mi][3],
                         sbase + (AOFF[t] + row * APAD + kk + a_c) * 2);
                }
                uint32_t bf[4][4];
                #pragma unroll
                for (int nj = 0; nj < 4; nj++) {
                    int krow = kk + bt_r;
                    int ccol = wn * 64 + nj * 16 + bt_c;
                    ldm4t(bf[nj][0], bf[nj][1], bf[nj][2], bf[nj][3],
                          sbase + (VOFF[t] + krow * VPAD + ccol) * 2);
                }
                #pragma unroll
                for (int mi = 0; mi < 2; mi++)
                    #pragma unroll
                    for (int nj = 0; nj < 4; nj++) {
                        mma16816(acc[mi][2 * nj], af[mi], bf[nj][0], bf[nj][1]);
                        mma16816(acc[mi][2 * nj + 1], af[mi], bf[nj][2], bf[nj][3]);
                    }
            }
        }
    }

    {
        int rbase = b * 1024 + rb * 128 + wm * 32 + (lane >> 2);
        int cbase = wn * 64 + 2 * (lane & 3);
        #pragma unroll
        for (int mi = 0; mi < 2; mi++)
            #pragma unroll
            for (int nj = 0; nj < 8; nj++) {
                #pragma unroll
                for (int half = 0; half < 2; half++) {
                    int row = rbase + mi * 16 + half * 8;
                    int col = cbase + nj * 8;
                    float v0 = acc[mi][nj][2 * half], v1 = acc[mi][nj][2 * half + 1];
                    __nv_bfloat16 h0, l0, h1, l1;
                    hilo(v0, h0, l0);
                    hilo(v1, h1, l1);
                    size_t o = (size_t)row * C + col;
                    *(__nv_bfloat162*)(g_viaH + o) = __nv_bfloat162{h0, h1};
                    *(__nv_bfloat162*)(g_viaL + o) = __nv_bfloat162{l0, l1};
                }
            }
    }
}

// ---------------------------------------------------------------------------
__device__ __forceinline__ void batch_bar(int b, unsigned target) {
    __syncthreads();
    if (threadIdx.x == 0) {
        __threadfence();
        atomicAdd(&g_bar[b], 1u);
        volatile unsigned* vb = (volatile unsigned*)&g_bar[b];
        while (*vb < target) { }
        __threadfence();
    }
    __syncthreads();
}

// persistent sinkhorn: 512 threads/block, single M read/iter, 4-way split
// column accumulator chains, per-batch convergence early exit (cap 30).
__global__ void __launch_bounds__(512) k_sinkhorn() {
    int b = blockIdx.x >> 4, sub = blockIdx.x & 15;
    const float* Mrows = g_scrA + (size_t)(b * 1024 + sub * 64) * N;
    int tid = threadIdx.x, warp = tid >> 5, lane = tid & 31;
    __shared__ float2 rp[8][512];
    __shared__ float rsm[64];
    __shared__ float sdel[2];
    __shared__ int sbrk;
    unsigned bar_t = 0;

    for (int it = 0; it < 30; it++) {
        float2 cc = *(const float2*)(g_c + b * N + 2 * tid);
        float cmx[4] = {-1e30f, -1e30f, -1e30f, -1e30f};
        float cs[4] = {0.f, 0.f, 0.f, 0.f};
        float cmy[4] = {-1e30f, -1e30f, -1e30f, -1e30f};
        float cy[4] = {0.f, 0.f, 0.f, 0.f};

        for (int g = 0; g < 8; g++) {
            float2 z[8];
            #pragma unroll
            for (int rr = 0; rr < 8; rr++) {
                float2 y = *(const float2*)(Mrows + (size_t)(g * 8 + rr) * N + 2 * tid);
                z[rr] = make_float2(y.x * K2, y.y * K2);
            }
            // per-thread pair partial (1 ex2): (mx, s)
            #pragma unroll
            for (int rr = 0; rr < 8; rr++) {
                float a0 = z[rr].x + cc.x, a1 = z[rr].y + cc.y;
                float mx = fmaxf(a0, a1);
                float s = 1.0f + fex2(fminf(a0, a1) - mx);
                rp[rr][tid] = make_float2(mx, s);
            }
            __syncthreads();
            // warps 0..7: warp rr reduces row rr (512 partials)
            if (warp < 8) {
                float mx = -1e30f, s = 0.f;
                #pragma unroll
                for (int i = 0; i < 16; i++) {
                    float2 p2 = rp[warp][lane + 32 * i];
                    comb(mx, s, p2.x, p2.y);
                }
                #pragma unroll
                for (int o = 16; o; o >>= 1) {
                    float m2 = __shfl_xor_sync(0xffffffffu, mx, o);
                    float s2 = __shfl_xor_sync(0xffffffffu, s, o);
                    comb(mx, s, m2, s2);
                }
                if (lane == 0) rsm[g * 8 + warp] = -(mx + flg2(s));
            }
            __syncthreads();
            // column accumulation, 4 independent chains
            #pragma unroll
            for (int rr = 0; rr < 8; rr++) {
                float rv = rsm[g * 8 + rr];
                int q = rr & 3;
                onl(cmx[q], cs[q], z[rr].x + rv);
                onl(cmy[q], cy[q], z[rr].y + rv);
            }
        }
        // combine 4 chains, publish partials for 2 columns
        comb(cmx[0], cs[0], cmx[1], cs[1]);
        comb(cmx[2], cs[2], cmx[3], cs[3]);
        comb(cmx[0], cs[0], cmx[2], cs[2]);
        comb(cmy[0], cy[0], cmy[1], cy[1]);
        comb(cmy[2], cy[2], cmy[3], cy[3]);
        comb(cmy[0], cy[0], cmy[2], cy[2]);
        float2* cp = g_cp + (b * 16 + sub) * N;
        cp[2 * tid] = make_float2(cmx[0], cs[0]);
        cp[2 * tid + 1] = make_float2(cmy[0], cy[0]);
        bar_t += SNB; batch_bar(b, bar_t);

        // combine: this block owns columns [sub*64, sub*64+64)
        if (tid < 64) {
            int col = sub * 64 + tid;
            float mx = -1e30f, s = 0.f;
            #pragma unroll
            for (int k = 0; k < 16; k++) {
                float2 p2 = g_cp[(b * 16 + k) * N + col];
                comb(mx, s, p2.x, p2.y);
            }
            float nc = -(mx + flg2(s));
            float d = fabsf(nc - g_c[b * N + col]);
            g_c[b * N + col] = nc;
            #pragma unroll
            for (int o = 16; o; o >>= 1) d = fmaxf(d, __shfl_xor_sync(0xffffffffu, d, o));
            if (lane == 0) sdel[warp] = d;
        }
        __syncthreads();
        if (tid == 0) g_cd[b * 16 + sub] = fmaxf(sdel[0], sdel[1]);
        bar_t += SNB; batch_bar(b, bar_t);

        if (tid == 0) {
            float m = 0.f;
            #pragma unroll
            for (int k = 0; k < 16; k++) m = fmaxf(m, g_cd[b * 16 + k]);
            sbrk = (m < CONV_EPS) ? 1 : 0;
        }
        __syncthreads();
        if (sbrk && it < 29) break;
    }
    if (tid < 64) g_r[b * N + sub * 64 + tid] = rsm[tid];
}

// ---------------------------------------------------------------------------
// fused final pass: row stats + dist + softmaxes + sink
__global__ void __launch_bounds__(256) k_final(const float* __restrict__ pc0) {
    int rowi = blockIdx.x;
    int b = rowi >> 10, n = rowi & 1023;
    size_t row = rowi;
    const float* pA = g_scrA + row * N;
    const float* pB = g_scrB + row * N;
    int tid = threadIdx.x, lane = tid & 31, warp = tid >> 5;

    __shared__ float spc[3 * 1024];
    __shared__ float scv[1024];
    __shared__ float sred[8];
    __shared__ int sarg[8];
    __shared__ float sbc[4];
    const float* pc = pc0 + (size_t)b * N * 3;
    for (int i = tid; i < 3 * 1024; i += 256) spc[i] = pc[i];
    for (int i = tid; i < 1024; i += 256) scv[i] = g_c[b * N + i];

    float vA[4], vB[4];
    #pragma unroll
    for (int t = 0; t < 4; t++) {
        vA[t] = pA[tid + 256 * t];
        vB[t] = pB[tid + 256 * t];
    }

    float mx = -1e30f; int arg = 0;
    #pragma unroll
    for (int t = 0; t < 4; t++)
        if (vA[t] > mx) { mx = vA[t]; arg = tid + 256 * t; }
    #pragma unroll
    for (int o = 16; o; o >>= 1) {
        float om = __shfl_xor_sync(0xffffffffu, mx, o);
        int oa = __shfl_xor_sync(0xffffffffu, arg, o);
        if (om > mx || (om == mx && oa < arg)) { mx = om; arg = oa; }
    }
    if (lane == 0) { sred[warp] = mx; sarg[warp] = arg; }
    __syncthreads();
    if (tid == 0) {
        float bm = sred[0]; int ba = sarg[0];
        #pragma unroll
        for (int q = 1; q < 8; q++)
            if (sred[q] > bm || (sred[q] == bm && sarg[q] < ba)) { bm = sred[q]; ba = sarg[q]; }
        if (ba == n) atomicAdd(&g_correct, 1);
        sbc[0] = bm;
    }
    __syncthreads();
    float mA = sbc[0];
    float s = 0.f;
    #pragma unroll
    for (int t = 0; t < 4; t++) s += fex2((vA[t] - mA) * LOG2E);
    #pragma unroll
    for (int o = 16; o; o >>= 1) s += __shfl_xor_sync(0xffffffffu, s, o);
    if (lane == 0) sred[warp] = s;
    __syncthreads();
    if (tid == 0) {
        float t0 = 0.f;
        #pragma unroll
        for (int q = 0; q < 8; q++) t0 += sred[q];
        sbc[1] = t0;
    }
    __syncthreads();
    mx = -1e30f;
    #pragma unroll
    for (int t = 0; t < 4; t++) mx = fmaxf(mx, vB[t]);
    #pragma unroll
    for (int o = 16; o; o >>= 1) mx = fmaxf(mx, __shfl_xor_sync(0xffffffffu, mx, o));
    if (lane == 0) sred[warp] = mx;
    __syncthreads();
    if (tid == 0) {
        float bm = sred[0];
        #pragma unroll
        for (int q = 1; q < 8; q++) bm = fmaxf(bm, sred[q]);
        sbc[2] = bm;
    }
    __syncthreads();
    float mB = sbc[2];
    s = 0.f;
    #pragma unroll
    for (int t = 0; t < 4; t++) s += fex2((vB[t] - mB) * LOG2E);
    #pragma unroll
    for (int o = 16; o; o >>= 1) s += __shfl_xor_sync(0xffffffffu, s, o);
    if (lane == 0) sred[warp] = s;
    __syncthreads();
    if (tid == 0) {
        float t0 = 0.f;
        #pragma unroll
        for (int q = 0; q < 8; q++) t0 += sred[q];
        sbc[3] = t0;
    }
    __syncthreads();

    float iA = 1.0f / sbc[1];
    float iB = 1.0f / sbc[3];
    float rn = g_r[row];

    float px = spc[3 * n], py = spc[3 * n + 1], pz = spc[3 * n + 2];
    float aL = 0.f, aC = 0.f, aP = 0.f;
    #pragma unroll
    for (int t = 0; t < 4; t++) {
        int m = tid + 256 * t;
        float xA = vA[t], xB = vB[t];
        float smA = fex2((xA - mA) * LOG2E) * iA;
        float smB = fex2((xB - mB) * LOG2E) * iB;
        float dx = px - spc[3 * m], dy = py - spc[3 * m + 1], dz = pz - spc[3 * m + 2];
        float d2 = dx * dx + dy * dy + dz * dz;
        float dist = sqrtf(sqrtf(d2));
        aL += dist * (smA + smB);
        float sink = fex2(xA * K2 + rn + scv[m]);
        aC += fabsf(sink - smA);
        aP += (m == n) ? fabsf(1.0f - sink) : sink;
    }
    #pragma unroll
    for (int o = 16; o; o >>= 1) {
        aL += __shfl_xor_sync(0xffffffffu, aL, o);
        aC += __shfl_xor_sync(0xffffffffu, aC, o);
        aP += __shfl_xor_sync(0xffffffffu, aP, o);
    }
    __shared__ float s1[8], s2[8], s3[8];
    if (lane == 0) { s1[warp] = aL; s2[warp] = aC; s3[warp] = aP; }
    __syncthreads();
    if (tid == 0) {
        float tL = 0.f, tC = 0.f, tP = 0.f;
        #pragma unroll
        for (int q = 0; q < 8; q++) { tL += s1[q]; tC += s2[q]; tP += s3[q]; }
        g_pL[row] = tL; g_pC[row] = tC; g_pP[row] = tP;
    }
}

// ---------------------------------------------------------------------------
__global__ void __launch_bounds__(256) k_out(float* __restrict__ out) {
    int tid = threadIdx.x;
    float sL = 0.f, sC = 0.f, sP = 0.f;
    for (int i = tid; i < B * N; i += 256) {
        sL += g_pL[i]; sC += g_pC[i]; sP += g_pP[i];
    }
    #pragma unroll
    for (int o = 16; o; o >>= 1) {
        sL += __shfl_xor_sync(0xffffffffu, sL, o);
        sC += __shfl_xor_sync(0xffffffffu, sC, o);
        sP += __shfl_xor_sync(0xffffffffu, sP, o);
    }
    __shared__ float s1[8], s2[8], s3[8];
    if ((tid & 31) == 0) { s1[tid >> 5] = sL; s2[tid >> 5] = sC; s3[tid >> 5] = sP; }
    __syncthreads();
    if (tid == 0) {
        float tL = 0.f, tC = 0.f, tP = 0.f;
        #pragma unroll
        for (int q = 0; q < 8; q++) { tL += s1[q]; tC += s2[q]; tP += s3[q]; }
        float invN = 1.0f / (float)N;
        float loss = tL * invN;
        float Lc = 3.0f * tC * invN;
        float perm = 3.0f * tP * invN;
        float corr = (float)g_correct;
        float invB = 1.0f / (float)B;
        out[0] = (loss + Lc) * invB;
        out[1] = loss * invB;
        out[2] = Lc * invB;
        out[3] = corr * invB;
        out[4] = perm * invB;
    }
}

// ---------------------------------------------------------------------------
extern "C" void kernel_launch(void* const* d_in, const int* in_sizes, int n_in,
                              void* d_out, int out_size) {
    const float* feats = (const float*)d_in[0];
    const float* pc0 = (const float*)d_in[1];
    float* out = (float*)d_out;

    const int nt_smem = 4 * TSZ * sizeof(__nv_bfloat16);
    const int nn_smem = NN_ELEMS * sizeof(__nv_bfloat16);
    static bool attr_done = false;
    if (!attr_done) {
        cudaFuncSetAttribute(k_hmma_nt, cudaFuncAttributeMaxDynamicSharedMemorySize,
                             nt_smem);
        cudaFuncSetAttribute(k_hmma_nn, cudaFuncAttributeMaxDynamicSharedMemorySize,
                             nn_smem);
        attr_done = true;
    }

    k_init<<<32, 256>>>();
    k_norm<<<2 * B * N, 128>>>(feats);
    k_hmma_nt<<<dim3(8, 8, 8), 256, nt_smem>>>(0);   // corr_1a -> scrA
    k_rowsoftmax<<<B * N, 256>>>();                  // smcorr hi/lo bf16
    k_hmma_nn<<<dim3(8, 8), 256, nn_smem>>>();       // via hi/lo
    k_hmma_nt<<<dim3(8, 8, 8), 256, nt_smem>>>(1);   // corr_1a2 -> scrA
    k_hmma_nt<<<dim3(8, 8, 8), 256, nt_smem>>>(2);   // corr_12 -> scrB
    k_sinkhorn<<<B * SNB, 512>>>();
    k_final<<<B * N, 256>>>(pc0);
    k_out<<<1, 256>>>(out);
}

// round 9
// speedup vs baseline: 1.1144x; 1.1144x over previous
#include <cuda_runtime.h>
#include <cuda_bf16.h>
#include <cstdint>

namespace {
constexpr int B = 8;
constexpr int N = 1024;
constexpr int C = 128;
constexpr float SCALEF = 20.0f;
constexpr float EPSF = 1e-12f;
constexpr float LOG2E = 1.4426950408889634f;
constexpr float K2 = 4.808983469629878f;   // log2(e)/0.3
constexpr int SNB = 16;                    // sinkhorn blocks per batch
constexpr int TPAD = 136;                  // NT smem row pad (bf16 elems)
constexpr int TSZ = 128 * TPAD;
constexpr int APAD = 72;                   // NN A-tile row pad
constexpr int VPAD = 136;                  // NN V-tile row pad
constexpr int AH_O = 0;
constexpr int AL_O = 128 * APAD;
constexpr int VH_O = AL_O + 128 * APAD;
constexpr int VL_O = VH_O + 64 * VPAD;
constexpr int NN_ELEMS = VL_O + 64 * VPAD;
}

__device__ float g_scrA[(size_t)B * N * N];
__device__ float g_scrB[(size_t)B * N * N];
__device__ __nv_bfloat16 g_FnH[2 * B * N * C];
__device__ __nv_bfloat16 g_FnL[2 * B * N * C];
__device__ __nv_bfloat16 g_viaH[B * N * C];
__device__ __nv_bfloat16 g_viaL[B * N * C];
__device__ __nv_bfloat16 g_smH[(size_t)B * N * N];
__device__ __nv_bfloat16 g_smL[(size_t)B * N * N];
__device__ float2 g_cp[2 * B * SNB * N];   // double-buffered column partials
__device__ float g_r[B * N];
__device__ float g_c[B * N];
__device__ unsigned g_bar[B];
__device__ int g_correct;
__device__ float g_pL[B * N], g_pC[B * N], g_pP[B * N];

__device__ __forceinline__ float fex2(float x) {
    float y; asm("ex2.approx.ftz.f32 %0, %1;" : "=f"(y) : "f"(x)); return y;
}
__device__ __forceinline__ float flg2(float x) {
    float y; asm("lg2.approx.ftz.f32 %0, %1;" : "=f"(y) : "f"(x)); return y;
}
__device__ __forceinline__ uint32_t smem_u32(const void* p) {
    uint32_t a;
    asm("{ .reg .u64 t; cvta.to.shared.u64 t, %1; cvt.u32.u64 %0, t; }"
        : "=r"(a) : "l"(p));
    return a;
}
__device__ __forceinline__ void ldm4(uint32_t& r0, uint32_t& r1, uint32_t& r2,
                                     uint32_t& r3, uint32_t addr) {
    asm volatile("ldmatrix.sync.aligned.m8n8.x4.shared.b16 {%0,%1,%2,%3}, [%4];"
                 : "=r"(r0), "=r"(r1), "=r"(r2), "=r"(r3) : "r"(addr));
}
__device__ __forceinline__ void ldm4t(uint32_t& r0, uint32_t& r1, uint32_t& r2,
                                      uint32_t& r3, uint32_t addr) {
    asm volatile("ldmatrix.sync.aligned.m8n8.x4.trans.shared.b16 {%0,%1,%2,%3}, [%4];"
                 : "=r"(r0), "=r"(r1), "=r"(r2), "=r"(r3) : "r"(addr));
}
__device__ __forceinline__ void mma16816(float* c, const uint32_t* a,
                                         uint32_t b0, uint32_t b1) {
    asm volatile(
        "mma.sync.aligned.m16n8k16.row.col.f32.bf16.bf16.f32 "
        "{%0,%1,%2,%3}, {%4,%5,%6,%7}, {%8,%9}, {%0,%1,%2,%3};"
        : "+f"(c[0]), "+f"(c[1]), "+f"(c[2]), "+f"(c[3])
        : "r"(a[0]), "r"(a[1]), "r"(a[2]), "r"(a[3]), "r"(b0), "r"(b1));
}
__device__ __forceinline__ void hilo(float v, __nv_bfloat16& h, __nv_bfloat16& l) {
    h = __float2bfloat16(v);
    l = __float2bfloat16(v - __bfloat162float(h));
}
__device__ __forceinline__ void onl(float& mx, float& s, float x) {
    if (x <= mx) {
        s += fex2(x - mx);
    } else {
        s = fmaf(s, fex2(mx - x), 1.0f);
        mx = x;
    }
}
__device__ __forceinline__ void comb(float& mx, float& s, float m2, float s2) {
    float nm = fmaxf(mx, m2);
    s = s * fex2(mx - nm) + s2 * fex2(m2 - nm);
    mx = nm;
}

// ---------------------------------------------------------------------------
__global__ void k_init() {
    int i = blockIdx.x * blockDim.x + threadIdx.x;
    if (i < B * N) { g_r[i] = 0.f; g_c[i] = 0.f; }
    if (i < B) g_bar[i] = 0u;
    if (i == 0) g_correct = 0;
}

__global__ void __launch_bounds__(128) k_norm(const float* __restrict__ feats) {
    int row = blockIdx.x;
    const float* p = feats + (size_t)row * C;
    float v = p[threadIdx.x];
    float s = v * v;
    #pragma unroll
    for (int o = 16; o; o >>= 1) s += __shfl_xor_sync(0xffffffffu, s, o);
    __shared__ float sh[4];
    if ((threadIdx.x & 31) == 0) sh[threadIdx.x >> 5] = s;
    __syncthreads();
    s = sh[0] + sh[1] + sh[2] + sh[3];
    float scl = SCALEF / fmaxf(sqrtf(s), EPSF);
    float val = v * scl;
    size_t idx = (size_t)row * C + threadIdx.x;
    __nv_bfloat16 h, l;
    hilo(val, h, l);
    g_FnH[idx] = h;
    g_FnL[idx] = l;
}

// ---------------------------------------------------------------------------
// HMMA NT gemm, bf16-split 3 terms. mode 0: corr_1a; mode 3: fused 1+2.
__global__ void __launch_bounds__(256) k_hmma_nt(int mode) {
    extern __shared__ __nv_bfloat16 smem[];
    int ia = blockIdx.x, ib = blockIdx.y;
    int b = blockIdx.z & 7;
    int m = mode;
    if (mode == 3) m = (blockIdx.z < 8) ? 1 : 2;
    int tid = threadIdx.x, wid = tid >> 5, lane = tid & 31;

    const __nv_bfloat16 *aHg, *aLg; float* dst;
    int fsB;
    if (m == 0) {
        aHg = g_FnH + (size_t)(2 * b) * N * C;
        aLg = g_FnL + (size_t)(2 * b) * N * C;
        fsB = 2 * ((b + 1) & 7);
        dst = g_scrA;
    } else if (m == 1) {
        aHg = g_viaH + (size_t)b * N * C;
        aLg = g_viaL + (size_t)b * N * C;
        fsB = 2 * b + 1;
        dst = g_scrA;
    } else {
        aHg = g_FnH + (size_t)(2 * b) * N * C;
        aLg = g_FnL + (size_t)(2 * b) * N * C;
        fsB = 2 * b + 1;
        dst = g_scrB;
    }
    const __nv_bfloat16* bHg = g_FnH + (size_t)fsB * N * C;
    const __nv_bfloat16* bLg = g_FnL + (size_t)fsB * N * C;
    aHg += (size_t)ia * 128 * C; aLg += (size_t)ia * 128 * C;
    bHg += (size_t)ib * 128 * C; bLg += (size_t)ib * 128 * C;

    {
        const uint4* src[4] = {(const uint4*)aHg, (const uint4*)aLg,
                               (const uint4*)bHg, (const uint4*)bLg};
        #pragma unroll
        for (int t4 = 0; t4 < 4; t4++) {
            __nv_bfloat16* dtile = smem + t4 * TSZ;
            #pragma unroll
            for (int i = 0; i < 8; i++) {
                int idx = tid + 256 * i;
                int row = idx >> 4, c8 = idx & 15;
                *(uint4*)(dtile + row * TPAD + c8 * 8) = src[t4][idx];
            }
        }
    }
    __syncthreads();

    int wm = wid & 3, wn = wid >> 2;
    float acc[2][8][4];
    #pragma unroll
    for (int mi = 0; mi < 2; mi++)
        #pragma unroll
        for (int nj = 0; nj < 8; nj++)
            #pragma unroll
            for (int q = 0; q < 4; q++) acc[mi][nj][q] = 0.f;

    uint32_t sbase = smem_u32(smem);
    const int selA[3] = {0, 0, 1};
    const int selB[3] = {2, 3, 2};
    int a_r = lane & 15, a_c = (lane >> 4) << 3;
    int b_r = (lane & 7) + ((lane >> 4) << 3);
    int b_c = ((lane >> 3) & 1) << 3;

    #pragma unroll
    for (int t = 0; t < 3; t++) {
        uint32_t aB = sbase + selA[t] * TSZ * 2;
        uint32_t bBs = sbase + selB[t] * TSZ * 2;
        #pragma unroll
        for (int k8 = 0; k8 < 8; k8++) {
            int kc = k8 * 16;
            uint32_t af[2][4];
            #pragma unroll
            for (int mi = 0; mi < 2; mi++) {
                int row = wm * 32 + mi * 16 + a_r;
                ldm4(af[mi][0], af[mi][1], af[mi][2], af[mi][3],
                     aB + (row * TPAD + kc + a_c) * 2);
            }
            uint32_t bf[4][4];
            #pragma unroll
            for (int nj = 0; nj < 4; nj++) {
                int row = wn * 64 + nj * 16 + b_r;
                ldm4(bf[nj][0], bf[nj][1], bf[nj][2], bf[nj][3],
                     bBs + (row * TPAD + kc + b_c) * 2);
            }
            #pragma unroll
            for (int mi = 0; mi < 2; mi++)
                #pragma unroll
                for (int nj = 0; nj < 4; nj++) {
                    mma16816(acc[mi][2 * nj], af[mi], bf[nj][0], bf[nj][1]);
                    mma16816(acc[mi][2 * nj + 1], af[mi], bf[nj][2], bf[nj][3]);
                }
        }
    }

    {
        int rbase = b * 1024 + ia * 128 + wm * 32 + (lane >> 2);
        int cbase = ib * 128 + wn * 64 + 2 * (lane & 3);
        #pragma unroll
        for (int mi = 0; mi < 2; mi++)
            #pragma unroll
            for (int nj = 0; nj < 8; nj++) {
                float* d0 = dst + (size_t)(rbase + mi * 16) * 1024 + cbase + nj * 8;
                *(float2*)d0 = make_float2(acc[mi][nj][0], acc[mi][nj][1]);
                float* d1 = d0 + 8 * 1024;
                *(float2*)d1 = make_float2(acc[mi][nj][2], acc[mi][nj][3]);
            }
    }
}

// ---------------------------------------------------------------------------
// row softmax of corr_1a (fp32 in scrA) -> bf16 hi/lo smcorr
__global__ void __launch_bounds__(256) k_rowsoftmax() {
    size_t row = blockIdx.x;
    const float4* p = (const float4*)(g_scrA + row * N);
    int tid = threadIdx.x, lane = tid & 31;
    float4 v = p[tid];
    float mx = fmaxf(fmaxf(v.x, v.y), fmaxf(v.z, v.w));
    #pragma unroll
    for (int o = 16; o; o >>= 1) mx = fmaxf(mx, __shfl_xor_sync(0xffffffffu, mx, o));
    __shared__ float shm[8], shs[8];
    if (lane == 0) shm[tid >> 5] = mx;
    __syncthreads();
    mx = fmaxf(fmaxf(fmaxf(shm[0], shm[1]), fmaxf(shm[2], shm[3])),
               fmaxf(fmaxf(shm[4], shm[5]), fmaxf(shm[6], shm[7])));
    float4 e;
    e.x = fex2((v.x - mx) * LOG2E);
    e.y = fex2((v.y - mx) * LOG2E);
    e.z = fex2((v.z - mx) * LOG2E);
    e.w = fex2((v.w - mx) * LOG2E);
    float s = e.x + e.y + e.z + e.w;
    #pragma unroll
    for (int o = 16; o; o >>= 1) s += __shfl_xor_sync(0xffffffffu, s, o);
    if (lane == 0) shs[tid >> 5] = s;
    __syncthreads();
    s = shs[0] + shs[1] + shs[2] + shs[3] + shs[4] + shs[5] + shs[6] + shs[7];
    float inv = 1.0f / s;
    float f[4] = {e.x * inv, e.y * inv, e.z * inv, e.w * inv};
    __nv_bfloat16 h[4], l[4];
    #pragma unroll
    for (int q = 0; q < 4; q++) hilo(f[q], h[q], l[q]);
    __nv_bfloat162* dH = (__nv_bfloat162*)(g_smH + row * N + 4 * tid);
    __nv_bfloat162* dL = (__nv_bfloat162*)(g_smL + row * N + 4 * tid);
    dH[0] = __nv_bfloat162{h[0], h[1]};
    dH[1] = __nv_bfloat162{h[2], h[3]};
    dL[0] = __nv_bfloat162{l[0], l[1]};
    dL[1] = __nv_bfloat162{l[2], l[3]};
}

// ---------------------------------------------------------------------------
// HMMA NN gemm: via[b] = smcorr[b] @ fa[b]; out hi/lo
__global__ void __launch_bounds__(256) k_hmma_nn() {
    extern __shared__ __nv_bfloat16 smem[];
    int rb = blockIdx.x, b = blockIdx.y;
    int tid = threadIdx.x, wid = tid >> 5, lane = tid & 31;
    int fs = 2 * ((b + 1) & 7);

    int wm = wid & 3, wn = wid >> 2;
    float acc[2][8][4];
    #pragma unroll
    for (int mi = 0; mi < 2; mi++)
        #pragma unroll
        for (int nj = 0; nj < 8; nj++)
            #pragma unroll
            for (int q = 0; q < 4; q++) acc[mi][nj][q] = 0.f;

    uint32_t sbase = smem_u32(smem);
    const int AOFF[3] = {AH_O, AH_O, AL_O};
    const int VOFF[3] = {VH_O, VL_O, VH_O};
    int a_r = lane & 15, a_c = (lane >> 4) << 3;
    int bt_r = (lane & 7) + (((lane >> 3) & 1) << 3);
    int bt_c = (lane >> 4) << 3;

    for (int kc = 0; kc < 16; kc++) {
        int kb = kc * 64;
        if (kc) __syncthreads();
        #pragma unroll
        for (int i = 0; i < 4; i++) {
            int idx = tid + 256 * i;
            int r = idx >> 3, c8 = idx & 7;
            size_t so = (size_t)(b * 1024 + rb * 128 + r) * 1024 + kb + c8 * 8;
            *(uint4*)(smem + AH_O + r * APAD + c8 * 8) = *(const uint4*)(g_smH + so);
            *(uint4*)(smem + AL_O + r * APAD + c8 * 8) = *(const uint4*)(g_smL + so);
        }
        #pragma unroll
        for (int i = 0; i < 4; i++) {
            int idx = tid + 256 * i;
            int r = idx >> 4, c8 = idx & 15;
            size_t so = (size_t)(fs * 1024 + kb + r) * 128 + c8 * 8;
            *(uint4*)(smem + VH_O + r * VPAD + c8 * 8) = *(const uint4*)(g_FnH + so);
            *(uint4*)(smem + VL_O + r * VPAD + c8 * 8) = *(const uint4*)(g_FnL + so);
        }
        __syncthreads();

        #pragma unroll
        for (int t = 0; t < 3; t++) {
            #pragma unroll
            for (int k16 = 0; k16 < 4; k16++) {
                int kk = k16 * 16;
                uint32_t af[2][4];
                #pragma unroll
                for (int mi = 0; mi < 2; mi++) {
                    int row = wm * 32 + mi * 16 + a_r;
                    ldm4(af[mi][0], af[mi][1], af[mi][2], af[mi][3],
                         sbase + (AOFF[t] + row * APAD + kk + a_c) * 2);
                }
                uint32_t bf[4][4];
                #pragma unroll
                for (int nj = 0; nj < 4; nj++) {
                    int krow = kk + bt_r;
                    int ccol = wn * 64 + nj * 16 + bt_c;
                    ldm4t(bf[nj][0], bf[nj][1], bf[nj][2], bf[nj][3],
                          sbase + (VOFF[t] + krow * VPAD + ccol) * 2);
                }
                #pragma unroll
                for (int mi = 0; mi < 2; mi++)
                    #pragma unroll
                    for (int nj = 0; nj < 4; nj++) {
                        mma16816(acc[mi][2 * nj], af[mi], bf[nj][0], bf[nj][1]);
                        mma16816(acc[mi][2 * nj + 1], af[mi], bf[nj][2], bf[nj][3]);
                    }
            }
        }
    }

    {
        int rbase = b * 1024 + rb * 128 + wm * 32 + (lane >> 2);
        int cbase = wn * 64 + 2 * (lane & 3);
        #pragma unroll
        for (int mi = 0; mi < 2; mi++)
            #pragma unroll
            for (int nj = 0; nj < 8; nj++) {
                #pragma unroll
                for (int half = 0; half < 2; half++) {
                    int row = rbase + mi * 16 + half * 8;
                    int col = cbase + nj * 8;
                    float v0 = acc[mi][nj][2 * half], v1 = acc[mi][nj][2 * half + 1];
                    __nv_bfloat16 h0, l0, h1, l1;
                    hilo(v0, h0, l0);
                    hilo(v1, h1, l1);
                    size_t o = (size_t)row * C + col;
                    *(__nv_bfloat162*)(g_viaH + o) = __nv_bfloat162{h0, h1};
                    *(__nv_bfloat162*)(g_viaL + o) = __nv_bfloat162{l0, l1};
                }
            }
    }
}

// ---------------------------------------------------------------------------
// release/acquire batch barrier (no full threadfence)
__device__ __forceinline__ void batch_bar(int b, unsigned target) {
    __syncthreads();
    if (threadIdx.x == 0) {
        unsigned v;
        asm volatile("red.release.gpu.add.u32 [%0], %1;"
                     :: "l"(&g_bar[b]), "r"(1u) : "memory");
        do {
            asm volatile("ld.acquire.gpu.u32 %0, [%1];"
                         : "=r"(v) : "l"(&g_bar[b]) : "memory");
        } while (v < target);
    }
    __syncthreads();
}

// persistent sinkhorn: ONE barrier per iteration. Blocks publish column
// partials (parity double-buffered), then every block redundantly combines
// all 16 partial sets into a local smem copy of c (bitwise identical).
__global__ void __launch_bounds__(512) k_sinkhorn() {
    int b = blockIdx.x >> 4, sub = blockIdx.x & 15;
    const float* Mrows = g_scrA + (size_t)(b * 1024 + sub * 64) * N;
    int tid = threadIdx.x, warp = tid >> 5, lane = tid & 31;
    __shared__ float sc[1024];
    __shared__ float2 rp[8][512];
    __shared__ float rsm[64];
    unsigned bar_t = 0;
    sc[tid] = 0.f;
    sc[tid + 512] = 0.f;
    __syncthreads();

    for (int it = 0; it < 30; it++) {
        int par = it & 1;
        float cc0 = sc[2 * tid], cc1 = sc[2 * tid + 1];
        float cmx[4] = {-1e30f, -1e30f, -1e30f, -1e30f};
        float cs[4] = {0.f, 0.f, 0.f, 0.f};
        float cmy[4] = {-1e30f, -1e30f, -1e30f, -1e30f};
        float cy[4] = {0.f, 0.f, 0.f, 0.f};

        for (int g = 0; g < 8; g++) {
            float2 z[8];
            #pragma unroll
            for (int rr = 0; rr < 8; rr++) {
                float2 y = *(const float2*)(Mrows + (size_t)(g * 8 + rr) * N + 2 * tid);
                z[rr] = make_float2(y.x * K2, y.y * K2);
            }
            #pragma unroll
            for (int rr = 0; rr < 8; rr++) {
                float a0 = z[rr].x + cc0, a1 = z[rr].y + cc1;
                float mx = fmaxf(a0, a1);
                float s = 1.0f + fex2(fminf(a0, a1) - mx);
                rp[rr][tid] = make_float2(mx, s);
            }
            __syncthreads();
            if (warp < 8) {
                float mx = -1e30f, s = 0.f;
                #pragma unroll
                for (int i = 0; i < 16; i++) {
                    float2 p2 = rp[warp][lane + 32 * i];
                    comb(mx, s, p2.x, p2.y);
                }
                #pragma unroll
                for (int o = 16; o; o >>= 1) {
                    float m2 = __shfl_xor_sync(0xffffffffu, mx, o);
                    float s2 = __shfl_xor_sync(0xffffffffu, s, o);
                    comb(mx, s, m2, s2);
                }
                if (lane == 0) rsm[g * 8 + warp] = -(mx + flg2(s));
            }
            __syncthreads();
            #pragma unroll
            for (int rr = 0; rr < 8; rr++) {
                float rv = rsm[g * 8 + rr];
                int q = rr & 3;
                onl(cmx[q], cs[q], z[rr].x + rv);
                onl(cmy[q], cy[q], z[rr].y + rv);
            }
        }
        comb(cmx[0], cs[0], cmx[1], cs[1]);
        comb(cmx[2], cs[2], cmx[3], cs[3]);
        comb(cmx[0], cs[0], cmx[2], cs[2]);
        comb(cmy[0], cy[0], cmy[1], cy[1]);
        comb(cmy[2], cy[2], cmy[3], cy[3]);
        comb(cmy[0], cy[0], cmy[2], cy[2]);

        float2* cp = g_cp + (size_t)par * (B * SNB * N) + (size_t)(b * 16 + sub) * N;
        cp[2 * tid] = make_float2(cmx[0], cs[0]);
        cp[2 * tid + 1] = make_float2(cmy[0], cy[0]);
        bar_t += SNB; batch_bar(b, bar_t);

        // redundant local combine of all 16 partial sets -> sc (identical in
        // every block; deterministic fixed order)
        const float2* base = g_cp + (size_t)par * (B * SNB * N) + (size_t)b * 16 * N;
        #pragma unroll
        for (int h = 0; h < 2; h++) {
            int col = tid + 512 * h;
            float mx = -1e30f, s = 0.f;
            #pragma unroll
            for (int k = 0; k < 16; k++) {
                float2 p2 = base[(size_t)k * N + col];
                comb(mx, s, p2.x, p2.y);
            }
            sc[col] = -(mx + flg2(s));
        }
        __syncthreads();
    }

    if (tid < 64) {
        g_r[b * N + sub * 64 + tid] = rsm[tid];
        g_c[b * N + sub * 64 + tid] = sc[sub * 64 + tid];
    }
}

// ---------------------------------------------------------------------------
// fused final pass: single-pass online stats (A: max+argmax+sum, B: max+sum)
__global__ void __launch_bounds__(256) k_final(const float* __restrict__ pc0) {
    int rowi = blockIdx.x;
    int b = rowi >> 10, n = rowi & 1023;
    size_t row = rowi;
    const float* pA = g_scrA + row * N;
    const float* pB = g_scrB + row * N;
    int tid = threadIdx.x, lane = tid & 31, warp = tid >> 5;

    __shared__ float spc[3 * 1024];
    __shared__ float scv[1024];
    __shared__ float smx[8], ssm[8];
    __shared__ int sarg[8];
    __shared__ float sbc[4];
    const float* pc = pc0 + (size_t)b * N * 3;
    for (int i = tid; i < 3 * 1024; i += 256) spc[i] = pc[i];
    for (int i = tid; i < 1024; i += 256) scv[i] = g_c[b * N + i];

    float vA[4], vB[4];
    #pragma unroll
    for (int t = 0; t < 4; t++) {
        vA[t] = pA[tid + 256 * t];
        vB[t] = pB[tid + 256 * t];
    }

    // --- pass A: online (max, scaled-sum, argmax) ---
    float mxA = -1e30f, sA = 0.f; int arg = -1;
    #pragma unroll
    for (int t = 0; t < 4; t++) {
        float x = vA[t];
        if (x > mxA) {
            sA = fmaf(sA, fex2((mxA - x) * LOG2E), 1.0f);
            mxA = x; arg = tid + 256 * t;
        } else {
            sA += fex2((x - mxA) * LOG2E);
        }
    }
    #pragma unroll
    for (int o = 16; o; o >>= 1) {
        float m2 = __shfl_xor_sync(0xffffffffu, mxA, o);
        float s2 = __shfl_xor_sync(0xffffffffu, sA, o);
        int a2 = __shfl_xor_sync(0xffffffffu, arg, o);
        if (m2 > mxA || (m2 == mxA && a2 < arg)) arg = a2;
        float nm = fmaxf(mxA, m2);
        sA = sA * fex2((mxA - nm) * LOG2E) + s2 * fex2((m2 - nm) * LOG2E);
        mxA = nm;
    }
    if (lane == 0) { smx[warp] = mxA; ssm[warp] = sA; sarg[warp] = arg; }
    __syncthreads();
    if (tid == 0) {
        float bm = smx[0], bs = ssm[0]; int ba = sarg[0];
        #pragma unroll
        for (int q = 1; q < 8; q++) {
            if (smx[q] > bm || (smx[q] == bm && sarg[q] < ba)) ba = sarg[q];
            float nm = fmaxf(bm, smx[q]);
            bs = bs * fex2((bm - nm) * LOG2E) + ssm[q] * fex2((smx[q] - nm) * LOG2E);
            bm = nm;
        }
        if (ba == n) atomicAdd(&g_correct, 1);
        sbc[0] = bm; sbc[1] = bs;
    }
    // --- pass B: online (max, scaled-sum) ---
    float mxB = -1e30f, sB = 0.f;
    #pragma unroll
    for (int t = 0; t < 4; t++) {
        float x = vB[t];
        if (x > mxB) {
            sB = fmaf(sB, fex2((mxB - x) * LOG2E), 1.0f);
            mxB = x;
        } else {
            sB += fex2((x - mxB) * LOG2E);
        }
    }
    #pragma unroll
    for (int o = 16; o; o >>= 1) {
        float m2 = __shfl_xor_sync(0xffffffffu, mxB, o);
        float s2 = __shfl_xor_sync(0xffffffffu, sB, o);
        float nm = fmaxf(mxB, m2);
        sB = sB * fex2((mxB - nm) * LOG2E) + s2 * fex2((m2 - nm) * LOG2E);
        mxB = nm;
    }
    __syncthreads();   // smx/ssm reuse
    if (lane == 0) { smx[warp] = mxB; ssm[warp] = sB; }
    __syncthreads();
    if (tid == 0) {
        float bm = smx[0], bs = ssm[0];
        #pragma unroll
        for (int q = 1; q < 8; q++) {
            float nm = fmaxf(bm, smx[q]);
            bs = bs * fex2((bm - nm) * LOG2E) + ssm[q] * fex2((smx[q] - nm) * LOG2E);
            bm = nm;
        }
        sbc[2] = bm; sbc[3] = bs;
    }
    __syncthreads();

    float mA = sbc[0], iA = 1.0f / sbc[1];
    float mB = sbc[2], iB = 1.0f / sbc[3];
    float rn = g_r[row];

    float px = spc[3 * n], py = spc[3 * n + 1], pz = spc[3 * n + 2];
    float aL = 0.f, aC = 0.f, aP = 0.f;
    #pragma unroll
    for (int t = 0; t < 4; t++) {
        int m = tid + 256 * t;
        float xA = vA[t], xB = vB[t];
        float smA = fex2((xA - mA) * LOG2E) * iA;
        float smB = fex2((xB - mB) * LOG2E) * iB;
        float dx = px - spc[3 * m], dy = py - spc[3 * m + 1], dz = pz - spc[3 * m + 2];
        float d2 = dx * dx + dy * dy + dz * dz;
        float dist = sqrtf(sqrtf(d2));
        aL += dist * (smA + smB);
        float sink = fex2(xA * K2 + rn + scv[m]);
        aC += fabsf(sink - smA);
        aP += (m == n) ? fabsf(1.0f - sink) : sink;
    }
    #pragma unroll
    for (int o = 16; o; o >>= 1) {
        aL += __shfl_xor_sync(0xffffffffu, aL, o);
        aC += __shfl_xor_sync(0xffffffffu, aC, o);
        aP += __shfl_xor_sync(0xffffffffu, aP, o);
    }
    __shared__ float s1[8], s2[8], s3[8];
    if (lane == 0) { s1[warp] = aL; s2[warp] = aC; s3[warp] = aP; }
    __syncthreads();
    if (tid == 0) {
        float tL = 0.f, tC = 0.f, tP = 0.f;
        #pragma unroll
        for (int q = 0; q < 8; q++) { tL += s1[q]; tC += s2[q]; tP += s3[q]; }
        g_pL[row] = tL; g_pC[row] = tC; g_pP[row] = tP;
    }
}

// ---------------------------------------------------------------------------
__global__ void __launch_bounds__(256) k_out(float* __restrict__ out) {
    int tid = threadIdx.x;
    float sL = 0.f, sC = 0.f, sP = 0.f;
    for (int i = tid; i < B * N; i += 256) {
        sL += g_pL[i]; sC += g_pC[i]; sP += g_pP[i];
    }
    #pragma unroll
    for (int o = 16; o; o >>= 1) {
        sL += __shfl_xor_sync(0xffffffffu, sL, o);
        sC += __shfl_xor_sync(0xffffffffu, sC, o);
        sP += __shfl_xor_sync(0xffffffffu, sP, o);
    }
    __shared__ float s1[8], s2[8], s3[8];
    if ((tid & 31) == 0) { s1[tid >> 5] = sL; s2[tid >> 5] = sC; s3[tid >> 5] = sP; }
    __syncthreads();
    if (tid == 0) {
        float tL = 0.f, tC = 0.f, tP = 0.f;
        #pragma unroll
        for (int q = 0; q < 8; q++) { tL += s1[q]; tC += s2[q]; tP += s3[q]; }
        float invN = 1.0f / (float)N;
        float loss = tL * invN;
        float Lc = 3.0f * tC * invN;
        float perm = 3.0f * tP * invN;
        float corr = (float)g_correct;
        float invB = 1.0f / (float)B;
        out[0] = (loss + Lc) * invB;
        out[1] = loss * invB;
        out[2] = Lc * invB;
        out[3] = corr * invB;
        out[4] = perm * invB;
    }
}

// ---------------------------------------------------------------------------
extern "C" void kernel_launch(void* const* d_in, const int* in_sizes, int n_in,
                              void* d_out, int out_size) {
    const float* feats = (const float*)d_in[0];
    const float* pc0 = (const float*)d_in[1];
    float* out = (float*)d_out;

    const int nt_smem = 4 * TSZ * sizeof(__nv_bfloat16);
    const int nn_smem = NN_ELEMS * sizeof(__nv_bfloat16);
    static bool attr_done = false;
    if (!attr_done) {
        cudaFuncSetAttribute(k_hmma_nt, cudaFuncAttributeMaxDynamicSharedMemorySize,
                             nt_smem);
        cudaFuncSetAttribute(k_hmma_nn, cudaFuncAttributeMaxDynamicSharedMemorySize,
                             nn_smem);
        attr_done = true;
    }

    k_init<<<32, 256>>>();
    k_norm<<<2 * B * N, 128>>>(feats);
    k_hmma_nt<<<dim3(8, 8, 8), 256, nt_smem>>>(0);    // corr_1a -> scrA
    k_rowsoftmax<<<B * N, 256>>>();                   // smcorr hi/lo bf16
    k_hmma_nn<<<dim3(8, 8), 256, nn_smem>>>();        // via hi/lo
    k_hmma_nt<<<dim3(8, 8, 16), 256, nt_smem>>>(3);   // corr_1a2 + corr_12
    k_sinkhorn<<<B * SNB, 512>>>();
    k_final<<<B * N, 256>>>(pc0);
    k_out<<<1, 256>>>(out);
}

// round 10
// speedup vs baseline: 1.1990x; 1.0759x over previous
#include <cuda_runtime.h>
#include <cuda_bf16.h>
#include <cstdint>

namespace {
constexpr int B = 8;
constexpr int N = 1024;
constexpr int C = 128;
constexpr float SCALEF = 20.0f;
constexpr float EPSF = 1e-12f;
constexpr float LOG2E = 1.4426950408889634f;
constexpr float K2 = 4.808983469629878f;   // log2(e)/0.3
constexpr int SNB = 16;                    // sinkhorn blocks per batch
constexpr int STATS_BLKS = 20;             // extra stats blocks
constexpr int TPAD = 136;
constexpr int TSZ = 128 * TPAD;
constexpr int APAD = 72;
constexpr int VPAD = 136;
constexpr int AH_O = 0;
constexpr int AL_O = 128 * APAD;
constexpr int VH_O = AL_O + 128 * APAD;
constexpr int VL_O = VH_O + 64 * VPAD;
constexpr int NN_ELEMS = VL_O + 64 * VPAD;
}

__device__ float g_scrA[(size_t)B * N * N];
__device__ float g_scrB[(size_t)B * N * N];
__device__ __nv_bfloat16 g_FnH[2 * B * N * C];
__device__ __nv_bfloat16 g_FnL[2 * B * N * C];
__device__ __nv_bfloat16 g_viaH[B * N * C];
__device__ __nv_bfloat16 g_viaL[B * N * C];
__device__ __nv_bfloat16 g_smH[(size_t)B * N * N];
__device__ __nv_bfloat16 g_smL[(size_t)B * N * N];
__device__ float2 g_cp[2 * B * SNB * N];
__device__ float g_r[B * N];
__device__ float g_c[B * N];
__device__ float g_maxA[B * N], g_sumA[B * N];
__device__ float g_maxB[B * N], g_sumB[B * N];
__device__ unsigned g_bar[B];
__device__ int g_correct;
__device__ float g_pL[B * N], g_pC[B * N], g_pP[B * N];

__device__ __forceinline__ float fex2(float x) {
    float y; asm("ex2.approx.ftz.f32 %0, %1;" : "=f"(y) : "f"(x)); return y;
}
__device__ __forceinline__ float flg2(float x) {
    float y; asm("lg2.approx.ftz.f32 %0, %1;" : "=f"(y) : "f"(x)); return y;
}
__device__ __forceinline__ uint32_t smem_u32(const void* p) {
    uint32_t a;
    asm("{ .reg .u64 t; cvta.to.shared.u64 t, %1; cvt.u32.u64 %0, t; }"
        : "=r"(a) : "l"(p));
    return a;
}
__device__ __forceinline__ void ldm4(uint32_t& r0, uint32_t& r1, uint32_t& r2,
                                     uint32_t& r3, uint32_t addr) {
    asm volatile("ldmatrix.sync.aligned.m8n8.x4.shared.b16 {%0,%1,%2,%3}, [%4];"
                 : "=r"(r0), "=r"(r1), "=r"(r2), "=r"(r3) : "r"(addr));
}
__device__ __forceinline__ void ldm4t(uint32_t& r0, uint32_t& r1, uint32_t& r2,
                                      uint32_t& r3, uint32_t addr) {
    asm volatile("ldmatrix.sync.aligned.m8n8.x4.trans.shared.b16 {%0,%1,%2,%3}, [%4];"
                 : "=r"(r0), "=r"(r1), "=r"(r2), "=r"(r3) : "r"(addr));
}
__device__ __forceinline__ void mma16816(float* c, const uint32_t* a,
                                         uint32_t b0, uint32_t b1) {
    asm volatile(
        "mma.sync.aligned.m16n8k16.row.col.f32.bf16.bf16.f32 "
        "{%0,%1,%2,%3}, {%4,%5,%6,%7}, {%8,%9}, {%0,%1,%2,%3};"
        : "+f"(c[0]), "+f"(c[1]), "+f"(c[2]), "+f"(c[3])
        : "r"(a[0]), "r"(a[1]), "r"(a[2]), "r"(a[3]), "r"(b0), "r"(b1));
}
__device__ __forceinline__ void hilo(float v, __nv_bfloat16& h, __nv_bfloat16& l) {
    h = __float2bfloat16(v);
    l = __float2bfloat16(v - __bfloat162float(h));
}
__device__ __forceinline__ void onl(float& mx, float& s, float x) {
    if (x <= mx) {
        s += fex2(x - mx);
    } else {
        s = fmaf(s, fex2(mx - x), 1.0f);
        mx = x;
    }
}
__device__ __forceinline__ void comb(float& mx, float& s, float m2, float s2) {
    float nm = fmaxf(mx, m2);
    s = s * fex2(mx - nm) + s2 * fex2(m2 - nm);
    mx = nm;
}

// ---------------------------------------------------------------------------
__global__ void k_init() {
    int i = blockIdx.x * blockDim.x + threadIdx.x;
    if (i < B) g_bar[i] = 0u;
    if (i == 0) g_correct = 0;
}

__global__ void __launch_bounds__(128) k_norm(const float* __restrict__ feats) {
    int row = blockIdx.x;
    const float* p = feats + (size_t)row * C;
    float v = p[threadIdx.x];
    float s = v * v;
    #pragma unroll
    for (int o = 16; o; o >>= 1) s += __shfl_xor_sync(0xffffffffu, s, o);
    __shared__ float sh[4];
    if ((threadIdx.x & 31) == 0) sh[threadIdx.x >> 5] = s;
    __syncthreads();
    s = sh[0] + sh[1] + sh[2] + sh[3];
    float scl = SCALEF / fmaxf(sqrtf(s), EPSF);
    float val = v * scl;
    size_t idx = (size_t)row * C + threadIdx.x;
    __nv_bfloat16 h, l;
    hilo(val, h, l);
    g_FnH[idx] = h;
    g_FnL[idx] = l;
}

// ---------------------------------------------------------------------------
// HMMA NT gemm, bf16-split 3 terms. mode 0: corr_1a; mode 3: fused 1+2.
__global__ void __launch_bounds__(256) k_hmma_nt(int mode) {
    extern __shared__ __nv_bfloat16 smem[];
    int ia = blockIdx.x, ib = blockIdx.y;
    int b = blockIdx.z & 7;
    int m = mode;
    if (mode == 3) m = (blockIdx.z < 8) ? 1 : 2;
    int tid = threadIdx.x, wid = tid >> 5, lane = tid & 31;

    const __nv_bfloat16 *aHg, *aLg; float* dst;
    int fsB;
    if (m == 0) {
        aHg = g_FnH + (size_t)(2 * b) * N * C;
        aLg = g_FnL + (size_t)(2 * b) * N * C;
        fsB = 2 * ((b + 1) & 7);
        dst = g_scrA;
    } else if (m == 1) {
        aHg = g_viaH + (size_t)b * N * C;
        aLg = g_viaL + (size_t)b * N * C;
        fsB = 2 * b + 1;
        dst = g_scrA;
    } else {
        aHg = g_FnH + (size_t)(2 * b) * N * C;
        aLg = g_FnL + (size_t)(2 * b) * N * C;
        fsB = 2 * b + 1;
        dst = g_scrB;
    }
    const __nv_bfloat16* bHg = g_FnH + (size_t)fsB * N * C;
    const __nv_bfloat16* bLg = g_FnL + (size_t)fsB * N * C;
    aHg += (size_t)ia * 128 * C; aLg += (size_t)ia * 128 * C;
    bHg += (size_t)ib * 128 * C; bLg += (size_t)ib * 128 * C;

    {
        const uint4* src[4] = {(const uint4*)aHg, (const uint4*)aLg,
                               (const uint4*)bHg, (const uint4*)bLg};
        #pragma unroll
        for (int t4 = 0; t4 < 4; t4++) {
            __nv_bfloat16* dtile = smem + t4 * TSZ;
            #pragma unroll
            for (int i = 0; i < 8; i++) {
                int idx = tid + 256 * i;
                int row = idx >> 4, c8 = idx & 15;
                *(uint4*)(dtile + row * TPAD + c8 * 8) = src[t4][idx];
            }
        }
    }
    __syncthreads();

    int wm = wid & 3, wn = wid >> 2;
    float acc[2][8][4];
    #pragma unroll
    for (int mi = 0; mi < 2; mi++)
        #pragma unroll
        for (int nj = 0; nj < 8; nj++)
            #pragma unroll
            for (int q = 0; q < 4; q++) acc[mi][nj][q] = 0.f;

    uint32_t sbase = smem_u32(smem);
    const int selA[3] = {0, 0, 1};
    const int selB[3] = {2, 3, 2};
    int a_r = lane & 15, a_c = (lane >> 4) << 3;
    int b_r = (lane & 7) + ((lane >> 4) << 3);
    int b_c = ((lane >> 3) & 1) << 3;

    #pragma unroll
    for (int t = 0; t < 3; t++) {
        uint32_t aB = sbase + selA[t] * TSZ * 2;
        uint32_t bBs = sbase + selB[t] * TSZ * 2;
        #pragma unroll
        for (int k8 = 0; k8 < 8; k8++) {
            int kc = k8 * 16;
            uint32_t af[2][4];
            #pragma unroll
            for (int mi = 0; mi < 2; mi++) {
                int row = wm * 32 + mi * 16 + a_r;
                ldm4(af[mi][0], af[mi][1], af[mi][2], af[mi][3],
                     aB + (row * TPAD + kc + a_c) * 2);
            }
            uint32_t bf[4][4];
            #pragma unroll
            for (int nj = 0; nj < 4; nj++) {
                int row = wn * 64 + nj * 16 + b_r;
                ldm4(bf[nj][0], bf[nj][1], bf[nj][2], bf[nj][3],
                     bBs + (row * TPAD + kc + b_c) * 2);
            }
            #pragma unroll
            for (int mi = 0; mi < 2; mi++)
                #pragma unroll
                for (int nj = 0; nj < 4; nj++) {
                    mma16816(acc[mi][2 * nj], af[mi], bf[nj][0], bf[nj][1]);
                    mma16816(acc[mi][2 * nj + 1], af[mi], bf[nj][2], bf[nj][3]);
                }
        }
    }

    {
        int rbase = b * 1024 + ia * 128 + wm * 32 + (lane >> 2);
        int cbase = ib * 128 + wn * 64 + 2 * (lane & 3);
        #pragma unroll
        for (int mi = 0; mi < 2; mi++)
            #pragma unroll
            for (int nj = 0; nj < 8; nj++) {
                float* d0 = dst + (size_t)(rbase + mi * 16) * 1024 + cbase + nj * 8;
                *(float2*)d0 = make_float2(acc[mi][nj][0], acc[mi][nj][1]);
                float* d1 = d0 + 8 * 1024;
                *(float2*)d1 = make_float2(acc[mi][nj][2], acc[mi][nj][3]);
            }
    }
}

// ---------------------------------------------------------------------------
// row softmax of corr_1a (fp32 in scrA) -> bf16 hi/lo smcorr
__global__ void __launch_bounds__(256) k_rowsoftmax() {
    size_t row = blockIdx.x;
    const float4* p = (const float4*)(g_scrA + row * N);
    int tid = threadIdx.x, lane = tid & 31;
    float4 v = p[tid];
    float mx = fmaxf(fmaxf(v.x, v.y), fmaxf(v.z, v.w));
    #pragma unroll
    for (int o = 16; o; o >>= 1) mx = fmaxf(mx, __shfl_xor_sync(0xffffffffu, mx, o));
    __shared__ float shm[8], shs[8];
    if (lane == 0) shm[tid >> 5] = mx;
    __syncthreads();
    mx = fmaxf(fmaxf(fmaxf(shm[0], shm[1]), fmaxf(shm[2], shm[3])),
               fmaxf(fmaxf(shm[4], shm[5]), fmaxf(shm[6], shm[7])));
    float4 e;
    e.x = fex2((v.x - mx) * LOG2E);
    e.y = fex2((v.y - mx) * LOG2E);
    e.z = fex2((v.z - mx) * LOG2E);
    e.w = fex2((v.w - mx) * LOG2E);
    float s = e.x + e.y + e.z + e.w;
    #pragma unroll
    for (int o = 16; o; o >>= 1) s += __shfl_xor_sync(0xffffffffu, s, o);
    if (lane == 0) shs[tid >> 5] = s;
    __syncthreads();
    s = shs[0] + shs[1] + shs[2] + shs[3] + shs[4] + shs[5] + shs[6] + shs[7];
    float inv = 1.0f / s;
    float f[4] = {e.x * inv, e.y * inv, e.z * inv, e.w * inv};
    __nv_bfloat16 h[4], l[4];
    #pragma unroll
    for (int q = 0; q < 4; q++) hilo(f[q], h[q], l[q]);
    __nv_bfloat162* dH = (__nv_bfloat162*)(g_smH + row * N + 4 * tid);
    __nv_bfloat162* dL = (__nv_bfloat162*)(g_smL + row * N + 4 * tid);
    dH[0] = __nv_bfloat162{h[0], h[1]};
    dH[1] = __nv_bfloat162{h[2], h[3]};
    dL[0] = __nv_bfloat162{l[0], l[1]};
    dL[1] = __nv_bfloat162{l[2], l[3]};
}

// ---------------------------------------------------------------------------
// HMMA NN gemm: via[b] = smcorr[b] @ fa[b]; out hi/lo
__global__ void __launch_bounds__(256) k_hmma_nn() {
    extern __shared__ __nv_bfloat16 smem[];
    int rb = blockIdx.x, b = blockIdx.y;
    int tid = threadIdx.x, wid = tid >> 5, lane = tid & 31;
    int fs = 2 * ((b + 1) & 7);

    int wm = wid & 3, wn = wid >> 2;
    float acc[2][8][4];
    #pragma unroll
    for (int mi = 0; mi < 2; mi++)
        #pragma unroll
        for (int nj = 0; nj < 8; nj++)
            #pragma unroll
            for (int q = 0; q < 4; q++) acc[mi][nj][q] = 0.f;

    uint32_t sbase = smem_u32(smem);
    const int AOFF[3] = {AH_O, AH_O, AL_O};
    const int VOFF[3] = {VH_O, VL_O, VH_O};
    int a_r = lane & 15, a_c = (lane >> 4) << 3;
    int bt_r = (lane & 7) + (((lane >> 3) & 1) << 3);
    int bt_c = (lane >> 4) << 3;

    for (int kc = 0; kc < 16; kc++) {
        int kb = kc * 64;
        if (kc) __syncthreads();
        #pragma unroll
        for (int i = 0; i < 4; i++) {
            int idx = tid + 256 * i;
            int r = idx >> 3, c8 = idx & 7;
            size_t so = (size_t)(b * 1024 + rb * 128 + r) * 1024 + kb + c8 * 8;
            *(uint4*)(smem + AH_O + r * APAD + c8 * 8) = *(const uint4*)(g_smH + so);
            *(uint4*)(smem + AL_O + r * APAD + c8 * 8) = *(const uint4*)(g_smL + so);
        }
        #pragma unroll
        for (int i = 0; i < 4; i++) {
            int idx = tid + 256 * i;
            int r = idx >> 4, c8 = idx & 15;
            size_t so = (size_t)(fs * 1024 + kb + r) * 128 + c8 * 8;
            *(uint4*)(smem + VH_O + r * VPAD + c8 * 8) = *(const uint4*)(g_FnH + so);
            *(uint4*)(smem + VL_O + r * VPAD + c8 * 8) = *(const uint4*)(g_FnL + so);
        }
        __syncthreads();

        #pragma unroll
        for (int t = 0; t < 3; t++) {
            #pragma unroll
            for (int k16 = 0; k16 < 4; k16++) {
                int kk = k16 * 16;
                uint32_t af[2][4];
                #pragma unroll
                for (int mi = 0; mi < 2; mi++) {
                    int row = wm * 32 + mi * 16 + a_r;
                    ldm4(af[mi][0], af[mi][1], af[mi][2], af[mi][3],
                         sbase + (AOFF[t] + row * APAD + kk + a_c) * 2);
                }
                uint32_t bf[4][4];
                #pragma unroll
                for (int nj = 0; nj < 4; nj++) {
                    int krow = kk + bt_r;
                    int ccol = wn * 64 + nj * 16 + bt_c;
                    ldm4t(bf[nj][0], bf[nj][1], bf[nj][2], bf[nj][3],
                          sbase + (VOFF[t] + krow * VPAD + ccol) * 2);
                }
                #pragma unroll
                for (int mi = 0; mi < 2; mi++)
                    #pragma unroll
                    for (int nj = 0; nj < 4; nj++) {
                        mma16816(acc[mi][2 * nj], af[mi], bf[nj][0], bf[nj][1]);
                        mma16816(acc[mi][2 * nj + 1], af[mi], bf[nj][2], bf[nj][3]);
                    }
            }
        }
    }

    {
        int rbase = b * 1024 + rb * 128 + wm * 32 + (lane >> 2);
        int cbase = wn * 64 + 2 * (lane & 3);
        #pragma unroll
        for (int mi = 0; mi < 2; mi++)
            #pragma unroll
            for (int nj = 0; nj < 8; nj++) {
                #pragma unroll
                for (int half = 0; half < 2; half++) {
                    int row = rbase + mi * 16 + half * 8;
                    int col = cbase + nj * 8;
                    float v0 = acc[mi][nj][2 * half], v1 = acc[mi][nj][2 * half + 1];
                    __nv_bfloat16 h0, l0, h1, l1;
                    hilo(v0, h0, l0);
                    hilo(v1, h1, l1);
                    size_t o = (size_t)row * C + col;
                    *(__nv_bfloat162*)(g_viaH + o) = __nv_bfloat162{h0, h1};
                    *(__nv_bfloat162*)(g_viaL + o) = __nv_bfloat162{l0, l1};
                }
            }
    }
}

// ---------------------------------------------------------------------------
__device__ __forceinline__ void batch_bar(int b, unsigned target) {
    __syncthreads();
    if (threadIdx.x == 0) {
        unsigned v;
        asm volatile("red.release.gpu.add.u32 [%0], %1;"
                     :: "l"(&g_bar[b]), "r"(1u) : "memory");
        do {
            asm volatile("ld.acquire.gpu.u32 %0, [%1];"
                         : "=r"(v) : "l"(&g_bar[b]) : "memory");
        } while (v < target);
    }
    __syncthreads();
}

// ---------------------------------------------------------------------------
// per-row stats for k_final (runs on the 20 extra blocks, warp-per-row)
__device__ void stats_work(int sbid) {
    int tid = threadIdx.x, wid = tid >> 5, lane = tid & 31;
    int w = sbid * 16 + wid;
    for (int row = w; row < B * N; row += STATS_BLKS * 16) {
        const float* pA = g_scrA + (size_t)row * N;
        const float* pB = g_scrB + (size_t)row * N;
        float vv[32];
        // --- A ---
        #pragma unroll
        for (int j = 0; j < 8; j++) {
            float4 f = *(const float4*)(pA + lane * 4 + 128 * j);
            vv[4 * j] = f.x; vv[4 * j + 1] = f.y; vv[4 * j + 2] = f.z; vv[4 * j + 3] = f.w;
        }
        float mx = -1e30f; int arg = 0;
        #pragma unroll
        for (int j = 0; j < 32; j++) {
            int idx = lane * 4 + 128 * (j >> 2) + (j & 3);
            if (vv[j] > mx) { mx = vv[j]; arg = idx; }
        }
        #pragma unroll
        for (int o = 16; o; o >>= 1) {
            float m2 = __shfl_xor_sync(0xffffffffu, mx, o);
            int a2 = __shfl_xor_sync(0xffffffffu, arg, o);
            if (m2 > mx || (m2 == mx && a2 < arg)) { mx = m2; arg = a2; }
        }
        float s = 0.f;
        #pragma unroll
        for (int j = 0; j < 32; j++) s += fex2((vv[j] - mx) * LOG2E);
        #pragma unroll
        for (int o = 16; o; o >>= 1) s += __shfl_xor_sync(0xffffffffu, s, o);
        if (lane == 0) {
            g_maxA[row] = mx; g_sumA[row] = s;
            if (arg == (row & 1023)) atomicAdd(&g_correct, 1);
        }
        // --- B ---
        #pragma unroll
        for (int j = 0; j < 8; j++) {
            float4 f = *(const float4*)(pB + lane * 4 + 128 * j);
            vv[4 * j] = f.x; vv[4 * j + 1] = f.y; vv[4 * j + 2] = f.z; vv[4 * j + 3] = f.w;
        }
        mx = -1e30f;
        #pragma unroll
        for (int j = 0; j < 32; j++) mx = fmaxf(mx, vv[j]);
        #pragma unroll
        for (int o = 16; o; o >>= 1) mx = fmaxf(mx, __shfl_xor_sync(0xffffffffu, mx, o));
        s = 0.f;
        #pragma unroll
        for (int j = 0; j < 32; j++) s += fex2((vv[j] - mx) * LOG2E);
        #pragma unroll
        for (int o = 16; o; o >>= 1) s += __shfl_xor_sync(0xffffffffu, s, o);
        if (lane == 0) { g_maxB[row] = mx; g_sumB[row] = s; }
    }
}

// persistent sinkhorn + concurrent stats blocks.
// rows: exact two-pass (fmax, then 1 ex2/elem). cols: it==0 safe onl path;
// it>=1 stale-shift identity (z+r+c_prev <= 0) -> plain ex2 sums, add-combine.
__global__ void __launch_bounds__(512) k_sinkhorn() {
    if (blockIdx.x >= B * SNB) { stats_work(blockIdx.x - B * SNB); return; }
    int b = blockIdx.x >> 4, sub = blockIdx.x & 15;
    const float* Mrows = g_scrA + (size_t)(b * 1024 + sub * 64) * N;
    int tid = threadIdx.x, warp = tid >> 5, lane = tid & 31;
    __shared__ float sc[1024];
    __shared__ float rp[8][512];
    __shared__ float rmx[8];
    __shared__ float rsm[64];
    unsigned bar_t = 0;
    sc[tid] = 0.f;
    sc[tid + 512] = 0.f;
    __syncthreads();

    for (int it = 0; it < 30; it++) {
        int par = it & 1;
        float cc0 = sc[2 * tid], cc1 = sc[2 * tid + 1];
        // col accumulators: it==0 online-LSE state, else plain sums
        float amx0 = -1e30f, amx1 = -1e30f;
        float as0a = 0.f, as0b = 0.f, as1a = 0.f, as1b = 0.f;

        for (int g = 0; g < 8; g++) {
            float2 z[8];
            #pragma unroll
            for (int rr = 0; rr < 8; rr++) {
                float2 y = *(const float2*)(Mrows + (size_t)(g * 8 + rr) * N + 2 * tid);
                z[rr] = make_float2(fmaf(y.x, K2, cc0), fmaf(y.y, K2, cc1));
            }
            // pass 1: per-thread pair max (no ex2)
            #pragma unroll
            for (int rr = 0; rr < 8; rr++)
                rp[rr][tid] = fmaxf(z[rr].x, z[rr].y);
            __syncthreads();
            if (warp < 8) {
                float mx = -1e30f;
                #pragma unroll
                for (int i = 0; i < 16; i++) mx = fmaxf(mx, rp[warp][lane + 32 * i]);
                #pragma unroll
                for (int o = 16; o; o >>= 1)
                    mx = fmaxf(mx, __shfl_xor_sync(0xffffffffu, mx, o));
                if (lane == 0) rmx[warp] = mx;
            }
            __syncthreads();
            // pass 2: 1 ex2/elem sums
            #pragma unroll
            for (int rr = 0; rr < 8; rr++) {
                float m = rmx[rr];
                rp[rr][tid] = fex2(z[rr].x - m) + fex2(z[rr].y - m);
            }
            __syncthreads();
            if (warp < 8) {
                float s = 0.f;
                #pragma unroll
                for (int i = 0; i < 16; i++) s += rp[warp][lane + 32 * i];
                #pragma unroll
                for (int o = 16; o; o >>= 1) s += __shfl_xor_sync(0xffffffffu, s, o);
                if (lane == 0) rsm[g * 8 + warp] = -(rmx[warp] + flg2(s));
            }
            __syncthreads();
            // column accumulation; v = z(+cc) + r  (== z + r + c_prev <= 0)
            if (it == 0) {
                #pragma unroll
                for (int rr = 0; rr < 8; rr++) {
                    float rv = rsm[g * 8 + rr];
                    onl(amx0, as0a, z[rr].x + rv);
                    onl(amx1, as1a, z[rr].y + rv);
                }
            } else {
                #pragma unroll
                for (int rr = 0; rr < 8; rr++) {
                    float rv = rsm[g * 8 + rr];
                    if (rr & 1) {
                        as0b += fex2(z[rr].x + rv);
                        as1b += fex2(z[rr].y + rv);
                    } else {
                        as0a += fex2(z[rr].x + rv);
                        as1a += fex2(z[rr].y + rv);
                    }
                }
            }
        }

        float2* cp = g_cp + (size_t)par * (B * SNB * N) + (size_t)(b * 16 + sub) * N;
        if (it == 0) {
            cp[2 * tid] = make_float2(amx0, as0a);
            cp[2 * tid + 1] = make_float2(amx1, as1a);
        } else {
            cp[2 * tid] = make_float2(0.f, as0a + as0b);
            cp[2 * tid + 1] = make_float2(0.f, as1a + as1b);
        }
        bar_t += SNB; batch_bar(b, bar_t);

        // redundant combine -> sc (bitwise identical in all blocks)
        const float2* base = g_cp + (size_t)par * (B * SNB * N) + (size_t)b * 16 * N;
        if (it == 0) {
            #pragma unroll
            for (int h = 0; h < 2; h++) {
                int col = tid + 512 * h;
                float mx = -1e30f, s = 0.f;
                #pragma unroll
                for (int k = 0; k < 16; k++) {
                    float2 p2 = base[(size_t)k * N + col];
                    comb(mx, s, p2.x, p2.y);
                }
                sc[col] = -(mx + flg2(s));
            }
        } else {
            #pragma unroll
            for (int h = 0; h < 2; h++) {
                int col = tid + 512 * h;
                float s = 0.f;
                #pragma unroll
                for (int k = 0; k < 16; k++) s += base[(size_t)k * N + col].y;
                sc[col] = sc[col] - flg2(s);
            }
        }
        __syncthreads();
    }

    if (tid < 64) {
        g_r[b * N + sub * 64 + tid] = rsm[tid];
        g_c[b * N + sub * 64 + tid] = sc[sub * 64 + tid];
    }
}

// ---------------------------------------------------------------------------
// fused final pass: uses precomputed row stats; dist + softmaxes + sink
__global__ void __launch_bounds__(256) k_final(const float* __restrict__ pc0) {
    int rowi = blockIdx.x;
    int b = rowi >> 10, n = rowi & 1023;
    size_t row = rowi;
    const float* pA = g_scrA + row * N;
    const float* pB = g_scrB + row * N;
    int tid = threadIdx.x, lane = tid & 31, warp = tid >> 5;

    __shared__ float spc[3 * 1024];
    __shared__ float scv[1024];
    const float* pc = pc0 + (size_t)b * N * 3;
    for (int i = tid; i < 3 * 1024; i += 256) spc[i] = pc[i];
    for (int i = tid; i < 1024; i += 256) scv[i] = g_c[b * N + i];

    float mA = g_maxA[row], iA = 1.0f / g_sumA[row];
    float mB = g_maxB[row], iB = 1.0f / g_sumB[row];
    float rn = g_r[row];
    __syncthreads();

    float px = spc[3 * n], py = spc[3 * n + 1], pz = spc[3 * n + 2];
    float aL = 0.f, aC = 0.f, aP = 0.f;
    #pragma unroll
    for (int t = 0; t < 4; t++) {
        int m = tid + 256 * t;
        float xA = pA[m], xB = pB[m];
        float smA = fex2((xA - mA) * LOG2E) * iA;
        float smB = fex2((xB - mB) * LOG2E) * iB;
        float dx = px - spc[3 * m], dy = py - spc[3 * m + 1], dz = pz - spc[3 * m + 2];
        float d2 = dx * dx + dy * dy + dz * dz;
        float dist = sqrtf(sqrtf(d2));
        aL += dist * (smA + smB);
        float sink = fex2(xA * K2 + rn + scv[m]);
        aC += fabsf(sink - smA);
        aP += (m == n) ? fabsf(1.0f - sink) : sink;
    }
    #pragma unroll
    for (int o = 16; o; o >>= 1) {
        aL += __shfl_xor_sync(0xffffffffu, aL, o);
        aC += __shfl_xor_sync(0xffffffffu, aC, o);
        aP += __shfl_xor_sync(0xffffffffu, aP, o);
    }
    __shared__ float s1[8], s2[8], s3[8];
    if (lane == 0) { s1[warp] = aL; s2[warp] = aC; s3[warp] = aP; }
    __syncthreads();
    if (tid == 0) {
        float tL = 0.f, tC = 0.f, tP = 0.f;
        #pragma unroll
        for (int q = 0; q < 8; q++) { tL += s1[q]; tC += s2[q]; tP += s3[q]; }
        g_pL[row] = tL; g_pC[row] = tC; g_pP[row] = tP;
    }
}

// ---------------------------------------------------------------------------
__global__ void __launch_bounds__(256) k_out(float* __restrict__ out) {
    int tid = threadIdx.x;
    float sL = 0.f, sC = 0.f, sP = 0.f;
    for (int i = tid; i < B * N; i += 256) {
        sL += g_pL[i]; sC += g_pC[i]; sP += g_pP[i];
    }
    #pragma unroll
    for (int o = 16; o; o >>= 1) {
        sL += __shfl_xor_sync(0xffffffffu, sL, o);
        sC += __shfl_xor_sync(0xffffffffu, sC, o);
        sP += __shfl_xor_sync(0xffffffffu, sP, o);
    }
    __shared__ float s1[8], s2[8], s3[8];
    if ((tid & 31) == 0) { s1[tid >> 5] = sL; s2[tid >> 5] = sC; s3[tid >> 5] = sP; }
    __syncthreads();
    if (tid == 0) {
        float tL = 0.f, tC = 0.f, tP = 0.f;
        #pragma unroll
        for (int q = 0; q < 8; q++) { tL += s1[q]; tC += s2[q]; tP += s3[q]; }
        float invN = 1.0f / (float)N;
        float loss = tL * invN;
        float Lc = 3.0f * tC * invN;
        float perm = 3.0f * tP * invN;
        float corr = (float)g_correct;
        float invB = 1.0f / (float)B;
        out[0] = (loss + Lc) * invB;
        out[1] = loss * invB;
        out[2] = Lc * invB;
        out[3] = corr * invB;
        out[4] = perm * invB;
    }
}

// ---------------------------------------------------------------------------
extern "C" void kernel_launch(void* const* d_in, const int* in_sizes, int n_in,
                              void* d_out, int out_size) {
    const float* feats = (const float*)d_in[0];
    const float* pc0 = (const float*)d_in[1];
    float* out = (float*)d_out;

    const int nt_smem = 4 * TSZ * sizeof(__nv_bfloat16);
    const int nn_smem = NN_ELEMS * sizeof(__nv_bfloat16);
    static bool attr_done = false;
    if (!attr_done) {
        cudaFuncSetAttribute(k_hmma_nt, cudaFuncAttributeMaxDynamicSharedMemorySize,
                             nt_smem);
        cudaFuncSetAttribute(k_hmma_nn, cudaFuncAttributeMaxDynamicSharedMemorySize,
                             nn_smem);
        attr_done = true;
    }

    k_init<<<32, 256>>>();
    k_norm<<<2 * B * N, 128>>>(feats);
    k_hmma_nt<<<dim3(8, 8, 8), 256, nt_smem>>>(0);    // corr_1a -> scrA
    k_rowsoftmax<<<B * N, 256>>>();                   // smcorr hi/lo bf16
    k_hmma_nn<<<dim3(8, 8), 256, nn_smem>>>();        // via hi/lo
    k_hmma_nt<<<dim3(8, 8, 16), 256, nt_smem>>>(3);   // corr_1a2 + corr_12
    k_sinkhorn<<<B * SNB + STATS_BLKS, 512>>>();      // + concurrent stats
    k_final<<<B * N, 256>>>(pc0);
    k_out<<<1, 256>>>(out);
}

// round 12
// speedup vs baseline: 1.2299x; 1.0257x over previous
#include <cuda_runtime.h>
#include <cuda_bf16.h>
#include <cstdint>

namespace {
constexpr int B = 8;
constexpr int N = 1024;
constexpr int C = 128;
constexpr float SCALEF = 20.0f;
constexpr float EPSF = 1e-12f;
constexpr float LOG2E = 1.4426950408889634f;
constexpr float K2 = 4.808983469629878f;   // log2(e)/0.3
constexpr int SNB = 16;                    // sinkhorn blocks per batch
constexpr int STATS_BLKS = 20;             // extra stats blocks
constexpr int TPAD = 136;
constexpr int TSZ = 128 * TPAD;
constexpr int APAD = 72;
constexpr int VPAD = 136;
constexpr int AH_O = 0;
constexpr int AL_O = 128 * APAD;
constexpr int VH_O = AL_O + 128 * APAD;
constexpr int VL_O = VH_O + 64 * VPAD;
constexpr int NN_ELEMS = VL_O + 64 * VPAD;
}

__device__ float g_scrA[(size_t)B * N * N];
__device__ float g_scrB[(size_t)B * N * N];
__device__ __nv_bfloat16 g_FnH[2 * B * N * C];
__device__ __nv_bfloat16 g_FnL[2 * B * N * C];
__device__ __nv_bfloat16 g_viaH[B * N * C];
__device__ __nv_bfloat16 g_viaL[B * N * C];
__device__ __nv_bfloat16 g_smH[(size_t)B * N * N];
__device__ __nv_bfloat16 g_smL[(size_t)B * N * N];
__device__ float2 g_cp[2 * B * SNB * N];   // double-buffered column partials
__device__ float g_r[B * N];
__device__ float g_c[B * N];
__device__ float g_maxA[B * N], g_sumA[B * N];
__device__ float g_maxB[B * N], g_sumB[B * N];
__device__ unsigned g_bar[B];
__device__ int g_correct;
__device__ float g_pL[B * N], g_pC[B * N], g_pP[B * N];

__device__ __forceinline__ float fex2(float x) {
    float y; asm("ex2.approx.ftz.f32 %0, %1;" : "=f"(y) : "f"(x)); return y;
}
__device__ __forceinline__ float flg2(float x) {
    float y; asm("lg2.approx.ftz.f32 %0, %1;" : "=f"(y) : "f"(x)); return y;
}
__device__ __forceinline__ uint32_t smem_u32(const void* p) {
    uint32_t a;
    asm("{ .reg .u64 t; cvta.to.shared.u64 t, %1; cvt.u32.u64 %0, t; }"
        : "=r"(a) : "l"(p));
    return a;
}
__device__ __forceinline__ void ldm4(uint32_t& r0, uint32_t& r1, uint32_t& r2,
                                     uint32_t& r3, uint32_t addr) {
    asm volatile("ldmatrix.sync.aligned.m8n8.x4.shared.b16 {%0,%1,%2,%3}, [%4];"
                 : "=r"(r0), "=r"(r1), "=r"(r2), "=r"(r3) : "r"(addr));
}
__device__ __forceinline__ void ldm4t(uint32_t& r0, uint32_t& r1, uint32_t& r2,
                                      uint32_t& r3, uint32_t addr) {
    asm volatile("ldmatrix.sync.aligned.m8n8.x4.trans.shared.b16 {%0,%1,%2,%3}, [%4];"
                 : "=r"(r0), "=r"(r1), "=r"(r2), "=r"(r3) : "r"(addr));
}
__device__ __forceinline__ void mma16816(float* c, const uint32_t* a,
                                         uint32_t b0, uint32_t b1) {
    asm volatile(
        "mma.sync.aligned.m16n8k16.row.col.f32.bf16.bf16.f32 "
        "{%0,%1,%2,%3}, {%4,%5,%6,%7}, {%8,%9}, {%0,%1,%2,%3};"
        : "+f"(c[0]), "+f"(c[1]), "+f"(c[2]), "+f"(c[3])
        : "r"(a[0]), "r"(a[1]), "r"(a[2]), "r"(a[3]), "r"(b0), "r"(b1));
}
__device__ __forceinline__ void hilo(float v, __nv_bfloat16& h, __nv_bfloat16& l) {
    h = __float2bfloat16(v);
    l = __float2bfloat16(v - __bfloat162float(h));
}
__device__ __forceinline__ void onl(float& mx, float& s, float x) {
    if (x <= mx) {
        s += fex2(x - mx);
    } else {
        s = fmaf(s, fex2(mx - x), 1.0f);
        mx = x;
    }
}
__device__ __forceinline__ void comb(float& mx, float& s, float m2, float s2) {
    float nm = fmaxf(mx, m2);
    s = s * fex2(mx - nm) + s2 * fex2(m2 - nm);
    mx = nm;
}

// ---------------------------------------------------------------------------
__global__ void k_init() {
    int i = blockIdx.x * blockDim.x + threadIdx.x;
    if (i < B) g_bar[i] = 0u;
    if (i == 0) g_correct = 0;
}

__global__ void __launch_bounds__(128) k_norm(const float* __restrict__ feats) {
    int row = blockIdx.x;
    const float* p = feats + (size_t)row * C;
    float v = p[threadIdx.x];
    float s = v * v;
    #pragma unroll
    for (int o = 16; o; o >>= 1) s += __shfl_xor_sync(0xffffffffu, s, o);
    __shared__ float sh[4];
    if ((threadIdx.x & 31) == 0) sh[threadIdx.x >> 5] = s;
    __syncthreads();
    s = sh[0] + sh[1] + sh[2] + sh[3];
    float scl = SCALEF / fmaxf(sqrtf(s), EPSF);
    float val = v * scl;
    size_t idx = (size_t)row * C + threadIdx.x;
    __nv_bfloat16 h, l;
    hilo(val, h, l);
    g_FnH[idx] = h;
    g_FnL[idx] = l;
}

// ---------------------------------------------------------------------------
// HMMA NT gemm, bf16-split 3 terms. mode 0: corr_1a; mode 3: fused 1+2.
__global__ void __launch_bounds__(256) k_hmma_nt(int mode) {
    extern __shared__ __nv_bfloat16 smem[];
    int ia = blockIdx.x, ib = blockIdx.y;
    int b = blockIdx.z & 7;
    int m = mode;
    if (mode == 3) m = (blockIdx.z < 8) ? 1 : 2;
    int tid = threadIdx.x, wid = tid >> 5, lane = tid & 31;

    const __nv_bfloat16 *aHg, *aLg; float* dst;
    int fsB;
    if (m == 0) {
        aHg = g_FnH + (size_t)(2 * b) * N * C;
        aLg = g_FnL + (size_t)(2 * b) * N * C;
        fsB = 2 * ((b + 1) & 7);
        dst = g_scrA;
    } else if (m == 1) {
        aHg = g_viaH + (size_t)b * N * C;
        aLg = g_viaL + (size_t)b * N * C;
        fsB = 2 * b + 1;
        dst = g_scrA;
    } else {
        aHg = g_FnH + (size_t)(2 * b) * N * C;
        aLg = g_FnL + (size_t)(2 * b) * N * C;
        fsB = 2 * b + 1;
        dst = g_scrB;
    }
    const __nv_bfloat16* bHg = g_FnH + (size_t)fsB * N * C;
    const __nv_bfloat16* bLg = g_FnL + (size_t)fsB * N * C;
    aHg += (size_t)ia * 128 * C; aLg += (size_t)ia * 128 * C;
    bHg += (size_t)ib * 128 * C; bLg += (size_t)ib * 128 * C;

    {
        const uint4* src[4] = {(const uint4*)aHg, (const uint4*)aLg,
                               (const uint4*)bHg, (const uint4*)bLg};
        #pragma unroll
        for (int t4 = 0; t4 < 4; t4++) {
            __nv_bfloat16* dtile = smem + t4 * TSZ;
            #pragma unroll
            for (int i = 0; i < 8; i++) {
                int idx = tid + 256 * i;
                int row = idx >> 4, c8 = idx & 15;
                *(uint4*)(dtile + row * TPAD + c8 * 8) = src[t4][idx];
            }
        }
    }
    __syncthreads();

    int wm = wid & 3, wn = wid >> 2;
    float acc[2][8][4];
    #pragma unroll
    for (int mi = 0; mi < 2; mi++)
        #pragma unroll
        for (int nj = 0; nj < 8; nj++)
            #pragma unroll
            for (int q = 0; q < 4; q++) acc[mi][nj][q] = 0.f;

    uint32_t sbase = smem_u32(smem);
    const int selA[3] = {0, 0, 1};
    const int selB[3] = {2, 3, 2};
    int a_r = lane & 15, a_c = (lane >> 4) << 3;
    int b_r = (lane & 7) + ((lane >> 4) << 3);
    int b_c = ((lane >> 3) & 1) << 3;

    #pragma unroll
    for (int t = 0; t < 3; t++) {
        uint32_t aB = sbase + selA[t] * TSZ * 2;
        uint32_t bBs = sbase + selB[t] * TSZ * 2;
        #pragma unroll
        for (int k8 = 0; k8 < 8; k8++) {
            int kc = k8 * 16;
            uint32_t af[2][4];
            #pragma unroll
            for (int mi = 0; mi < 2; mi++) {
                int row = wm * 32 + mi * 16 + a_r;
                ldm4(af[mi][0], af[mi][1], af[mi][2], af[mi][3],
                     aB + (row * TPAD + kc + a_c) * 2);
            }
            uint32_t bf[4][4];
            #pragma unroll
            for (int nj = 0; nj < 4; nj++) {
                int row = wn * 64 + nj * 16 + b_r;
                ldm4(bf[nj][0], bf[nj][1], bf[nj][2], bf[nj][3],
                     bBs + (row * TPAD + kc + b_c) * 2);
            }
            #pragma unroll
            for (int mi = 0; mi < 2; mi++)
                #pragma unroll
                for (int nj = 0; nj < 4; nj++) {
                    mma16816(acc[mi][2 * nj], af[mi], bf[nj][0], bf[nj][1]);
                    mma16816(acc[mi][2 * nj + 1], af[mi], bf[nj][2], bf[nj][3]);
                }
        }
    }

    {
        int rbase = b * 1024 + ia * 128 + wm * 32 + (lane >> 2);
        int cbase = ib * 128 + wn * 64 + 2 * (lane & 3);
        #pragma unroll
        for (int mi = 0; mi < 2; mi++)
            #pragma unroll
            for (int nj = 0; nj < 8; nj++) {
                float* d0 = dst + (size_t)(rbase + mi * 16) * 1024 + cbase + nj * 8;
                *(float2*)d0 = make_float2(acc[mi][nj][0], acc[mi][nj][1]);
                float* d1 = d0 + 8 * 1024;
                *(float2*)d1 = make_float2(acc[mi][nj][2], acc[mi][nj][3]);
            }
    }
}

// ---------------------------------------------------------------------------
// row softmax of corr_1a (fp32 in scrA) -> bf16 hi/lo smcorr
__global__ void __launch_bounds__(256) k_rowsoftmax() {
    size_t row = blockIdx.x;
    const float4* p = (const float4*)(g_scrA + row * N);
    int tid = threadIdx.x, lane = tid & 31;
    float4 v = p[tid];
    float mx = fmaxf(fmaxf(v.x, v.y), fmaxf(v.z, v.w));
    #pragma unroll
    for (int o = 16; o; o >>= 1) mx = fmaxf(mx, __shfl_xor_sync(0xffffffffu, mx, o));
    __shared__ float shm[8], shs[8];
    if (lane == 0) shm[tid >> 5] = mx;
    __syncthreads();
    mx = fmaxf(fmaxf(fmaxf(shm[0], shm[1]), fmaxf(shm[2], shm[3])),
               fmaxf(fmaxf(shm[4], shm[5]), fmaxf(shm[6], shm[7])));
    float4 e;
    e.x = fex2((v.x - mx) * LOG2E);
    e.y = fex2((v.y - mx) * LOG2E);
    e.z = fex2((v.z - mx) * LOG2E);
    e.w = fex2((v.w - mx) * LOG2E);
    float s = e.x + e.y + e.z + e.w;
    #pragma unroll
    for (int o = 16; o; o >>= 1) s += __shfl_xor_sync(0xffffffffu, s, o);
    if (lane == 0) shs[tid >> 5] = s;
    __syncthreads();
    s = shs[0] + shs[1] + shs[2] + shs[3] + shs[4] + shs[5] + shs[6] + shs[7];
    float inv = 1.0f / s;
    float f[4] = {e.x * inv, e.y * inv, e.z * inv, e.w * inv};
    __nv_bfloat16 h[4], l[4];
    #pragma unroll
    for (int q = 0; q < 4; q++) hilo(f[q], h[q], l[q]);
    __nv_bfloat162* dH = (__nv_bfloat162*)(g_smH + row * N + 4 * tid);
    __nv_bfloat162* dL = (__nv_bfloat162*)(g_smL + row * N + 4 * tid);
    dH[0] = __nv_bfloat162{h[0], h[1]};
    dH[1] = __nv_bfloat162{h[2], h[3]};
    dL[0] = __nv_bfloat162{l[0], l[1]};
    dL[1] = __nv_bfloat162{l[2], l[3]};
}

// ---------------------------------------------------------------------------
// HMMA NN gemm: via[b] = smcorr[b] @ fa[b]; out hi/lo
__global__ void __launch_bounds__(256) k_hmma_nn() {
    extern __shared__ __nv_bfloat16 smem[];
    int rb = blockIdx.x, b = blockIdx.y;
    int tid = threadIdx.x, wid = tid >> 5, lane = tid & 31;
    int fs = 2 * ((b + 1) & 7);

    int wm = wid & 3, wn = wid >> 2;
    float acc[2][8][4];
    #pragma unroll
    for (int mi = 0; mi < 2; mi++)
        #pragma unroll
        for (int nj = 0; nj < 8; nj++)
            #pragma unroll
            for (int q = 0; q < 4; q++) acc[mi][nj][q] = 0.f;

    uint32_t sbase = smem_u32(smem);
    const int AOFF[3] = {AH_O, AH_O, AL_O};
    const int VOFF[3] = {VH_O, VL_O, VH_O};
    int a_r = lane & 15, a_c = (lane >> 4) << 3;
    int bt_r = (lane & 7) + (((lane >> 3) & 1) << 3);
    int bt_c = (lane >> 4) << 3;

    for (int kc = 0; kc < 16; kc++) {
        int kb = kc * 64;
        if (kc) __syncthreads();
        #pragma unroll
        for (int i = 0; i < 4; i++) {
            int idx = tid + 256 * i;
            int r = idx >> 3, c8 = idx & 7;
            size_t so = (size_t)(b * 1024 + rb * 128 + r) * 1024 + kb + c8 * 8;
            *(uint4*)(smem + AH_O + r * APAD + c8 * 8) = *(const uint4*)(g_smH + so);
            *(uint4*)(smem + AL_O + r * APAD + c8 * 8) = *(const uint4*)(g_smL + so);
        }
        #pragma unroll
        for (int i = 0; i < 4; i++) {
            int idx = tid + 256 * i;
            int r = idx >> 4, c8 = idx & 15;
            size_t so = (size_t)(fs * 1024 + kb + r) * 128 + c8 * 8;
            *(uint4*)(smem + VH_O + r * VPAD + c8 * 8) = *(const uint4*)(g_FnH + so);
            *(uint4*)(smem + VL_O + r * VPAD + c8 * 8) = *(const uint4*)(g_FnL + so);
        }
        __syncthreads();

        #pragma unroll
        for (int t = 0; t < 3; t++) {
            #pragma unroll
            for (int k16 = 0; k16 < 4; k16++) {
                int kk = k16 * 16;
                uint32_t af[2][4];
                #pragma unroll
                for (int mi = 0; mi < 2; mi++) {
                    int row = wm * 32 + mi * 16 + a_r;
                    ldm4(af[mi][0], af[mi][1], af[mi][2], af[mi][3],
                         sbase + (AOFF[t] + row * APAD + kk + a_c) * 2);
                }
                uint32_t bf[4][4];
                #pragma unroll
                for (int nj = 0; nj < 4; nj++) {
                    int krow = kk + bt_r;
                    int ccol = wn * 64 + nj * 16 + bt_c;
                    ldm4t(bf[nj][0], bf[nj][1], bf[nj][2], bf[nj][3],
                          sbase + (VOFF[t] + krow * VPAD + ccol) * 2);
                }
                #pragma unroll
                for (int mi = 0; mi < 2; mi++)
                    #pragma unroll
                    for (int nj = 0; nj < 4; nj++) {
                        mma16816(acc[mi][2 * nj], af[mi], bf[nj][0], bf[nj][1]);
                        mma16816(acc[mi][2 * nj + 1], af[mi], bf[nj][2], bf[nj][3]);
                    }
            }
        }
    }

    {
        int rbase = b * 1024 + rb * 128 + wm * 32 + (lane >> 2);
        int cbase = wn * 64 + 2 * (lane & 3);
        #pragma unroll
        for (int mi = 0; mi < 2; mi++)
            #pragma unroll
            for (int nj = 0; nj < 8; nj++) {
                #pragma unroll
                for (int half = 0; half < 2; half++) {
                    int row = rbase + mi * 16 + half * 8;
                    int col = cbase + nj * 8;
                    float v0 = acc[mi][nj][2 * half], v1 = acc[mi][nj][2 * half + 1];
                    __nv_bfloat16 h0, l0, h1, l1;
                    hilo(v0, h0, l0);
                    hilo(v1, h1, l1);
                    size_t o = (size_t)row * C + col;
                    *(__nv_bfloat162*)(g_viaH + o) = __nv_bfloat162{h0, h1};
                    *(__nv_bfloat162*)(g_viaL + o) = __nv_bfloat162{l0, l1};
                }
            }
    }
}

// ---------------------------------------------------------------------------
__device__ __forceinline__ void batch_bar(int b, unsigned target) {
    __syncthreads();
    if (threadIdx.x == 0) {
        unsigned v;
        asm volatile("red.release.gpu.add.u32 [%0], %1;"
                     :: "l"(&g_bar[b]), "r"(1u) : "memory");
        do {
            asm volatile("ld.acquire.gpu.u32 %0, [%1];"
                         : "=r"(v) : "l"(&g_bar[b]) : "memory");
        } while (v < target);
    }
    __syncthreads();
}

// ---------------------------------------------------------------------------
// per-row stats for k_final (runs on the 20 extra blocks, warp-per-row)
__device__ void stats_work(int sbid) {
    int tid = threadIdx.x, wid = tid >> 5, lane = tid & 31;
    int w = sbid * 16 + wid;
    for (int row = w; row < B * N; row += STATS_BLKS * 16) {
        const float* pA = g_scrA + (size_t)row * N;
        const float* pB = g_scrB + (size_t)row * N;
        float vv[32];
        #pragma unroll
        for (int j = 0; j < 8; j++) {
            float4 f = *(const float4*)(pA + lane * 4 + 128 * j);
            vv[4 * j] = f.x; vv[4 * j + 1] = f.y; vv[4 * j + 2] = f.z; vv[4 * j + 3] = f.w;
        }
        float mx = -1e30f; int arg = 0;
        #pragma unroll
        for (int j = 0; j < 32; j++) {
            int idx = lane * 4 + 128 * (j >> 2) + (j & 3);
            if (vv[j] > mx) { mx = vv[j]; arg = idx; }
        }
        #pragma unroll
        for (int o = 16; o; o >>= 1) {
            float m2 = __shfl_xor_sync(0xffffffffu, mx, o);
            int a2 = __shfl_xor_sync(0xffffffffu, arg, o);
            if (m2 > mx || (m2 == mx && a2 < arg)) { mx = m2; arg = a2; }
        }
        float s = 0.f;
        #pragma unroll
        for (int j = 0; j < 32; j++) s += fex2((vv[j] - mx) * LOG2E);
        #pragma unroll
        for (int o = 16; o; o >>= 1) s += __shfl_xor_sync(0xffffffffu, s, o);
        if (lane == 0) {
            g_maxA[row] = mx; g_sumA[row] = s;
            if (arg == (row & 1023)) atomicAdd(&g_correct, 1);
        }
        #pragma unroll
        for (int j = 0; j < 8; j++) {
            float4 f = *(const float4*)(pB + lane * 4 + 128 * j);
            vv[4 * j] = f.x; vv[4 * j + 1] = f.y; vv[4 * j + 2] = f.z; vv[4 * j + 3] = f.w;
        }
        mx = -1e30f;
        #pragma unroll
        for (int j = 0; j < 32; j++) mx = fmaxf(mx, vv[j]);
        #pragma unroll
        for (int o = 16; o; o >>= 1) mx = fmaxf(mx, __shfl_xor_sync(0xffffffffu, mx, o));
        s = 0.f;
        #pragma unroll
        for (int j = 0; j < 32; j++) s += fex2((vv[j] - mx) * LOG2E);
        #pragma unroll
        for (int o = 16; o; o >>= 1) s += __shfl_xor_sync(0xffffffffu, s, o);
        if (lane == 0) { g_maxB[row] = mx; g_sumB[row] = s; }
    }
}

// persistent sinkhorn + concurrent stats blocks.
// it==0: exact online-LSE column path (handles full dynamic range; c=0 start).
// it>=1: row-stochastic identity — column q accumulated by pure FMA from the
// row-phase e values (no extra ex2); safe because c from it0 bounds all
// column maxima of z+r near 0 (no underflow of the whole column sum).
__global__ void __launch_bounds__(512) k_sinkhorn() {
    if (blockIdx.x >= B * SNB) { stats_work(blockIdx.x - B * SNB); return; }
    int b = blockIdx.x >> 4, sub = blockIdx.x & 15;
    const float* Mrows = g_scrA + (size_t)(b * 1024 + sub * 64) * N;
    int tid = threadIdx.x, warp = tid >> 5, lane = tid & 31;
    __shared__ float sc[1024];
    __shared__ float rp[8][512];
    __shared__ float rmx[8];
    __shared__ float rsm[64];
    __shared__ float ris[64];
    unsigned bar_t = 0;
    sc[tid] = 0.f;
    sc[tid + 512] = 0.f;
    __syncthreads();

    for (int it = 0; it < 30; it++) {
        int par = it & 1;
        float cc0 = sc[2 * tid], cc1 = sc[2 * tid + 1];

        if (it == 0) {
            // ---------- exact path (round-10 proven) ----------
            float amx0 = -1e30f, amx1 = -1e30f;
            float as0 = 0.f, as1 = 0.f;
            for (int g = 0; g < 8; g++) {
                float2 z[8];
                #pragma unroll
                for (int rr = 0; rr < 8; rr++) {
                    float2 y = *(const float2*)(Mrows + (size_t)(g * 8 + rr) * N + 2 * tid);
                    z[rr] = make_float2(fmaf(y.x, K2, cc0), fmaf(y.y, K2, cc1));
                }
                #pragma unroll
                for (int rr = 0; rr < 8; rr++)
                    rp[rr][tid] = fmaxf(z[rr].x, z[rr].y);
                __syncthreads();
                if (warp < 8) {
                    float mx = -1e30f;
                    #pragma unroll
                    for (int i = 0; i < 16; i++) mx = fmaxf(mx, rp[warp][lane + 32 * i]);
                    #pragma unroll
                    for (int o = 16; o; o >>= 1)
                        mx = fmaxf(mx, __shfl_xor_sync(0xffffffffu, mx, o));
                    if (lane == 0) rmx[warp] = mx;
                }
                __syncthreads();
                #pragma unroll
                for (int rr = 0; rr < 8; rr++) {
                    float m = rmx[rr];
                    rp[rr][tid] = fex2(z[rr].x - m) + fex2(z[rr].y - m);
                }
                __syncthreads();
                if (warp < 8) {
                    float s = 0.f;
                    #pragma unroll
                    for (int i = 0; i < 16; i++) s += rp[warp][lane + 32 * i];
                    #pragma unroll
                    for (int o = 16; o; o >>= 1) s += __shfl_xor_sync(0xffffffffu, s, o);
                    if (lane == 0) rsm[g * 8 + warp] = -(rmx[warp] + flg2(s));
                }
                __syncthreads();
                #pragma unroll
                for (int rr = 0; rr < 8; rr++) {
                    float rv = rsm[g * 8 + rr];
                    onl(amx0, as0, z[rr].x + rv);
                    onl(amx1, as1, z[rr].y + rv);
                }
            }
            float2* cp = g_cp + (size_t)par * (B * SNB * N) + (size_t)(b * 16 + sub) * N;
            cp[2 * tid] = make_float2(amx0, as0);
            cp[2 * tid + 1] = make_float2(amx1, as1);
            bar_t += SNB; batch_bar(b, bar_t);

            const float2* base = g_cp + (size_t)par * (B * SNB * N) + (size_t)b * 16 * N;
            #pragma unroll
            for (int h = 0; h < 2; h++) {
                int col = tid + 512 * h;
                float mx = -1e30f, s = 0.f;
                #pragma unroll
                for (int k = 0; k < 16; k++) {
                    float2 p2 = base[(size_t)k * N + col];
                    comb(mx, s, p2.x, p2.y);
                }
                sc[col] = -(mx + flg2(s));
            }
            __syncthreads();
        } else {
            // ---------- fast path: row-stochastic FMA accumulation ----------
            float q0 = 0.f, q1 = 0.f;
            for (int g = 0; g < 8; g++) {
                float2 z[8];
                #pragma unroll
                for (int rr = 0; rr < 8; rr++) {
                    float2 y = *(const float2*)(Mrows + (size_t)(g * 8 + rr) * N + 2 * tid);
                    z[rr] = make_float2(fmaf(y.x, K2, cc0), fmaf(y.y, K2, cc1));
                }
                #pragma unroll
                for (int rr = 0; rr < 8; rr++)
                    rp[rr][tid] = fmaxf(z[rr].x, z[rr].y);
                __syncthreads();
                if (warp < 8) {
                    float mx = -1e30f;
                    #pragma unroll
                    for (int i = 0; i < 16; i++) mx = fmaxf(mx, rp[warp][lane + 32 * i]);
                    #pragma unroll
                    for (int o = 16; o; o >>= 1)
                        mx = fmaxf(mx, __shfl_xor_sync(0xffffffffu, mx, o));
                    if (lane == 0) rmx[warp] = mx;
                }
                __syncthreads();
                // e = ex2(z - mx) kept in regs (z overwritten)
                #pragma unroll
                for (int rr = 0; rr < 8; rr++) {
                    float m = rmx[rr];
                    z[rr].x = fex2(z[rr].x - m);
                    z[rr].y = fex2(z[rr].y - m);
                    rp[rr][tid] = z[rr].x + z[rr].y;
                }
                __syncthreads();
                if (warp < 8) {
                    float s = 0.f;
                    #pragma unroll
                    for (int i = 0; i < 16; i++) s += rp[warp][lane + 32 * i];
                    #pragma unroll
                    for (int o = 16; o; o >>= 1) s += __shfl_xor_sync(0xffffffffu, s, o);
                    if (lane == 0) {
                        float lg = flg2(s);
                        rsm[g * 8 + warp] = -(rmx[warp] + lg);
                        ris[g * 8 + warp] = fex2(-lg);   // 1/s
                    }
                }
                __syncthreads();
                #pragma unroll
                for (int rr = 0; rr < 8; rr++) {
                    float w = ris[g * 8 + rr];
                    q0 = fmaf(z[rr].x, w, q0);
                    q1 = fmaf(z[rr].y, w, q1);
                }
            }
            float2* cp = g_cp + (size_t)par * (B * SNB * N) + (size_t)(b * 16 + sub) * N;
            cp[2 * tid] = make_float2(0.f, q0);
            cp[2 * tid + 1] = make_float2(0.f, q1);
            bar_t += SNB; batch_bar(b, bar_t);

            const float2* base = g_cp + (size_t)par * (B * SNB * N) + (size_t)b * 16 * N;
            #pragma unroll
            for (int h = 0; h < 2; h++) {
                int col = tid + 512 * h;
                float s = 0.f;
                #pragma unroll
                for (int k = 0; k < 16; k++) s += base[(size_t)k * N + col].y;
                sc[col] = sc[col] - flg2(s);
            }
            __syncthreads();
        }
    }

    if (tid < 64) {
        g_r[b * N + sub * 64 + tid] = rsm[tid];
        g_c[b * N + sub * 64 + tid] = sc[sub * 64 + tid];
    }
}

// ---------------------------------------------------------------------------
// fused final pass: uses precomputed row stats; dist + softmaxes + sink
__global__ void __launch_bounds__(256) k_final(const float* __restrict__ pc0) {
    int rowi = blockIdx.x;
    int b = rowi >> 10, n = rowi & 1023;
    size_t row = rowi;
    const float* pA = g_scrA + row * N;
    const float* pB = g_scrB + row * N;
    int tid = threadIdx.x, lane = tid & 31, warp = tid >> 5;

    __shared__ float spc[3 * 1024];
    __shared__ float scv[1024];
    const float* pc = pc0 + (size_t)b * N * 3;
    for (int i = tid; i < 3 * 1024; i += 256) spc[i] = pc[i];
    for (int i = tid; i < 1024; i += 256) scv[i] = g_c[b * N + i];

    float mA = g_maxA[row], iA = 1.0f / g_sumA[row];
    float mB = g_maxB[row], iB = 1.0f / g_sumB[row];
    float rn = g_r[row];
    __syncthreads();

    float px = spc[3 * n], py = spc[3 * n + 1], pz = spc[3 * n + 2];
    float aL = 0.f, aC = 0.f, aP = 0.f;
    #pragma unroll
    for (int t = 0; t < 4; t++) {
        int m = tid + 256 * t;
        float xA = pA[m], xB = pB[m];
        float smA = fex2((xA - mA) * LOG2E) * iA;
        float smB = fex2((xB - mB) * LOG2E) * iB;
        float dx = px - spc[3 * m], dy = py - spc[3 * m + 1], dz = pz - spc[3 * m + 2];
        float d2 = dx * dx + dy * dy + dz * dz;
        float dist = sqrtf(sqrtf(d2));
        aL += dist * (smA + smB);
        float sink = fex2(xA * K2 + rn + scv[m]);
        aC += fabsf(sink - smA);
        aP += (m == n) ? fabsf(1.0f - sink) : sink;
    }
    #pragma unroll
    for (int o = 16; o; o >>= 1) {
        aL += __shfl_xor_sync(0xffffffffu, aL, o);
        aC += __shfl_xor_sync(0xffffffffu, aC, o);
        aP += __shfl_xor_sync(0xffffffffu, aP, o);
    }
    __shared__ float s1[8], s2[8], s3[8];
    if (lane == 0) { s1[warp] = aL; s2[warp] = aC; s3[warp] = aP; }
    __syncthreads();
    if (tid == 0) {
        float tL = 0.f, tC = 0.f, tP = 0.f;
        #pragma unroll
        for (int q = 0; q < 8; q++) { tL += s1[q]; tC += s2[q]; tP += s3[q]; }
        g_pL[row] = tL; g_pC[row] = tC; g_pP[row] = tP;
    }
}

// ---------------------------------------------------------------------------
__global__ void __launch_bounds__(256) k_out(float* __restrict__ out) {
    int tid = threadIdx.x;
    float sL = 0.f, sC = 0.f, sP = 0.f;
    for (int i = tid; i < B * N; i += 256) {
        sL += g_pL[i]; sC += g_pC[i]; sP += g_pP[i];
    }
    #pragma unroll
    for (int o = 16; o; o >>= 1) {
        sL += __shfl_xor_sync(0xffffffffu, sL, o);
        sC += __shfl_xor_sync(0xffffffffu, sC, o);
        sP += __shfl_xor_sync(0xffffffffu, sP, o);
    }
    __shared__ float s1[8], s2[8], s3[8];
    if ((tid & 31) == 0) { s1[tid >> 5] = sL; s2[tid >> 5] = sC; s3[tid >> 5] = sP; }
    __syncthreads();
    if (tid == 0) {
        float tL = 0.f, tC = 0.f, tP = 0.f;
        #pragma unroll
        for (int q = 0; q < 8; q++) { tL += s1[q]; tC += s2[q]; tP += s3[q]; }
        float invN = 1.0f / (float)N;
        float loss = tL * invN;
        float Lc = 3.0f * tC * invN;
        float perm = 3.0f * tP * invN;
        float corr = (float)g_correct;
        float invB = 1.0f / (float)B;
        out[0] = (loss + Lc) * invB;
        out[1] = loss * invB;
        out[2] = Lc * invB;
        out[3] = corr * invB;
        out[4] = perm * invB;
    }
}

// ---------------------------------------------------------------------------
extern "C" void kernel_launch(void* const* d_in, const int* in_sizes, int n_in,
                              void* d_out, int out_size) {
    const float* feats = (const float*)d_in[0];
    const float* pc0 = (const float*)d_in[1];
    float* out = (float*)d_out;

    const int nt_smem = 4 * TSZ * sizeof(__nv_bfloat16);
    const int nn_smem = NN_ELEMS * sizeof(__nv_bfloat16);
    static bool attr_done = false;
    if (!attr_done) {
        cudaFuncSetAttribute(k_hmma_nt, cudaFuncAttributeMaxDynamicSharedMemorySize,
                             nt_smem);
        cudaFuncSetAttribute(k_hmma_nn, cudaFuncAttributeMaxDynamicSharedMemorySize,
                             nn_smem);
        attr_done = true;
    }

    k_init<<<32, 256>>>();
    k_norm<<<2 * B * N, 128>>>(feats);
    k_hmma_nt<<<dim3(8, 8, 8), 256, nt_smem>>>(0);    // corr_1a -> scrA
    k_rowsoftmax<<<B * N, 256>>>();                   // smcorr hi/lo bf16
    k_hmma_nn<<<dim3(8, 8), 256, nn_smem>>>();        // via hi/lo
    k_hmma_nt<<<dim3(8, 8, 16), 256, nt_smem>>>(3);   // corr_1a2 + corr_12
    k_sinkhorn<<<B * SNB + STATS_BLKS, 512>>>();      // + concurrent stats
    k_final<<<B * N, 256>>>(pc0);
    k_out<<<1, 256>>>(out);
}

// round 13
// speedup vs baseline: 1.6302x; 1.3255x over previous
#include <cuda_runtime.h>
#include <cuda_bf16.h>
#include <cstdint>

namespace {
constexpr int B = 8;
constexpr int N = 1024;
constexpr int C = 128;
constexpr float SCALEF = 20.0f;
constexpr float EPSF = 1e-12f;
constexpr float LOG2E = 1.4426950408889634f;
constexpr float K2 = 4.808983469629878f;   // log2(e)/0.3
constexpr int SNB = 16;                    // sinkhorn blocks per batch
constexpr int STATS_BLKS = 20;             // extra stats blocks
constexpr int TPAD = 136;
constexpr int TSZ = 128 * TPAD;
constexpr int APAD = 72;
constexpr int VPAD = 136;
constexpr int AH_O = 0;
constexpr int AL_O = 128 * APAD;
constexpr int VH_O = AL_O + 128 * APAD;
constexpr int VL_O = VH_O + 64 * VPAD;
constexpr int NN_ELEMS = VL_O + 64 * VPAD;
constexpr int SINK_SMEM = (1024 + 16 * 1024) * 4;  // sc + sq staging
}

__device__ float g_scrA[(size_t)B * N * N];
__device__ float g_scrB[(size_t)B * N * N];
__device__ __nv_bfloat16 g_FnH[2 * B * N * C];
__device__ __nv_bfloat16 g_FnL[2 * B * N * C];
__device__ __nv_bfloat16 g_viaH[B * N * C];
__device__ __nv_bfloat16 g_viaL[B * N * C];
__device__ __nv_bfloat16 g_smH[(size_t)B * N * N];
__device__ __nv_bfloat16 g_smL[(size_t)B * N * N];
__device__ float g_cpf[2 * B * SNB * N];   // double-buffered column partial sums
__device__ float g_r[B * N];
__device__ float g_c[B * N];
__device__ float g_maxA[B * N], g_sumA[B * N];
__device__ float g_maxB[B * N], g_sumB[B * N];
__device__ unsigned g_bar[B];
__device__ int g_correct;
__device__ float g_pL[B * N], g_pC[B * N], g_pP[B * N];

__device__ __forceinline__ float fex2(float x) {
    float y; asm("ex2.approx.ftz.f32 %0, %1;" : "=f"(y) : "f"(x)); return y;
}
__device__ __forceinline__ float flg2(float x) {
    float y; asm("lg2.approx.ftz.f32 %0, %1;" : "=f"(y) : "f"(x)); return y;
}
__device__ __forceinline__ uint32_t smem_u32(const void* p) {
    uint32_t a;
    asm("{ .reg .u64 t; cvta.to.shared.u64 t, %1; cvt.u32.u64 %0, t; }"
        : "=r"(a) : "l"(p));
    return a;
}
__device__ __forceinline__ void ldm4(uint32_t& r0, uint32_t& r1, uint32_t& r2,
                                     uint32_t& r3, uint32_t addr) {
    asm volatile("ldmatrix.sync.aligned.m8n8.x4.shared.b16 {%0,%1,%2,%3}, [%4];"
                 : "=r"(r0), "=r"(r1), "=r"(r2), "=r"(r3) : "r"(addr));
}
__device__ __forceinline__ void ldm4t(uint32_t& r0, uint32_t& r1, uint32_t& r2,
                                      uint32_t& r3, uint32_t addr) {
    asm volatile("ldmatrix.sync.aligned.m8n8.x4.trans.shared.b16 {%0,%1,%2,%3}, [%4];"
                 : "=r"(r0), "=r"(r1), "=r"(r2), "=r"(r3) : "r"(addr));
}
__device__ __forceinline__ void mma16816(float* c, const uint32_t* a,
                                         uint32_t b0, uint32_t b1) {
    asm volatile(
        "mma.sync.aligned.m16n8k16.row.col.f32.bf16.bf16.f32 "
        "{%0,%1,%2,%3}, {%4,%5,%6,%7}, {%8,%9}, {%0,%1,%2,%3};"
        : "+f"(c[0]), "+f"(c[1]), "+f"(c[2]), "+f"(c[3])
        : "r"(a[0]), "r"(a[1]), "r"(a[2]), "r"(a[3]), "r"(b0), "r"(b1));
}
__device__ __forceinline__ void hilo(float v, __nv_bfloat16& h, __nv_bfloat16& l) {
    h = __float2bfloat16(v);
    l = __float2bfloat16(v - __bfloat162float(h));
}

// ---------------------------------------------------------------------------
__global__ void k_init() {
    int i = blockIdx.x * blockDim.x + threadIdx.x;
    if (i < B) g_bar[i] = 0u;
    if (i == 0) g_correct = 0;
}

__global__ void __launch_bounds__(128) k_norm(const float* __restrict__ feats) {
    int row = blockIdx.x;
    const float* p = feats + (size_t)row * C;
    float v = p[threadIdx.x];
    float s = v * v;
    #pragma unroll
    for (int o = 16; o; o >>= 1) s += __shfl_xor_sync(0xffffffffu, s, o);
    __shared__ float sh[4];
    if ((threadIdx.x & 31) == 0) sh[threadIdx.x >> 5] = s;
    __syncthreads();
    s = sh[0] + sh[1] + sh[2] + sh[3];
    float scl = SCALEF / fmaxf(sqrtf(s), EPSF);
    float val = v * scl;
    size_t idx = (size_t)row * C + threadIdx.x;
    __nv_bfloat16 h, l;
    hilo(val, h, l);
    g_FnH[idx] = h;
    g_FnL[idx] = l;
}

// ---------------------------------------------------------------------------
// HMMA NT gemm, bf16-split 3 terms. mode 0: corr_1a; mode 3: fused 1+2.
__global__ void __launch_bounds__(256) k_hmma_nt(int mode) {
    extern __shared__ __nv_bfloat16 smem[];
    int ia = blockIdx.x, ib = blockIdx.y;
    int b = blockIdx.z & 7;
    int m = mode;
    if (mode == 3) m = (blockIdx.z < 8) ? 1 : 2;
    int tid = threadIdx.x, wid = tid >> 5, lane = tid & 31;

    const __nv_bfloat16 *aHg, *aLg; float* dst;
    int fsB;
    if (m == 0) {
        aHg = g_FnH + (size_t)(2 * b) * N * C;
        aLg = g_FnL + (size_t)(2 * b) * N * C;
        fsB = 2 * ((b + 1) & 7);
        dst = g_scrA;
    } else if (m == 1) {
        aHg = g_viaH + (size_t)b * N * C;
        aLg = g_viaL + (size_t)b * N * C;
        fsB = 2 * b + 1;
        dst = g_scrA;
    } else {
        aHg = g_FnH + (size_t)(2 * b) * N * C;
        aLg = g_FnL + (size_t)(2 * b) * N * C;
        fsB = 2 * b + 1;
        dst = g_scrB;
    }
    const __nv_bfloat16* bHg = g_FnH + (size_t)fsB * N * C;
    const __nv_bfloat16* bLg = g_FnL + (size_t)fsB * N * C;
    aHg += (size_t)ia * 128 * C; aLg += (size_t)ia * 128 * C;
    bHg += (size_t)ib * 128 * C; bLg += (size_t)ib * 128 * C;

    {
        const uint4* src[4] = {(const uint4*)aHg, (const uint4*)aLg,
                               (const uint4*)bHg, (const uint4*)bLg};
        #pragma unroll
        for (int t4 = 0; t4 < 4; t4++) {
            __nv_bfloat16* dtile = smem + t4 * TSZ;
            #pragma unroll
            for (int i = 0; i < 8; i++) {
                int idx = tid + 256 * i;
                int row = idx >> 4, c8 = idx & 15;
                *(uint4*)(dtile + row * TPAD + c8 * 8) = src[t4][idx];
            }
        }
    }
    __syncthreads();

    int wm = wid & 3, wn = wid >> 2;
    float acc[2][8][4];
    #pragma unroll
    for (int mi = 0; mi < 2; mi++)
        #pragma unroll
        for (int nj = 0; nj < 8; nj++)
            #pragma unroll
            for (int q = 0; q < 4; q++) acc[mi][nj][q] = 0.f;

    uint32_t sbase = smem_u32(smem);
    const int selA[3] = {0, 0, 1};
    const int selB[3] = {2, 3, 2};
    int a_r = lane & 15, a_c = (lane >> 4) << 3;
    int b_r = (lane & 7) + ((lane >> 4) << 3);
    int b_c = ((lane >> 3) & 1) << 3;

    #pragma unroll
    for (int t = 0; t < 3; t++) {
        uint32_t aB = sbase + selA[t] * TSZ * 2;
        uint32_t bBs = sbase + selB[t] * TSZ * 2;
        #pragma unroll
        for (int k8 = 0; k8 < 8; k8++) {
            int kc = k8 * 16;
            uint32_t af[2][4];
            #pragma unroll
            for (int mi = 0; mi < 2; mi++) {
                int row = wm * 32 + mi * 16 + a_r;
                ldm4(af[mi][0], af[mi][1], af[mi][2], af[mi][3],
                     aB + (row * TPAD + kc + a_c) * 2);
            }
            uint32_t bf[4][4];
            #pragma unroll
            for (int nj = 0; nj < 4; nj++) {
                int row = wn * 64 + nj * 16 + b_r;
                ldm4(bf[nj][0], bf[nj][1], bf[nj][2], bf[nj][3],
                     bBs + (row * TPAD + kc + b_c) * 2);
            }
            #pragma unroll
            for (int mi = 0; mi < 2; mi++)
                #pragma unroll
                for (int nj = 0; nj < 4; nj++) {
                    mma16816(acc[mi][2 * nj], af[mi], bf[nj][0], bf[nj][1]);
                    mma16816(acc[mi][2 * nj + 1], af[mi], bf[nj][2], bf[nj][3]);
                }
        }
    }

    {
        int rbase = b * 1024 + ia * 128 + wm * 32 + (lane >> 2);
        int cbase = ib * 128 + wn * 64 + 2 * (lane & 3);
        #pragma unroll
        for (int mi = 0; mi < 2; mi++)
            #pragma unroll
            for (int nj = 0; nj < 8; nj++) {
                float* d0 = dst + (size_t)(rbase + mi * 16) * 1024 + cbase + nj * 8;
                *(float2*)d0 = make_float2(acc[mi][nj][0], acc[mi][nj][1]);
                float* d1 = d0 + 8 * 1024;
                *(float2*)d1 = make_float2(acc[mi][nj][2], acc[mi][nj][3]);
            }
    }
}

// ---------------------------------------------------------------------------
// row softmax of corr_1a (fp32 in scrA) -> bf16 hi/lo smcorr
__global__ void __launch_bounds__(256) k_rowsoftmax() {
    size_t row = blockIdx.x;
    const float4* p = (const float4*)(g_scrA + row * N);
    int tid = threadIdx.x, lane = tid & 31;
    float4 v = p[tid];
    float mx = fmaxf(fmaxf(v.x, v.y), fmaxf(v.z, v.w));
    #pragma unroll
    for (int o = 16; o; o >>= 1) mx = fmaxf(mx, __shfl_xor_sync(0xffffffffu, mx, o));
    __shared__ float shm[8], shs[8];
    if (lane == 0) shm[tid >> 5] = mx;
    __syncthreads();
    mx = fmaxf(fmaxf(fmaxf(shm[0], shm[1]), fmaxf(shm[2], shm[3])),
               fmaxf(fmaxf(shm[4], shm[5]), fmaxf(shm[6], shm[7])));
    float4 e;
    e.x = fex2((v.x - mx) * LOG2E);
    e.y = fex2((v.y - mx) * LOG2E);
    e.z = fex2((v.z - mx) * LOG2E);
    e.w = fex2((v.w - mx) * LOG2E);
    float s = e.x + e.y + e.z + e.w;
    #pragma unroll
    for (int o = 16; o; o >>= 1) s += __shfl_xor_sync(0xffffffffu, s, o);
    if (lane == 0) shs[tid >> 5] = s;
    __syncthreads();
    s = shs[0] + shs[1] + shs[2] + shs[3] + shs[4] + shs[5] + shs[6] + shs[7];
    float inv = 1.0f / s;
    float f[4] = {e.x * inv, e.y * inv, e.z * inv, e.w * inv};
    __nv_bfloat16 h[4], l[4];
    #pragma unroll
    for (int q = 0; q < 4; q++) hilo(f[q], h[q], l[q]);
    __nv_bfloat162* dH = (__nv_bfloat162*)(g_smH + row * N + 4 * tid);
    __nv_bfloat162* dL = (__nv_bfloat162*)(g_smL + row * N + 4 * tid);
    dH[0] = __nv_bfloat162{h[0], h[1]};
    dH[1] = __nv_bfloat162{h[2], h[3]};
    dL[0] = __nv_bfloat162{l[0], l[1]};
    dL[1] = __nv_bfloat162{l[2], l[3]};
}

// ---------------------------------------------------------------------------
// HMMA NN gemm: via[b] = smcorr[b] @ fa[b]; out hi/lo
__global__ void __launch_bounds__(256) k_hmma_nn() {
    extern __shared__ __nv_bfloat16 smem[];
    int rb = blockIdx.x, b = blockIdx.y;
    int tid = threadIdx.x, wid = tid >> 5, lane = tid & 31;
    int fs = 2 * ((b + 1) & 7);

    int wm = wid & 3, wn = wid >> 2;
    float acc[2][8][4];
    #pragma unroll
    for (int mi = 0; mi < 2; mi++)
        #pragma unroll
        for (int nj = 0; nj < 8; nj++)
            #pragma unroll
            for (int q = 0; q < 4; q++) acc[mi][nj][q] = 0.f;

    uint32_t sbase = smem_u32(smem);
    const int AOFF[3] = {AH_O, AH_O, AL_O};
    const int VOFF[3] = {VH_O, VL_O, VH_O};
    int a_r = lane & 15, a_c = (lane >> 4) << 3;
    int bt_r = (lane & 7) + (((lane >> 3) & 1) << 3);
    int bt_c = (lane >> 4) << 3;

    for (int kc = 0; kc < 16; kc++) {
        int kb = kc * 64;
        if (kc) __syncthreads();
        #pragma unroll
        for (int i = 0; i < 4; i++) {
            int idx = tid + 256 * i;
            int r = idx >> 3, c8 = idx & 7;
            size_t so = (size_t)(b * 1024 + rb * 128 + r) * 1024 + kb + c8 * 8;
            *(uint4*)(smem + AH_O + r * APAD + c8 * 8) = *(const uint4*)(g_smH + so);
            *(uint4*)(smem + AL_O + r * APAD + c8 * 8) = *(const uint4*)(g_smL + so);
        }
        #pragma unroll
        for (int i = 0; i < 4; i++) {
            int idx = tid + 256 * i;
            int r = idx >> 4, c8 = idx & 15;
            size_t so = (size_t)(fs * 1024 + kb + r) * 128 + c8 * 8;
            *(uint4*)(smem + VH_O + r * VPAD + c8 * 8) = *(const uint4*)(g_FnH + so);
            *(uint4*)(smem + VL_O + r * VPAD + c8 * 8) = *(const uint4*)(g_FnL + so);
        }
        __syncthreads();

        #pragma unroll
        for (int t = 0; t < 3; t++) {
            #pragma unroll
            for (int k16 = 0; k16 < 4; k16++) {
                int kk = k16 * 16;
                uint32_t af[2][4];
                #pragma unroll
                for (int mi = 0; mi < 2; mi++) {
                    int row = wm * 32 + mi * 16 + a_r;
                    ldm4(af[mi][0], af[mi][1], af[mi][2], af[mi][3],
                         sbase + (AOFF[t] + row * APAD + kk + a_c) * 2);
                }
                uint32_t bf[4][4];
                #pragma unroll
                for (int nj = 0; nj < 4; nj++) {
                    int krow = kk + bt_r;
                    int ccol = wn * 64 + nj * 16 + bt_c;
                    ldm4t(bf[nj][0], bf[nj][1], bf[nj][2], bf[nj][3],
                          sbase + (VOFF[t] + krow * VPAD + ccol) * 2);
                }
                #pragma unroll
                for (int mi = 0; mi < 2; mi++)
                    #pragma unroll
                    for (int nj = 0; nj < 4; nj++) {
                        mma16816(acc[mi][2 * nj], af[mi], bf[nj][0], bf[nj][1]);
                        mma16816(acc[mi][2 * nj + 1], af[mi], bf[nj][2], bf[nj][3]);
                    }
            }
        }
    }

    {
        int rbase = b * 1024 + rb * 128 + wm * 32 + (lane >> 2);
        int cbase = wn * 64 + 2 * (lane & 3);
        #pragma unroll
        for (int mi = 0; mi < 2; mi++)
            #pragma unroll
            for (int nj = 0; nj < 8; nj++) {
                #pragma unroll
                for (int half = 0; half < 2; half++) {
                    int row = rbase + mi * 16 + half * 8;
                    int col = cbase + nj * 8;
                    float v0 = acc[mi][nj][2 * half], v1 = acc[mi][nj][2 * half + 1];
                    __nv_bfloat16 h0, l0, h1, l1;
                    hilo(v0, h0, l0);
                    hilo(v1, h1, l1);
                    size_t o = (size_t)row * C + col;
                    *(__nv_bfloat162*)(g_viaH + o) = __nv_bfloat162{h0, h1};
                    *(__nv_bfloat162*)(g_viaL + o) = __nv_bfloat162{l0, l1};
                }
            }
    }
}

// ---------------------------------------------------------------------------
__device__ __forceinline__ void batch_bar(int b, unsigned target) {
    __syncthreads();
    if (threadIdx.x == 0) {
        unsigned v;
        asm volatile("red.release.gpu.add.u32 [%0], %1;"
                     :: "l"(&g_bar[b]), "r"(1u) : "memory");
        do {
            asm volatile("ld.acquire.gpu.u32 %0, [%1];"
                         : "=r"(v) : "l"(&g_bar[b]) : "memory");
        } while (v < target);
    }
    __syncthreads();
}

// ---------------------------------------------------------------------------
// per-row stats for k_final (runs on the 20 extra blocks, warp-per-row)
__device__ void stats_work(int sbid) {
    int tid = threadIdx.x, wid = tid >> 5, lane = tid & 31;
    int w = sbid * 16 + wid;
    for (int row = w; row < B * N; row += STATS_BLKS * 16) {
        const float* pA = g_scrA + (size_t)row * N;
        const float* pB = g_scrB + (size_t)row * N;
        float vv[32];
        #pragma unroll
        for (int j = 0; j < 8; j++) {
            float4 f = *(const float4*)(pA + lane * 4 + 128 * j);
            vv[4 * j] = f.x; vv[4 * j + 1] = f.y; vv[4 * j + 2] = f.z; vv[4 * j + 3] = f.w;
        }
        float mx = -1e30f; int arg = 0;
        #pragma unroll
        for (int j = 0; j < 32; j++) {
            int idx = lane * 4 + 128 * (j >> 2) + (j & 3);
            if (vv[j] > mx) { mx = vv[j]; arg = idx; }
        }
        #pragma unroll
        for (int o = 16; o; o >>= 1) {
            float m2 = __shfl_xor_sync(0xffffffffu, mx, o);
            int a2 = __shfl_xor_sync(0xffffffffu, arg, o);
            if (m2 > mx || (m2 == mx && a2 < arg)) { mx = m2; arg = a2; }
        }
        float s = 0.f;
        #pragma unroll
        for (int j = 0; j < 32; j++) s += fex2((vv[j] - mx) * LOG2E);
        #pragma unroll
        for (int o = 16; o; o >>= 1) s += __shfl_xor_sync(0xffffffffu, s, o);
        if (lane == 0) {
            g_maxA[row] = mx; g_sumA[row] = s;
            if (arg == (row & 1023)) atomicAdd(&g_correct, 1);
        }
        #pragma unroll
        for (int j = 0; j < 8; j++) {
            float4 f = *(const float4*)(pB + lane * 4 + 128 * j);
            vv[4 * j] = f.x; vv[4 * j + 1] = f.y; vv[4 * j + 2] = f.z; vv[4 * j + 3] = f.w;
        }
        mx = -1e30f;
        #pragma unroll
        for (int j = 0; j < 32; j++) mx = fmaxf(mx, vv[j]);
        #pragma unroll
        for (int o = 16; o; o >>= 1) mx = fmaxf(mx, __shfl_xor_sync(0xffffffffu, mx, o));
        s = 0.f;
        #pragma unroll
        for (int j = 0; j < 32; j++) s += fex2((vv[j] - mx) * LOG2E);
        #pragma unroll
        for (int o = 16; o; o >>= 1) s += __shfl_xor_sync(0xffffffffu, s, o);
        if (lane == 0) { g_maxB[row] = mx; g_sumB[row] = s; }
    }
}

// persistent sinkhorn, warp-autonomous rows:
//  - 16 warps x 4 rows; lane l owns columns l+32j. Row LSE = warp shuffles only.
//  - it==0: exact max-shifted row LSE. it>=1: stale-r shift (no max pass).
//  - column update: q_m = sum_n e_nm/s_n (pure FMA); c -= log2(max(q,1e-30)).
//    Clamp caps |c| ~100 so starved-column underflow cannot produce inf/NaN;
//    subsequent iterations self-correct (Sinkhorn recomputes from M each pass).
//  - only 2 __syncthreads per iteration + 1 inter-block barrier.
__global__ void __launch_bounds__(512) k_sinkhorn() {
    if (blockIdx.x >= B * SNB) { stats_work(blockIdx.x - B * SNB); return; }
    extern __shared__ float dsm[];
    float* sc = dsm;            // [1024] current c (identical in all blocks)
    float* sq = dsm + 1024;     // [16][1024] per-warp column partials
    int b = blockIdx.x >> 4, sub = blockIdx.x & 15;
    const float* Mblk = g_scrA + (size_t)(b * 1024 + sub * 64) * N;
    int tid = threadIdx.x, warp = tid >> 5, lane = tid & 31;
    sc[tid] = 0.f;
    sc[tid + 512] = 0.f;
    __syncthreads();

    float rprev[4];
    unsigned bar_t = 0;

    for (int it = 0; it < 30; it++) {
        int par = it & 1;
        float q[32];
        #pragma unroll
        for (int j = 0; j < 32; j++) q[j] = 0.f;

        #pragma unroll
        for (int ri = 0; ri < 4; ri++) {
            const float* rowp = Mblk + (size_t)(warp * 4 + ri) * N;
            float e[32];
            float lg;
            if (it == 0) {
                float m = -1e30f;
                #pragma unroll
                for (int j = 0; j < 32; j++) {
                    float z = fmaf(rowp[lane + 32 * j], K2, sc[lane + 32 * j]);
                    e[j] = z;
                    m = fmaxf(m, z);
                }
                #pragma unroll
                for (int o = 16; o; o >>= 1)
                    m = fmaxf(m, __shfl_xor_sync(0xffffffffu, m, o));
                float s = 0.f;
                #pragma unroll
                for (int j = 0; j < 32; j++) { e[j] = fex2(e[j] - m); s += e[j]; }
                #pragma unroll
                for (int o = 16; o; o >>= 1) s += __shfl_xor_sync(0xffffffffu, s, o);
                lg = flg2(s);
                rprev[ri] = -(m + lg);
            } else {
                float rp = rprev[ri];
                float s = 0.f;
                #pragma unroll
                for (int j = 0; j < 32; j++) {
                    float z = fmaf(rowp[lane + 32 * j], K2, sc[lane + 32 * j]);
                    e[j] = fex2(z + rp);
                    s += e[j];
                }
                #pragma unroll
                for (int o = 16; o; o >>= 1) s += __shfl_xor_sync(0xffffffffu, s, o);
                lg = flg2(fmaxf(s, 1e-30f));
                rprev[ri] = rp - lg;
            }
            float is = fex2(-lg);
            #pragma unroll
            for (int j = 0; j < 32; j++) q[j] = fmaf(e[j], is, q[j]);
        }

        // stage per-warp column partials (bank-conflict-free)
        #pragma unroll
        for (int j = 0; j < 32; j++) sq[warp * 1024 + lane + 32 * j] = q[j];
        __syncthreads();
        // block combine: thread t owns columns 2t, 2t+1
        float s0 = 0.f, s1 = 0.f;
        #pragma unroll
        for (int k = 0; k < 16; k++) {
            s0 += sq[k * 1024 + 2 * tid];
            s1 += sq[k * 1024 + 2 * tid + 1];
        }
        float* cp = g_cpf + (size_t)par * (B * SNB * N) + (size_t)(b * 16 + sub) * N;
        cp[2 * tid] = s0;
        cp[2 * tid + 1] = s1;
        bar_t += SNB; batch_bar(b, bar_t);

        // global combine -> sc (plain adds, identical in all blocks)
        const float* base = g_cpf + (size_t)par * (B * SNB * N) + (size_t)b * 16 * N;
        #pragma unroll
        for (int h = 0; h < 2; h++) {
            int col = tid + 512 * h;
            float s = 0.f;
            #pragma unroll
            for (int k = 0; k < 16; k++) s += base[(size_t)k * N + col];
            sc[col] = sc[col] - flg2(fmaxf(s, 1e-30f));
        }
        __syncthreads();
    }

    if (lane == 0) {
        #pragma unroll
        for (int ri = 0; ri < 4; ri++)
            g_r[b * N + sub * 64 + warp * 4 + ri] = rprev[ri];
    }
    if (tid < 64) g_c[b * N + sub * 64 + tid] = sc[sub * 64 + tid];
}

// ---------------------------------------------------------------------------
// fused final pass: uses precomputed row stats; dist + softmaxes + sink
__global__ void __launch_bounds__(256) k_final(const float* __restrict__ pc0) {
    int rowi = blockIdx.x;
    int b = rowi >> 10, n = rowi & 1023;
    size_t row = rowi;
    const float* pA = g_scrA + row * N;
    const float* pB = g_scrB + row * N;
    int tid = threadIdx.x, lane = tid & 31, warp = tid >> 5;

    __shared__ float spc[3 * 1024];
    __shared__ float scv[1024];
    const float* pc = pc0 + (size_t)b * N * 3;
    for (int i = tid; i < 3 * 1024; i += 256) spc[i] = pc[i];
    for (int i = tid; i < 1024; i += 256) scv[i] = g_c[b * N + i];

    float mA = g_maxA[row], iA = 1.0f / g_sumA[row];
    float mB = g_maxB[row], iB = 1.0f / g_sumB[row];
    float rn = g_r[row];
    __syncthreads();

    float px = spc[3 * n], py = spc[3 * n + 1], pz = spc[3 * n + 2];
    float aL = 0.f, aC = 0.f, aP = 0.f;
    #pragma unroll
    for (int t = 0; t < 4; t++) {
        int m = tid + 256 * t;
        float xA = pA[m], xB = pB[m];
        float smA = fex2((xA - mA) * LOG2E) * iA;
        float smB = fex2((xB - mB) * LOG2E) * iB;
        float dx = px - spc[3 * m], dy = py - spc[3 * m + 1], dz = pz - spc[3 * m + 2];
        float d2 = dx * dx + dy * dy + dz * dz;
        float dist = sqrtf(sqrtf(d2));
        aL += dist * (smA + smB);
        float sink = fex2(xA * K2 + rn + scv[m]);
        aC += fabsf(sink - smA);
        aP += (m == n) ? fabsf(1.0f - sink) : sink;
    }
    #pragma unroll
    for (int o = 16; o; o >>= 1) {
        aL += __shfl_xor_sync(0xffffffffu, aL, o);
        aC += __shfl_xor_sync(0xffffffffu, aC, o);
        aP += __shfl_xor_sync(0xffffffffu, aP, o);
    }
    __shared__ float s1[8], s2[8], s3[8];
    if (lane == 0) { s1[warp] = aL; s2[warp] = aC; s3[warp] = aP; }
    __syncthreads();
    if (tid == 0) {
        float tL = 0.f, tC = 0.f, tP = 0.f;
        #pragma unroll
        for (int q = 0; q < 8; q++) { tL += s1[q]; tC += s2[q]; tP += s3[q]; }
        g_pL[row] = tL; g_pC[row] = tC; g_pP[row] = tP;
    }
}

// ---------------------------------------------------------------------------
__global__ void __launch_bounds__(256) k_out(float* __restrict__ out) {
    int tid = threadIdx.x;
    float sL = 0.f, sC = 0.f, sP = 0.f;
    for (int i = tid; i < B * N; i += 256) {
        sL += g_pL[i]; sC += g_pC[i]; sP += g_pP[i];
    }
    #pragma unroll
    for (int o = 16; o; o >>= 1) {
        sL += __shfl_xor_sync(0xffffffffu, sL, o);
        sC += __shfl_xor_sync(0xffffffffu, sC, o);
        sP += __shfl_xor_sync(0xffffffffu, sP, o);
    }
    __shared__ float s1[8], s2[8], s3[8];
    if ((tid & 31) == 0) { s1[tid >> 5] = sL; s2[tid >> 5] = sC; s3[tid >> 5] = sP; }
    __syncthreads();
    if (tid == 0) {
        float tL = 0.f, tC = 0.f, tP = 0.f;
        #pragma unroll
        for (int q = 0; q < 8; q++) { tL += s1[q]; tC += s2[q]; tP += s3[q]; }
        float invN = 1.0f / (float)N;
        float loss = tL * invN;
        float Lc = 3.0f * tC * invN;
        float perm = 3.0f * tP * invN;
        float corr = (float)g_correct;
        float invB = 1.0f / (float)B;
        out[0] = (loss + Lc) * invB;
        out[1] = loss * invB;
        out[2] = Lc * invB;
        out[3] = corr * invB;
        out[4] = perm * invB;
    }
}

// ---------------------------------------------------------------------------
extern "C" void kernel_launch(void* const* d_in, const int* in_sizes, int n_in,
                              void* d_out, int out_size) {
    const float* feats = (const float*)d_in[0];
    const float* pc0 = (const float*)d_in[1];
    float* out = (float*)d_out;

    const int nt_smem = 4 * TSZ * sizeof(__nv_bfloat16);
    const int nn_smem = NN_ELEMS * sizeof(__nv_bfloat16);
    static bool attr_done = false;
    if (!attr_done) {
        cudaFuncSetAttribute(k_hmma_nt, cudaFuncAttributeMaxDynamicSharedMemorySize,
                             nt_smem);
        cudaFuncSetAttribute(k_hmma_nn, cudaFuncAttributeMaxDynamicSharedMemorySize,
                             nn_smem);
        cudaFuncSetAttribute(k_sinkhorn, cudaFuncAttributeMaxDynamicSharedMemorySize,
                             SINK_SMEM);
        attr_done = true;
    }

    k_init<<<32, 256>>>();
    k_norm<<<2 * B * N, 128>>>(feats);
    k_hmma_nt<<<dim3(8, 8, 8), 256, nt_smem>>>(0);    // corr_1a -> scrA
    k_rowsoftmax<<<B * N, 256>>>();                   // smcorr hi/lo bf16
    k_hmma_nn<<<dim3(8, 8), 256, nn_smem>>>();        // via hi/lo
    k_hmma_nt<<<dim3(8, 8, 16), 256, nt_smem>>>(3);   // corr_1a2 + corr_12
    k_sinkhorn<<<B * SNB + STATS_BLKS, 512, SINK_SMEM>>>();
    k_final<<<B * N, 256>>>(pc0);
    k_out<<<1, 256>>>(out);
}

// round 14
// speedup vs baseline: 1.7162x; 1.0527x over previous
#include <cuda_runtime.h>
#include <cuda_bf16.h>
#include <cstdint>

namespace {
constexpr int B = 8;
constexpr int N = 1024;
constexpr int C = 128;
constexpr float SCALEF = 20.0f;
constexpr float EPSF = 1e-12f;
constexpr float LOG2E = 1.4426950408889634f;
constexpr float K2 = 4.808983469629878f;   // log2(e)/0.3
constexpr int SNB = 16;                    // sinkhorn blocks per batch
constexpr int STATS_BLKS = 20;             // extra stats blocks
constexpr int TPAD = 136;
constexpr int TSZ = 128 * TPAD;
constexpr int APAD = 72;
constexpr int VPAD = 136;
// NN smem (64-row A tiles)
constexpr int AH_O = 0;
constexpr int AL_O = 64 * APAD;
constexpr int VH_O = 2 * 64 * APAD;
constexpr int VL_O = VH_O + 64 * VPAD;
constexpr int NN_ELEMS = VL_O + 64 * VPAD;
constexpr int SINK_SMEM = (1024 + 16 * 1024) * 4;  // sc + sq staging
}

__device__ float g_scrA[(size_t)B * N * N];
__device__ float g_scrB[(size_t)B * N * N];
__device__ __nv_bfloat16 g_FnH[2 * B * N * C];
__device__ __nv_bfloat16 g_FnL[2 * B * N * C];
__device__ __nv_bfloat16 g_viaH[B * N * C];
__device__ __nv_bfloat16 g_viaL[B * N * C];
__device__ __nv_bfloat16 g_smH[(size_t)B * N * N];
__device__ __nv_bfloat16 g_smL[(size_t)B * N * N];
__device__ float g_cpf[2 * B * SNB * N];
__device__ float g_r[B * N];
__device__ float g_c[B * N];
__device__ float g_maxA[B * N], g_sumA[B * N];
__device__ float g_maxB[B * N], g_sumB[B * N];
__device__ unsigned g_bar[B];
__device__ int g_correct;
__device__ float g_pL[B * N], g_pC[B * N], g_pP[B * N];

__device__ __forceinline__ float fex2(float x) {
    float y; asm("ex2.approx.ftz.f32 %0, %1;" : "=f"(y) : "f"(x)); return y;
}
__device__ __forceinline__ float flg2(float x) {
    float y; asm("lg2.approx.ftz.f32 %0, %1;" : "=f"(y) : "f"(x)); return y;
}
__device__ __forceinline__ uint32_t smem_u32(const void* p) {
    uint32_t a;
    asm("{ .reg .u64 t; cvta.to.shared.u64 t, %1; cvt.u32.u64 %0, t; }"
        : "=r"(a) : "l"(p));
    return a;
}
__device__ __forceinline__ void ldm4(uint32_t& r0, uint32_t& r1, uint32_t& r2,
                                     uint32_t& r3, uint32_t addr) {
    asm volatile("ldmatrix.sync.aligned.m8n8.x4.shared.b16 {%0,%1,%2,%3}, [%4];"
                 : "=r"(r0), "=r"(r1), "=r"(r2), "=r"(r3) : "r"(addr));
}
__device__ __forceinline__ void ldm4t(uint32_t& r0, uint32_t& r1, uint32_t& r2,
                                      uint32_t& r3, uint32_t addr) {
    asm volatile("ldmatrix.sync.aligned.m8n8.x4.trans.shared.b16 {%0,%1,%2,%3}, [%4];"
                 : "=r"(r0), "=r"(r1), "=r"(r2), "=r"(r3) : "r"(addr));
}
__device__ __forceinline__ void mma16816(float* c, const uint32_t* a,
                                         uint32_t b0, uint32_t b1) {
    asm volatile(
        "mma.sync.aligned.m16n8k16.row.col.f32.bf16.bf16.f32 "
        "{%0,%1,%2,%3}, {%4,%5,%6,%7}, {%8,%9}, {%0,%1,%2,%3};"
        : "+f"(c[0]), "+f"(c[1]), "+f"(c[2]), "+f"(c[3])
        : "r"(a[0]), "r"(a[1]), "r"(a[2]), "r"(a[3]), "r"(b0), "r"(b1));
}
__device__ __forceinline__ void hilo(float v, __nv_bfloat16& h, __nv_bfloat16& l) {
    h = __float2bfloat16(v);
    l = __float2bfloat16(v - __bfloat162float(h));
}

// ---------------------------------------------------------------------------
__global__ void k_init() {
    int i = blockIdx.x * blockDim.x + threadIdx.x;
    if (i < B) g_bar[i] = 0u;
    if (i == 0) g_correct = 0;
}

__global__ void __launch_bounds__(128) k_norm(const float* __restrict__ feats) {
    int row = blockIdx.x;
    const float* p = feats + (size_t)row * C;
    float v = p[threadIdx.x];
    float s = v * v;
    #pragma unroll
    for (int o = 16; o; o >>= 1) s += __shfl_xor_sync(0xffffffffu, s, o);
    __shared__ float sh[4];
    if ((threadIdx.x & 31) == 0) sh[threadIdx.x >> 5] = s;
    __syncthreads();
    s = sh[0] + sh[1] + sh[2] + sh[3];
    float scl = SCALEF / fmaxf(sqrtf(s), EPSF);
    float val = v * scl;
    size_t idx = (size_t)row * C + threadIdx.x;
    __nv_bfloat16 h, l;
    hilo(val, h, l);
    g_FnH[idx] = h;
    g_FnL[idx] = l;
}

// ---------------------------------------------------------------------------
// HMMA NT gemm, bf16-split 3 terms. mode 0: corr_1a; mode 3: fused 1+2.
__global__ void __launch_bounds__(256) k_hmma_nt(int mode) {
    extern __shared__ __nv_bfloat16 smem[];
    int ia = blockIdx.x, ib = blockIdx.y;
    int b = blockIdx.z & 7;
    int m = mode;
    if (mode == 3) m = (blockIdx.z < 8) ? 1 : 2;
    int tid = threadIdx.x, wid = tid >> 5, lane = tid & 31;

    const __nv_bfloat16 *aHg, *aLg; float* dst;
    int fsB;
    if (m == 0) {
        aHg = g_FnH + (size_t)(2 * b) * N * C;
        aLg = g_FnL + (size_t)(2 * b) * N * C;
        fsB = 2 * ((b + 1) & 7);
        dst = g_scrA;
    } else if (m == 1) {
        aHg = g_viaH + (size_t)b * N * C;
        aLg = g_viaL + (size_t)b * N * C;
        fsB = 2 * b + 1;
        dst = g_scrA;
    } else {
        aHg = g_FnH + (size_t)(2 * b) * N * C;
        aLg = g_FnL + (size_t)(2 * b) * N * C;
        fsB = 2 * b + 1;
        dst = g_scrB;
    }
    const __nv_bfloat16* bHg = g_FnH + (size_t)fsB * N * C;
    const __nv_bfloat16* bLg = g_FnL + (size_t)fsB * N * C;
    aHg += (size_t)ia * 128 * C; aLg += (size_t)ia * 128 * C;
    bHg += (size_t)ib * 128 * C; bLg += (size_t)ib * 128 * C;

    {
        const uint4* src[4] = {(const uint4*)aHg, (const uint4*)aLg,
                               (const uint4*)bHg, (const uint4*)bLg};
        #pragma unroll
        for (int t4 = 0; t4 < 4; t4++) {
            __nv_bfloat16* dtile = smem + t4 * TSZ;
            #pragma unroll
            for (int i = 0; i < 8; i++) {
                int idx = tid + 256 * i;
                int row = idx >> 4, c8 = idx & 15;
                *(uint4*)(dtile + row * TPAD + c8 * 8) = src[t4][idx];
            }
        }
    }
    __syncthreads();

    int wm = wid & 3, wn = wid >> 2;
    float acc[2][8][4];
    #pragma unroll
    for (int mi = 0; mi < 2; mi++)
        #pragma unroll
        for (int nj = 0; nj < 8; nj++)
            #pragma unroll
            for (int q = 0; q < 4; q++) acc[mi][nj][q] = 0.f;

    uint32_t sbase = smem_u32(smem);
    const int selA[3] = {0, 0, 1};
    const int selB[3] = {2, 3, 2};
    int a_r = lane & 15, a_c = (lane >> 4) << 3;
    int b_r = (lane & 7) + ((lane >> 4) << 3);
    int b_c = ((lane >> 3) & 1) << 3;

    #pragma unroll
    for (int t = 0; t < 3; t++) {
        uint32_t aB = sbase + selA[t] * TSZ * 2;
        uint32_t bBs = sbase + selB[t] * TSZ * 2;
        #pragma unroll
        for (int k8 = 0; k8 < 8; k8++) {
            int kc = k8 * 16;
            uint32_t af[2][4];
            #pragma unroll
            for (int mi = 0; mi < 2; mi++) {
                int row = wm * 32 + mi * 16 + a_r;
                ldm4(af[mi][0], af[mi][1], af[mi][2], af[mi][3],
                     aB + (row * TPAD + kc + a_c) * 2);
            }
            uint32_t bf[4][4];
            #pragma unroll
            for (int nj = 0; nj < 4; nj++) {
                int row = wn * 64 + nj * 16 + b_r;
                ldm4(bf[nj][0], bf[nj][1], bf[nj][2], bf[nj][3],
                     bBs + (row * TPAD + kc + b_c) * 2);
            }
            #pragma unroll
            for (int mi = 0; mi < 2; mi++)
                #pragma unroll
                for (int nj = 0; nj < 4; nj++) {
                    mma16816(acc[mi][2 * nj], af[mi], bf[nj][0], bf[nj][1]);
                    mma16816(acc[mi][2 * nj + 1], af[mi], bf[nj][2], bf[nj][3]);
                }
        }
    }

    {
        int rbase = b * 1024 + ia * 128 + wm * 32 + (lane >> 2);
        int cbase = ib * 128 + wn * 64 + 2 * (lane & 3);
        #pragma unroll
        for (int mi = 0; mi < 2; mi++)
            #pragma unroll
            for (int nj = 0; nj < 8; nj++) {
                float* d0 = dst + (size_t)(rbase + mi * 16) * 1024 + cbase + nj * 8;
                *(float2*)d0 = make_float2(acc[mi][nj][0], acc[mi][nj][1]);
                float* d1 = d0 + 8 * 1024;
                *(float2*)d1 = make_float2(acc[mi][nj][2], acc[mi][nj][3]);
            }
    }
}

// ---------------------------------------------------------------------------
// row softmax of corr_1a (fp32 in scrA) -> bf16 hi/lo smcorr
__global__ void __launch_bounds__(256) k_rowsoftmax() {
    size_t row = blockIdx.x;
    const float4* p = (const float4*)(g_scrA + row * N);
    int tid = threadIdx.x, lane = tid & 31;
    float4 v = p[tid];
    float mx = fmaxf(fmaxf(v.x, v.y), fmaxf(v.z, v.w));
    #pragma unroll
    for (int o = 16; o; o >>= 1) mx = fmaxf(mx, __shfl_xor_sync(0xffffffffu, mx, o));
    __shared__ float shm[8], shs[8];
    if (lane == 0) shm[tid >> 5] = mx;
    __syncthreads();
    mx = fmaxf(fmaxf(fmaxf(shm[0], shm[1]), fmaxf(shm[2], shm[3])),
               fmaxf(fmaxf(shm[4], shm[5]), fmaxf(shm[6], shm[7])));
    float4 e;
    e.x = fex2((v.x - mx) * LOG2E);
    e.y = fex2((v.y - mx) * LOG2E);
    e.z = fex2((v.z - mx) * LOG2E);
    e.w = fex2((v.w - mx) * LOG2E);
    float s = e.x + e.y + e.z + e.w;
    #pragma unroll
    for (int o = 16; o; o >>= 1) s += __shfl_xor_sync(0xffffffffu, s, o);
    if (lane == 0) shs[tid >> 5] = s;
    __syncthreads();
    s = shs[0] + shs[1] + shs[2] + shs[3] + shs[4] + shs[5] + shs[6] + shs[7];
    float inv = 1.0f / s;
    float f[4] = {e.x * inv, e.y * inv, e.z * inv, e.w * inv};
    __nv_bfloat16 h[4], l[4];
    #pragma unroll
    for (int q = 0; q < 4; q++) hilo(f[q], h[q], l[q]);
    __nv_bfloat162* dH = (__nv_bfloat162*)(g_smH + row * N + 4 * tid);
    __nv_bfloat162* dL = (__nv_bfloat162*)(g_smL + row * N + 4 * tid);
    dH[0] = __nv_bfloat162{h[0], h[1]};
    dH[1] = __nv_bfloat162{h[2], h[3]};
    dL[0] = __nv_bfloat162{l[0], l[1]};
    dL[1] = __nv_bfloat162{l[2], l[3]};
}

// ---------------------------------------------------------------------------
// HMMA NN gemm, 64-row CTAs (128 CTAs): via[b] = smcorr[b] @ fa[b]; out hi/lo
__global__ void __launch_bounds__(256) k_hmma_nn() {
    extern __shared__ __nv_bfloat16 smem[];
    int rb = blockIdx.x, b = blockIdx.y;       // rb in [0,16)
    int tid = threadIdx.x, wid = tid >> 5, lane = tid & 31;
    int fs = 2 * ((b + 1) & 7);

    int wm = wid & 1, wn = wid >> 1;           // warp tile: 32 rows x 32 cols
    float acc[2][4][4];
    #pragma unroll
    for (int mi = 0; mi < 2; mi++)
        #pragma unroll
        for (int nj = 0; nj < 4; nj++)
            #pragma unroll
            for (int q = 0; q < 4; q++) acc[mi][nj][q] = 0.f;

    uint32_t sbase = smem_u32(smem);
    const int AOFF[3] = {AH_O, AH_O, AL_O};
    const int VOFF[3] = {VH_O, VL_O, VH_O};
    int a_r = lane & 15, a_c = (lane >> 4) << 3;
    int bt_r = (lane & 7) + (((lane >> 3) & 1) << 3);
    int bt_c = (lane >> 4) << 3;

    for (int kc = 0; kc < 16; kc++) {
        int kb = kc * 64;
        if (kc) __syncthreads();
        // A tiles: 64 rows x 64 k (512 uint4 per tile)
        #pragma unroll
        for (int i = 0; i < 2; i++) {
            int idx = tid + 256 * i;
            int r = idx >> 3, c8 = idx & 7;
            size_t so = (size_t)(b * 1024 + rb * 64 + r) * 1024 + kb + c8 * 8;
            *(uint4*)(smem + AH_O + r * APAD + c8 * 8) = *(const uint4*)(g_smH + so);
            *(uint4*)(smem + AL_O + r * APAD + c8 * 8) = *(const uint4*)(g_smL + so);
        }
        // V tiles: 64 k-rows x 128 c
        #pragma unroll
        for (int i = 0; i < 4; i++) {
            int idx = tid + 256 * i;
            int r = idx >> 4, c8 = idx & 15;
            size_t so = (size_t)(fs * 1024 + kb + r) * 128 + c8 * 8;
            *(uint4*)(smem + VH_O + r * VPAD + c8 * 8) = *(const uint4*)(g_FnH + so);
            *(uint4*)(smem + VL_O + r * VPAD + c8 * 8) = *(const uint4*)(g_FnL + so);
        }
        __syncthreads();

        #pragma unroll
        for (int t = 0; t < 3; t++) {
            #pragma unroll
            for (int k16 = 0; k16 < 4; k16++) {
                int kk = k16 * 16;
                uint32_t af[2][4];
                #pragma unroll
                for (int mi = 0; mi < 2; mi++) {
                    int row = wm * 32 + mi * 16 + a_r;
                    ldm4(af[mi][0], af[mi][1], af[mi][2], af[mi][3],
                         sbase + (AOFF[t] + row * APAD + kk + a_c) * 2);
                }
                uint32_t bf[2][4];
                #pragma unroll
                for (int nj = 0; nj < 2; nj++) {
                    int krow = kk + bt_r;
                    int ccol = wn * 32 + nj * 16 + bt_c;
                    ldm4t(bf[nj][0], bf[nj][1], bf[nj][2], bf[nj][3],
                          sbase + (VOFF[t] + krow * VPAD + ccol) * 2);
                }
                #pragma unroll
                for (int mi = 0; mi < 2; mi++)
                    #pragma unroll
                    for (int nj = 0; nj < 2; nj++) {
                        mma16816(acc[mi][2 * nj], af[mi], bf[nj][0], bf[nj][1]);
                        mma16816(acc[mi][2 * nj + 1], af[mi], bf[nj][2], bf[nj][3]);
                    }
            }
        }
    }

    {
        int rbase = b * 1024 + rb * 64 + wm * 32 + (lane >> 2);
        int cbase = wn * 32 + 2 * (lane & 3);
        #pragma unroll
        for (int mi = 0; mi < 2; mi++)
            #pragma unroll
            for (int nj = 0; nj < 4; nj++) {
                #pragma unroll
                for (int half = 0; half < 2; half++) {
                    int row = rbase + mi * 16 + half * 8;
                    int col = cbase + nj * 8;
                    float v0 = acc[mi][nj][2 * half], v1 = acc[mi][nj][2 * half + 1];
                    __nv_bfloat16 h0, l0, h1, l1;
                    hilo(v0, h0, l0);
                    hilo(v1, h1, l1);
                    size_t o = (size_t)row * C + col;
                    *(__nv_bfloat162*)(g_viaH + o) = __nv_bfloat162{h0, h1};
                    *(__nv_bfloat162*)(g_viaL + o) = __nv_bfloat162{l0, l1};
                }
            }
    }
}

// ---------------------------------------------------------------------------
__device__ __forceinline__ void batch_bar(int b, unsigned target) {
    __syncthreads();
    if (threadIdx.x == 0) {
        unsigned v;
        asm volatile("red.release.gpu.add.u32 [%0], %1;"
                     :: "l"(&g_bar[b]), "r"(1u) : "memory");
        do {
            asm volatile("ld.acquire.gpu.u32 %0, [%1];"
                         : "=r"(v) : "l"(&g_bar[b]) : "memory");
        } while (v < target);
    }
    __syncthreads();
}

// ---------------------------------------------------------------------------
// per-row stats for k_final (runs on the 20 extra blocks, warp-per-row)
__device__ void stats_work(int sbid) {
    int tid = threadIdx.x, wid = tid >> 5, lane = tid & 31;
    int w = sbid * 16 + wid;
    for (int row = w; row < B * N; row += STATS_BLKS * 16) {
        const float* pA = g_scrA + (size_t)row * N;
        const float* pB = g_scrB + (size_t)row * N;
        float vv[32];
        #pragma unroll
        for (int j = 0; j < 8; j++) {
            float4 f = *(const float4*)(pA + lane * 4 + 128 * j);
            vv[4 * j] = f.x; vv[4 * j + 1] = f.y; vv[4 * j + 2] = f.z; vv[4 * j + 3] = f.w;
        }
        float mx = -1e30f; int arg = 0;
        #pragma unroll
        for (int j = 0; j < 32; j++) {
            int idx = lane * 4 + 128 * (j >> 2) + (j & 3);
            if (vv[j] > mx) { mx = vv[j]; arg = idx; }
        }
        #pragma unroll
        for (int o = 16; o; o >>= 1) {
            float m2 = __shfl_xor_sync(0xffffffffu, mx, o);
            int a2 = __shfl_xor_sync(0xffffffffu, arg, o);
            if (m2 > mx || (m2 == mx && a2 < arg)) { mx = m2; arg = a2; }
        }
        float s = 0.f;
        #pragma unroll
        for (int j = 0; j < 32; j++) s += fex2((vv[j] - mx) * LOG2E);
        #pragma unroll
        for (int o = 16; o; o >>= 1) s += __shfl_xor_sync(0xffffffffu, s, o);
        if (lane == 0) {
            g_maxA[row] = mx; g_sumA[row] = s;
            if (arg == (row & 1023)) atomicAdd(&g_correct, 1);
        }
        #pragma unroll
        for (int j = 0; j < 8; j++) {
            float4 f = *(const float4*)(pB + lane * 4 + 128 * j);
            vv[4 * j] = f.x; vv[4 * j + 1] = f.y; vv[4 * j + 2] = f.z; vv[4 * j + 3] = f.w;
        }
        mx = -1e30f;
        #pragma unroll
        for (int j = 0; j < 32; j++) mx = fmaxf(mx, vv[j]);
        #pragma unroll
        for (int o = 16; o; o >>= 1) mx = fmaxf(mx, __shfl_xor_sync(0xffffffffu, mx, o));
        s = 0.f;
        #pragma unroll
        for (int j = 0; j < 32; j++) s += fex2((vv[j] - mx) * LOG2E);
        #pragma unroll
        for (int o = 16; o; o >>= 1) s += __shfl_xor_sync(0xffffffffu, s, o);
        if (lane == 0) { g_maxB[row] = mx; g_sumB[row] = s; }
    }
}

// persistent sinkhorn, warp-autonomous rows; c register-resident per lane
// (float2 x 16), float2 M loads; 2 __syncthreads + 1 inter-block barrier/iter.
__global__ void __launch_bounds__(512) k_sinkhorn() {
    if (blockIdx.x >= B * SNB) { stats_work(blockIdx.x - B * SNB); return; }
    extern __shared__ float dsm[];
    float* sc = dsm;            // [1024] current c
    float* sq = dsm + 1024;     // [16][1024] per-warp column partials
    int b = blockIdx.x >> 4, sub = blockIdx.x & 15;
    const float* Mblk = g_scrA + (size_t)(b * 1024 + sub * 64) * N;
    int tid = threadIdx.x, warp = tid >> 5, lane = tid & 31;
    sc[tid] = 0.f;
    sc[tid + 512] = 0.f;
    __syncthreads();

    float rprev[4];
    unsigned bar_t = 0;

    for (int it = 0; it < 30; it++) {
        int par = it & 1;
        float2 cc[16];
        #pragma unroll
        for (int j = 0; j < 16; j++) cc[j] = *(float2*)&sc[2 * lane + 64 * j];
        float2 q[16];
        #pragma unroll
        for (int j = 0; j < 16; j++) q[j] = make_float2(0.f, 0.f);

        #pragma unroll
        for (int ri = 0; ri < 4; ri++) {
            const float2* rowp = (const float2*)(Mblk + (size_t)(warp * 4 + ri) * N);
            float2 e[16];
            float lg;
            if (it == 0) {
                float m = -1e30f;
                #pragma unroll
                for (int j = 0; j < 16; j++) {
                    float2 y = rowp[lane + 32 * j];
                    e[j].x = fmaf(y.x, K2, cc[j].x);
                    e[j].y = fmaf(y.y, K2, cc[j].y);
                    m = fmaxf(m, fmaxf(e[j].x, e[j].y));
                }
                #pragma unroll
                for (int o = 16; o; o >>= 1)
                    m = fmaxf(m, __shfl_xor_sync(0xffffffffu, m, o));
                float s = 0.f;
                #pragma unroll
                for (int j = 0; j < 16; j++) {
                    e[j].x = fex2(e[j].x - m);
                    e[j].y = fex2(e[j].y - m);
                    s += e[j].x + e[j].y;
                }
                #pragma unroll
                for (int o = 16; o; o >>= 1) s += __shfl_xor_sync(0xffffffffu, s, o);
                lg = flg2(s);
                rprev[ri] = -(m + lg);
            } else {
                float rp = rprev[ri];
                float s = 0.f;
                #pragma unroll
                for (int j = 0; j < 16; j++) {
                    float2 y = rowp[lane + 32 * j];
                    e[j].x = fex2(fmaf(y.x, K2, cc[j].x) + rp);
                    e[j].y = fex2(fmaf(y.y, K2, cc[j].y) + rp);
                    s += e[j].x + e[j].y;
                }
                #pragma unroll
                for (int o = 16; o; o >>= 1) s += __shfl_xor_sync(0xffffffffu, s, o);
                lg = flg2(fmaxf(s, 1e-30f));
                rprev[ri] = rp - lg;
            }
            float is = fex2(-lg);
            #pragma unroll
            for (int j = 0; j < 16; j++) {
                q[j].x = fmaf(e[j].x, is, q[j].x);
                q[j].y = fmaf(e[j].y, is, q[j].y);
            }
        }

        // stage per-warp column partials
        #pragma unroll
        for (int j = 0; j < 16; j++)
            *(float2*)&sq[warp * 1024 + 2 * lane + 64 * j] = q[j];
        __syncthreads();
        // block combine: thread t owns columns 2t, 2t+1
        float s0 = 0.f, s1 = 0.f;
        #pragma unroll
        for (int k = 0; k < 16; k++) {
            float2 t2 = *(float2*)&sq[k * 1024 + 2 * tid];
            s0 += t2.x; s1 += t2.y;
        }
        float* cp = g_cpf + (size_t)par * (B * SNB * N) + (size_t)(b * 16 + sub) * N;
        *(float2*)&cp[2 * tid] = make_float2(s0, s1);
        bar_t += SNB; batch_bar(b, bar_t);

        // global combine -> sc (plain adds, identical in all blocks)
        const float* base = g_cpf + (size_t)par * (B * SNB * N) + (size_t)b * 16 * N;
        #pragma unroll
        for (int h = 0; h < 2; h++) {
            int col = tid + 512 * h;
            float s = 0.f;
            #pragma unroll
            for (int k = 0; k < 16; k++) s += base[(size_t)k * N + col];
            sc[col] = sc[col] - flg2(fmaxf(s, 1e-30f));
        }
        __syncthreads();
    }

    if (lane == 0) {
        #pragma unroll
        for (int ri = 0; ri < 4; ri++)
            g_r[b * N + sub * 64 + warp * 4 + ri] = rprev[ri];
    }
    if (tid < 64) g_c[b * N + sub * 64 + tid] = sc[sub * 64 + tid];
}

// ---------------------------------------------------------------------------
// fused final pass: 2 rows per block; uses precomputed row stats
__global__ void __launch_bounds__(256) k_final(const float* __restrict__ pc0) {
    int pair = blockIdx.x;             // 0..4095
    int b = pair >> 9;
    int n0 = (pair & 511) * 2;
    int tid = threadIdx.x, lane = tid & 31, warp = tid >> 5;

    __shared__ float spc[3 * 1024];
    __shared__ float scv[1024];
    __shared__ float s1[8], s2[8], s3[8];
    const float* pc = pc0 + (size_t)b * N * 3;
    for (int i = tid; i < 3 * 1024; i += 256) spc[i] = pc[i];
    for (int i = tid; i < 1024; i += 256) scv[i] = g_c[b * N + i];
    __syncthreads();

    #pragma unroll
    for (int rr = 0; rr < 2; rr++) {
        int n = n0 + rr;
        size_t row = (size_t)b * N + n;
        const float* pA = g_scrA + row * N;
        const float* pB = g_scrB + row * N;
        float mA = g_maxA[row], iA = 1.0f / g_sumA[row];
        float mB = g_maxB[row], iB = 1.0f / g_sumB[row];
        float rn = g_r[row];
        float px = spc[3 * n], py = spc[3 * n + 1], pz = spc[3 * n + 2];
        float aL = 0.f, aC = 0.f, aP = 0.f;
        #pragma unroll
        for (int t = 0; t < 4; t++) {
            int m = tid + 256 * t;
            float xA = pA[m], xB = pB[m];
            float smA = fex2((xA - mA) * LOG2E) * iA;
            float smB = fex2((xB - mB) * LOG2E) * iB;
            float dx = px - spc[3 * m], dy = py - spc[3 * m + 1], dz = pz - spc[3 * m + 2];
            float d2 = dx * dx + dy * dy + dz * dz;
            float dist = sqrtf(sqrtf(d2));
            aL += dist * (smA + smB);
            float sink = fex2(xA * K2 + rn + scv[m]);
            aC += fabsf(sink - smA);
            aP += (m == n) ? fabsf(1.0f - sink) : sink;
        }
        #pragma unroll
        for (int o = 16; o; o >>= 1) {
            aL += __shfl_xor_sync(0xffffffffu, aL, o);
            aC += __shfl_xor_sync(0xffffffffu, aC, o);
            aP += __shfl_xor_sync(0xffffffffu, aP, o);
        }
        if (lane == 0) { s1[warp] = aL; s2[warp] = aC; s3[warp] = aP; }
        __syncthreads();
        if (tid == 0) {
            float tL = 0.f, tC = 0.f, tP = 0.f;
            #pragma unroll
            for (int q = 0; q < 8; q++) { tL += s1[q]; tC += s2[q]; tP += s3[q]; }
            g_pL[row] = tL; g_pC[row] = tC; g_pP[row] = tP;
        }
        __syncthreads();
    }
}

// ---------------------------------------------------------------------------
__global__ void __launch_bounds__(256) k_out(float* __restrict__ out) {
    int tid = threadIdx.x;
    float sL = 0.f, sC = 0.f, sP = 0.f;
    for (int i = tid; i < B * N; i += 256) {
        sL += g_pL[i]; sC += g_pC[i]; sP += g_pP[i];
    }
    #pragma unroll
    for (int o = 16; o; o >>= 1) {
        sL += __shfl_xor_sync(0xffffffffu, sL, o);
        sC += __shfl_xor_sync(0xffffffffu, sC, o);
        sP += __shfl_xor_sync(0xffffffffu, sP, o);
    }
    __shared__ float s1[8], s2[8], s3[8];
    if ((tid & 31) == 0) { s1[tid >> 5] = sL; s2[tid >> 5] = sC; s3[tid >> 5] = sP; }
    __syncthreads();
    if (tid == 0) {
        float tL = 0.f, tC = 0.f, tP = 0.f;
        #pragma unroll
        for (int q = 0; q < 8; q++) { tL += s1[q]; tC += s2[q]; tP += s3[q]; }
        float invN = 1.0f / (float)N;
        float loss = tL * invN;
        float Lc = 3.0f * tC * invN;
        float perm = 3.0f * tP * invN;
        float corr = (float)g_correct;
        float invB = 1.0f / (float)B;
        out[0] = (loss + Lc) * invB;
        out[1] = loss * invB;
        out[2] = Lc * invB;
        out[3] = corr * invB;
        out[4] = perm * invB;
    }
}

// ---------------------------------------------------------------------------
extern "C" void kernel_launch(void* const* d_in, const int* in_sizes, int n_in,
                              void* d_out, int out_size) {
    const float* feats = (const float*)d_in[0];
    const float* pc0 = (const float*)d_in[1];
    float* out = (float*)d_out;

    const int nt_smem = 4 * TSZ * sizeof(__nv_bfloat16);
    const int nn_smem = NN_ELEMS * sizeof(__nv_bfloat16);
    static bool attr_done = false;
    if (!attr_done) {
        cudaFuncSetAttribute(k_hmma_nt, cudaFuncAttributeMaxDynamicSharedMemorySize,
                             nt_smem);
        cudaFuncSetAttribute(k_hmma_nn, cudaFuncAttributeMaxDynamicSharedMemorySize,
                             nn_smem);
        cudaFuncSetAttribute(k_sinkhorn, cudaFuncAttributeMaxDynamicSharedMemorySize,
                             SINK_SMEM);
        attr_done = true;
    }

    k_init<<<1, 32>>>();
    k_norm<<<2 * B * N, 128>>>(feats);
    k_hmma_nt<<<dim3(8, 8, 8), 256, nt_smem>>>(0);    // corr_1a -> scrA
    k_rowsoftmax<<<B * N, 256>>>();                   // smcorr hi/lo bf16
    k_hmma_nn<<<dim3(16, 8), 256, nn_smem>>>();       // via hi/lo (128 CTAs)
    k_hmma_nt<<<dim3(8, 8, 16), 256, nt_smem>>>(3);   // corr_1a2 + corr_12
    k_sinkhorn<<<B * SNB + STATS_BLKS, 512, SINK_SMEM>>>();
    k_final<<<B * N / 2, 256>>>(pc0);
    k_out<<<1, 256>>>(out);
}

// round 15
// speedup vs baseline: 1.7227x; 1.0038x over previous
#include <cuda_runtime.h>
#include <cuda_bf16.h>
#include <cstdint>

namespace {
constexpr int B = 8;
constexpr int N = 1024;
constexpr int C = 128;
constexpr float SCALEF = 20.0f;
constexpr float EPSF = 1e-12f;
constexpr float LOG2E = 1.4426950408889634f;
constexpr float K2 = 4.808983469629878f;   // log2(e)/0.3
constexpr int SNB = 16;                    // sinkhorn blocks per batch
constexpr int STATS_BLKS = 20;             // extra stats blocks
constexpr int TPAD = 136;
constexpr int TSZ = 128 * TPAD;
constexpr int APAD = 72;
constexpr int VPAD = 136;
// NN smem (64-row A tiles)
constexpr int AH_O = 0;
constexpr int AL_O = 64 * APAD;
constexpr int VH_O = 2 * 64 * APAD;
constexpr int VL_O = VH_O + 64 * VPAD;
constexpr int NN_ELEMS = VL_O + 64 * VPAD;
constexpr int SINK_SMEM = (1024 + 16 * 1024) * 4;
// fused 1a2+12 smem tile offsets (elements)
constexpr int T_VIAH = 0;
constexpr int T_VIAL = TSZ;
constexpr int T_F1H = 2 * TSZ;
constexpr int T_F1L = 3 * TSZ;
constexpr int T_BH = 4 * TSZ;
constexpr int T_BL = 5 * TSZ;
}

__device__ float g_scrA[(size_t)B * N * N];
__device__ float g_scrB[(size_t)B * N * N];
__device__ __nv_bfloat16 g_FnH[2 * B * N * C];
__device__ __nv_bfloat16 g_FnL[2 * B * N * C];
__device__ __nv_bfloat16 g_viaH[B * N * C];
__device__ __nv_bfloat16 g_viaL[B * N * C];
__device__ __nv_bfloat16 g_smH[(size_t)B * N * N];
__device__ __nv_bfloat16 g_smL[(size_t)B * N * N];
__device__ float g_cpf[2 * B * SNB * N];
__device__ float g_r[B * N];
__device__ float g_c[B * N];
__device__ float g_maxA[B * N], g_sumA[B * N];
__device__ float g_maxB[B * N], g_sumB[B * N];
__device__ unsigned g_bar[B];
__device__ int g_correct;
__device__ float g_pL[B * N], g_pC[B * N], g_pP[B * N];

__device__ __forceinline__ float fex2(float x) {
    float y; asm("ex2.approx.ftz.f32 %0, %1;" : "=f"(y) : "f"(x)); return y;
}
__device__ __forceinline__ float flg2(float x) {
    float y; asm("lg2.approx.ftz.f32 %0, %1;" : "=f"(y) : "f"(x)); return y;
}
__device__ __forceinline__ uint32_t smem_u32(const void* p) {
    uint32_t a;
    asm("{ .reg .u64 t; cvta.to.shared.u64 t, %1; cvt.u32.u64 %0, t; }"
        : "=r"(a) : "l"(p));
    return a;
}
__device__ __forceinline__ void ldm4(uint32_t& r0, uint32_t& r1, uint32_t& r2,
                                     uint32_t& r3, uint32_t addr) {
    asm volatile("ldmatrix.sync.aligned.m8n8.x4.shared.b16 {%0,%1,%2,%3}, [%4];"
                 : "=r"(r0), "=r"(r1), "=r"(r2), "=r"(r3) : "r"(addr));
}
__device__ __forceinline__ void ldm4t(uint32_t& r0, uint32_t& r1, uint32_t& r2,
                                      uint32_t& r3, uint32_t addr) {
    asm volatile("ldmatrix.sync.aligned.m8n8.x4.trans.shared.b16 {%0,%1,%2,%3}, [%4];"
                 : "=r"(r0), "=r"(r1), "=r"(r2), "=r"(r3) : "r"(addr));
}
__device__ __forceinline__ void mma16816(float* c, const uint32_t* a,
                                         uint32_t b0, uint32_t b1) {
    asm volatile(
        "mma.sync.aligned.m16n8k16.row.col.f32.bf16.bf16.f32 "
        "{%0,%1,%2,%3}, {%4,%5,%6,%7}, {%8,%9}, {%0,%1,%2,%3};"
        : "+f"(c[0]), "+f"(c[1]), "+f"(c[2]), "+f"(c[3])
        : "r"(a[0]), "r"(a[1]), "r"(a[2]), "r"(a[3]), "r"(b0), "r"(b1));
}
__device__ __forceinline__ void hilo(float v, __nv_bfloat16& h, __nv_bfloat16& l) {
    h = __float2bfloat16(v);
    l = __float2bfloat16(v - __bfloat162float(h));
}

// ---------------------------------------------------------------------------
// norm (+ global state reset in block 0)
__global__ void __launch_bounds__(128) k_norm(const float* __restrict__ feats) {
    if (blockIdx.x == 0 && threadIdx.x < 32) {
        if (threadIdx.x < B) g_bar[threadIdx.x] = 0u;
        if (threadIdx.x == 0) g_correct = 0;
    }
    int row = blockIdx.x;
    const float* p = feats + (size_t)row * C;
    float v = p[threadIdx.x];
    float s = v * v;
    #pragma unroll
    for (int o = 16; o; o >>= 1) s += __shfl_xor_sync(0xffffffffu, s, o);
    __shared__ float sh[4];
    if ((threadIdx.x & 31) == 0) sh[threadIdx.x >> 5] = s;
    __syncthreads();
    s = sh[0] + sh[1] + sh[2] + sh[3];
    float scl = SCALEF / fmaxf(sqrtf(s), EPSF);
    float val = v * scl;
    size_t idx = (size_t)row * C + threadIdx.x;
    __nv_bfloat16 h, l;
    hilo(val, h, l);
    g_FnH[idx] = h;
    g_FnL[idx] = l;
}

// ---------------------------------------------------------------------------
// HMMA NT gemm for corr_1a only (f1 @ fa^T), bf16-split 3 terms.
__global__ void __launch_bounds__(256) k_hmma_nt0() {
    extern __shared__ __nv_bfloat16 smem[];
    int ia = blockIdx.x, ib = blockIdx.y, b = blockIdx.z;
    int tid = threadIdx.x, wid = tid >> 5, lane = tid & 31;

    const __nv_bfloat16* aHg = g_FnH + (size_t)(2 * b) * N * C + (size_t)ia * 128 * C;
    const __nv_bfloat16* aLg = g_FnL + (size_t)(2 * b) * N * C + (size_t)ia * 128 * C;
    int fsB = 2 * ((b + 1) & 7);
    const __nv_bfloat16* bHg = g_FnH + (size_t)fsB * N * C + (size_t)ib * 128 * C;
    const __nv_bfloat16* bLg = g_FnL + (size_t)fsB * N * C + (size_t)ib * 128 * C;

    {
        const uint4* src[4] = {(const uint4*)aHg, (const uint4*)aLg,
                               (const uint4*)bHg, (const uint4*)bLg};
        #pragma unroll
        for (int t4 = 0; t4 < 4; t4++) {
            __nv_bfloat16* dtile = smem + t4 * TSZ;
            #pragma unroll
            for (int i = 0; i < 8; i++) {
                int idx = tid + 256 * i;
                int row = idx >> 4, c8 = idx & 15;
                *(uint4*)(dtile + row * TPAD + c8 * 8) = src[t4][idx];
            }
        }
    }
    __syncthreads();

    int wm = wid & 3, wn = wid >> 2;
    float acc[2][8][4];
    #pragma unroll
    for (int mi = 0; mi < 2; mi++)
        #pragma unroll
        for (int nj = 0; nj < 8; nj++)
            #pragma unroll
            for (int q = 0; q < 4; q++) acc[mi][nj][q] = 0.f;

    uint32_t sbase = smem_u32(smem);
    const int selA[3] = {0, 0, 1};
    const int selB[3] = {2, 3, 2};
    int a_r = lane & 15, a_c = (lane >> 4) << 3;
    int b_r = (lane & 7) + ((lane >> 4) << 3);
    int b_c = ((lane >> 3) & 1) << 3;

    #pragma unroll
    for (int t = 0; t < 3; t++) {
        uint32_t aB = sbase + selA[t] * TSZ * 2;
        uint32_t bBs = sbase + selB[t] * TSZ * 2;
        #pragma unroll
        for (int k8 = 0; k8 < 8; k8++) {
            int kc = k8 * 16;
            uint32_t af[2][4];
            #pragma unroll
            for (int mi = 0; mi < 2; mi++) {
                int row = wm * 32 + mi * 16 + a_r;
                ldm4(af[mi][0], af[mi][1], af[mi][2], af[mi][3],
                     aB + (row * TPAD + kc + a_c) * 2);
            }
            uint32_t bf[4][4];
            #pragma unroll
            for (int nj = 0; nj < 4; nj++) {
                int row = wn * 64 + nj * 16 + b_r;
                ldm4(bf[nj][0], bf[nj][1], bf[nj][2], bf[nj][3],
                     bBs + (row * TPAD + kc + b_c) * 2);
            }
            #pragma unroll
            for (int mi = 0; mi < 2; mi++)
                #pragma unroll
                for (int nj = 0; nj < 4; nj++) {
                    mma16816(acc[mi][2 * nj], af[mi], bf[nj][0], bf[nj][1]);
                    mma16816(acc[mi][2 * nj + 1], af[mi], bf[nj][2], bf[nj][3]);
                }
        }
    }

    {
        int rbase = b * 1024 + ia * 128 + wm * 32 + (lane >> 2);
        int cbase = ib * 128 + wn * 64 + 2 * (lane & 3);
        #pragma unroll
        for (int mi = 0; mi < 2; mi++)
            #pragma unroll
            for (int nj = 0; nj < 8; nj++) {
                float* d0 = g_scrA + (size_t)(rbase + mi * 16) * 1024 + cbase + nj * 8;
                *(float2*)d0 = make_float2(acc[mi][nj][0], acc[mi][nj][1]);
                float* d1 = d0 + 8 * 1024;
                *(float2*)d1 = make_float2(acc[mi][nj][2], acc[mi][nj][3]);
            }
    }
}

// ---------------------------------------------------------------------------
// Fused NT gemms sharing B = f2: corr_1a2 = via@f2^T -> scrA,
// corr_12 = f1@f2^T -> scrB. B fragments loaded once per k-step.
__global__ void __launch_bounds__(256) k_hmma_nt12() {
    extern __shared__ __nv_bfloat16 smem[];
    int ia = blockIdx.x, ib = blockIdx.y, b = blockIdx.z;
    int tid = threadIdx.x, wid = tid >> 5, lane = tid & 31;

    {
        const uint4* src[6] = {
            (const uint4*)(g_viaH + (size_t)b * N * C + (size_t)ia * 128 * C),
            (const uint4*)(g_viaL + (size_t)b * N * C + (size_t)ia * 128 * C),
            (const uint4*)(g_FnH + (size_t)(2 * b) * N * C + (size_t)ia * 128 * C),
            (const uint4*)(g_FnL + (size_t)(2 * b) * N * C + (size_t)ia * 128 * C),
            (const uint4*)(g_FnH + (size_t)(2 * b + 1) * N * C + (size_t)ib * 128 * C),
            (const uint4*)(g_FnL + (size_t)(2 * b + 1) * N * C + (size_t)ib * 128 * C)};
        #pragma unroll
        for (int t6 = 0; t6 < 6; t6++) {
            __nv_bfloat16* dtile = smem + t6 * TSZ;
            #pragma unroll
            for (int i = 0; i < 8; i++) {
                int idx = tid + 256 * i;
                int row = idx >> 4, c8 = idx & 15;
                *(uint4*)(dtile + row * TPAD + c8 * 8) = src[t6][idx];
            }
        }
    }
    __syncthreads();

    int wm = wid & 3, wn = wid >> 2;
    float accA[2][8][4], accB[2][8][4];
    #pragma unroll
    for (int mi = 0; mi < 2; mi++)
        #pragma unroll
        for (int nj = 0; nj < 8; nj++)
            #pragma unroll
            for (int q = 0; q < 4; q++) { accA[mi][nj][q] = 0.f; accB[mi][nj][q] = 0.f; }

    uint32_t sbase = smem_u32(smem);
    int a_r = lane & 15, a_c = (lane >> 4) << 3;
    int b_r = (lane & 7) + ((lane >> 4) << 3);
    int b_c = ((lane >> 3) & 1) << 3;

    #pragma unroll
    for (int k8 = 0; k8 < 8; k8++) {
        int kc = k8 * 16;
        // shared B fragments (hi + lo), loaded once
        uint32_t bh[4][4], bl[4][4];
        #pragma unroll
        for (int nj = 0; nj < 4; nj++) {
            int row = wn * 64 + nj * 16 + b_r;
            ldm4(bh[nj][0], bh[nj][1], bh[nj][2], bh[nj][3],
                 sbase + (T_BH + row * TPAD + kc + b_c) * 2);
            ldm4(bl[nj][0], bl[nj][1], bl[nj][2], bl[nj][3],
                 sbase + (T_BL + row * TPAD + kc + b_c) * 2);
        }
        // two outputs: 0 = via (->accA), 1 = f1 (->accB)
        #pragma unroll
        for (int out = 0; out < 2; out++) {
            int aH_off = out ? T_F1H : T_VIAH;
            int aL_off = out ? T_F1L : T_VIAL;
            uint32_t ah[2][4], al[2][4];
            #pragma unroll
            for (int mi = 0; mi < 2; mi++) {
                int row = wm * 32 + mi * 16 + a_r;
                ldm4(ah[mi][0], ah[mi][1], ah[mi][2], ah[mi][3],
                     sbase + (aH_off + row * TPAD + kc + a_c) * 2);
                ldm4(al[mi][0], al[mi][1], al[mi][2], al[mi][3],
                     sbase + (aL_off + row * TPAD + kc + a_c) * 2);
            }
            float (*acc)[8][4] = out ? accB : accA;
            #pragma unroll
            for (int mi = 0; mi < 2; mi++)
                #pragma unroll
                for (int nj = 0; nj < 4; nj++) {
                    // aHi*bHi
                    mma16816(acc[mi][2 * nj], ah[mi], bh[nj][0], bh[nj][1]);
                    mma16816(acc[mi][2 * nj + 1], ah[mi], bh[nj][2], bh[nj][3]);
                    // aHi*bLo
                    mma16816(acc[mi][2 * nj], ah[mi], bl[nj][0], bl[nj][1]);
                    mma16816(acc[mi][2 * nj + 1], ah[mi], bl[nj][2], bl[nj][3]);
                    // aLo*bHi
                    mma16816(acc[mi][2 * nj], al[mi], bh[nj][0], bh[nj][1]);
                    mma16816(acc[mi][2 * nj + 1], al[mi], bh[nj][2], bh[nj][3]);
                }
        }
    }

    {
        int rbase = b * 1024 + ia * 128 + wm * 32 + (lane >> 2);
        int cbase = ib * 128 + wn * 64 + 2 * (lane & 3);
        #pragma unroll
        for (int mi = 0; mi < 2; mi++)
            #pragma unroll
            for (int nj = 0; nj < 8; nj++) {
                size_t o0 = (size_t)(rbase + mi * 16) * 1024 + cbase + nj * 8;
                *(float2*)(g_scrA + o0) = make_float2(accA[mi][nj][0], accA[mi][nj][1]);
                *(float2*)(g_scrA + o0 + 8 * 1024) = make_float2(accA[mi][nj][2], accA[mi][nj][3]);
                *(float2*)(g_scrB + o0) = make_float2(accB[mi][nj][0], accB[mi][nj][1]);
                *(float2*)(g_scrB + o0 + 8 * 1024) = make_float2(accB[mi][nj][2], accB[mi][nj][3]);
            }
    }
}

// ---------------------------------------------------------------------------
// row softmax of corr_1a (fp32 in scrA) -> bf16 hi/lo smcorr
__global__ void __launch_bounds__(256) k_rowsoftmax() {
    size_t row = blockIdx.x;
    const float4* p = (const float4*)(g_scrA + row * N);
    int tid = threadIdx.x, lane = tid & 31;
    float4 v = p[tid];
    float mx = fmaxf(fmaxf(v.x, v.y), fmaxf(v.z, v.w));
    #pragma unroll
    for (int o = 16; o; o >>= 1) mx = fmaxf(mx, __shfl_xor_sync(0xffffffffu, mx, o));
    __shared__ float shm[8], shs[8];
    if (lane == 0) shm[tid >> 5] = mx;
    __syncthreads();
    mx = fmaxf(fmaxf(fmaxf(shm[0], shm[1]), fmaxf(shm[2], shm[3])),
               fmaxf(fmaxf(shm[4], shm[5]), fmaxf(shm[6], shm[7])));
    float4 e;
    e.x = fex2((v.x - mx) * LOG2E);
    e.y = fex2((v.y - mx) * LOG2E);
    e.z = fex2((v.z - mx) * LOG2E);
    e.w = fex2((v.w - mx) * LOG2E);
    float s = e.x + e.y + e.z + e.w;
    #pragma unroll
    for (int o = 16; o; o >>= 1) s += __shfl_xor_sync(0xffffffffu, s, o);
    if (lane == 0) shs[tid >> 5] = s;
    __syncthreads();
    s = shs[0] + shs[1] + shs[2] + shs[3] + shs[4] + shs[5] + shs[6] + shs[7];
    float inv = 1.0f / s;
    float f[4] = {e.x * inv, e.y * inv, e.z * inv, e.w * inv};
    __nv_bfloat16 h[4], l[4];
    #pragma unroll
    for (int q = 0; q < 4; q++) hilo(f[q], h[q], l[q]);
    __nv_bfloat162* dH = (__nv_bfloat162*)(g_smH + row * N + 4 * tid);
    __nv_bfloat162* dL = (__nv_bfloat162*)(g_smL + row * N + 4 * tid);
    dH[0] = __nv_bfloat162{h[0], h[1]};
    dH[1] = __nv_bfloat162{h[2], h[3]};
    dL[0] = __nv_bfloat162{l[0], l[1]};
    dL[1] = __nv_bfloat162{l[2], l[3]};
}

// ---------------------------------------------------------------------------
// HMMA NN gemm, 64-row CTAs (128 CTAs): via[b] = smcorr[b] @ fa[b]; out hi/lo
__global__ void __launch_bounds__(256) k_hmma_nn() {
    extern __shared__ __nv_bfloat16 smem[];
    int rb = blockIdx.x, b = blockIdx.y;
    int tid = threadIdx.x, wid = tid >> 5, lane = tid & 31;
    int fs = 2 * ((b + 1) & 7);

    int wm = wid & 1, wn = wid >> 1;
    float acc[2][4][4];
    #pragma unroll
    for (int mi = 0; mi < 2; mi++)
        #pragma unroll
        for (int nj = 0; nj < 4; nj++)
            #pragma unroll
            for (int q = 0; q < 4; q++) acc[mi][nj][q] = 0.f;

    uint32_t sbase = smem_u32(smem);
    const int AOFF[3] = {AH_O, AH_O, AL_O};
    const int VOFF[3] = {VH_O, VL_O, VH_O};
    int a_r = lane & 15, a_c = (lane >> 4) << 3;
    int bt_r = (lane & 7) + (((lane >> 3) & 1) << 3);
    int bt_c = (lane >> 4) << 3;

    for (int kc = 0; kc < 16; kc++) {
        int kb = kc * 64;
        if (kc) __syncthreads();
        #pragma unroll
        for (int i = 0; i < 2; i++) {
            int idx = tid + 256 * i;
            int r = idx >> 3, c8 = idx & 7;
            size_t so = (size_t)(b * 1024 + rb * 64 + r) * 1024 + kb + c8 * 8;
            *(uint4*)(smem + AH_O + r * APAD + c8 * 8) = *(const uint4*)(g_smH + so);
            *(uint4*)(smem + AL_O + r * APAD + c8 * 8) = *(const uint4*)(g_smL + so);
        }
        #pragma unroll
        for (int i = 0; i < 4; i++) {
            int idx = tid + 256 * i;
            int r = idx >> 4, c8 = idx & 15;
            size_t so = (size_t)(fs * 1024 + kb + r) * 128 + c8 * 8;
            *(uint4*)(smem + VH_O + r * VPAD + c8 * 8) = *(const uint4*)(g_FnH + so);
            *(uint4*)(smem + VL_O + r * VPAD + c8 * 8) = *(const uint4*)(g_FnL + so);
        }
        __syncthreads();

        #pragma unroll
        for (int t = 0; t < 3; t++) {
            #pragma unroll
            for (int k16 = 0; k16 < 4; k16++) {
                int kk = k16 * 16;
                uint32_t af[2][4];
                #pragma unroll
                for (int mi = 0; mi < 2; mi++) {
                    int row = wm * 32 + mi * 16 + a_r;
                    ldm4(af[mi][0], af[mi][1], af[mi][2], af[mi][3],
                         sbase + (AOFF[t] + row * APAD + kk + a_c) * 2);
                }
                uint32_t bf[2][4];
                #pragma unroll
                for (int nj = 0; nj < 2; nj++) {
                    int krow = kk + bt_r;
                    int ccol = wn * 32 + nj * 16 + bt_c;
                    ldm4t(bf[nj][0], bf[nj][1], bf[nj][2], bf[nj][3],
                          sbase + (VOFF[t] + krow * VPAD + ccol) * 2);
                }
                #pragma unroll
                for (int mi = 0; mi < 2; mi++)
                    #pragma unroll
                    for (int nj = 0; nj < 2; nj++) {
                        mma16816(acc[mi][2 * nj], af[mi], bf[nj][0], bf[nj][1]);
                        mma16816(acc[mi][2 * nj + 1], af[mi], bf[nj][2], bf[nj][3]);
                    }
            }
        }
    }

    {
        int rbase = b * 1024 + rb * 64 + wm * 32 + (lane >> 2);
        int cbase = wn * 32 + 2 * (lane & 3);
        #pragma unroll
        for (int mi = 0; mi < 2; mi++)
            #pragma unroll
            for (int nj = 0; nj < 4; nj++) {
                #pragma unroll
                for (int half = 0; half < 2; half++) {
                    int row = rbase + mi * 16 + half * 8;
                    int col = cbase + nj * 8;
                    float v0 = acc[mi][nj][2 * half], v1 = acc[mi][nj][2 * half + 1];
                    __nv_bfloat16 h0, l0, h1, l1;
                    hilo(v0, h0, l0);
                    hilo(v1, h1, l1);
                    size_t o = (size_t)row * C + col;
                    *(__nv_bfloat162*)(g_viaH + o) = __nv_bfloat162{h0, h1};
                    *(__nv_bfloat162*)(g_viaL + o) = __nv_bfloat162{l0, l1};
                }
            }
    }
}

// ---------------------------------------------------------------------------
__device__ __forceinline__ void batch_bar(int b, unsigned target) {
    __syncthreads();
    if (threadIdx.x == 0) {
        unsigned v;
        asm volatile("red.release.gpu.add.u32 [%0], %1;"
                     :: "l"(&g_bar[b]), "r"(1u) : "memory");
        do {
            asm volatile("ld.acquire.gpu.u32 %0, [%1];"
                         : "=r"(v) : "l"(&g_bar[b]) : "memory");
        } while (v < target);
    }
    __syncthreads();
}

// ---------------------------------------------------------------------------
__device__ void stats_work(int sbid) {
    int tid = threadIdx.x, wid = tid >> 5, lane = tid & 31;
    int w = sbid * 16 + wid;
    for (int row = w; row < B * N; row += STATS_BLKS * 16) {
        const float* pA = g_scrA + (size_t)row * N;
        const float* pB = g_scrB + (size_t)row * N;
        float vv[32];
        #pragma unroll
        for (int j = 0; j < 8; j++) {
            float4 f = *(const float4*)(pA + lane * 4 + 128 * j);
            vv[4 * j] = f.x; vv[4 * j + 1] = f.y; vv[4 * j + 2] = f.z; vv[4 * j + 3] = f.w;
        }
        float mx = -1e30f; int arg = 0;
        #pragma unroll
        for (int j = 0; j < 32; j++) {
            int idx = lane * 4 + 128 * (j >> 2) + (j & 3);
            if (vv[j] > mx) { mx = vv[j]; arg = idx; }
        }
        #pragma unroll
        for (int o = 16; o; o >>= 1) {
            float m2 = __shfl_xor_sync(0xffffffffu, mx, o);
            int a2 = __shfl_xor_sync(0xffffffffu, arg, o);
            if (m2 > mx || (m2 == mx && a2 < arg)) { mx = m2; arg = a2; }
        }
        float s = 0.f;
        #pragma unroll
        for (int j = 0; j < 32; j++) s += fex2((vv[j] - mx) * LOG2E);
        #pragma unroll
        for (int o = 16; o; o >>= 1) s += __shfl_xor_sync(0xffffffffu, s, o);
        if (lane == 0) {
            g_maxA[row] = mx; g_sumA[row] = s;
            if (arg == (row & 1023)) atomicAdd(&g_correct, 1);
        }
        #pragma unroll
        for (int j = 0; j < 8; j++) {
            float4 f = *(const float4*)(pB + lane * 4 + 128 * j);
            vv[4 * j] = f.x; vv[4 * j + 1] = f.y; vv[4 * j + 2] = f.z; vv[4 * j + 3] = f.w;
        }
        mx = -1e30f;
        #pragma unroll
        for (int j = 0; j < 32; j++) mx = fmaxf(mx, vv[j]);
        #pragma unroll
        for (int o = 16; o; o >>= 1) mx = fmaxf(mx, __shfl_xor_sync(0xffffffffu, mx, o));
        s = 0.f;
        #pragma unroll
        for (int j = 0; j < 32; j++) s += fex2((vv[j] - mx) * LOG2E);
        #pragma unroll
        for (int o = 16; o; o >>= 1) s += __shfl_xor_sync(0xffffffffu, s, o);
        if (lane == 0) { g_maxB[row] = mx; g_sumB[row] = s; }
    }
}

// persistent sinkhorn, warp-autonomous rows; c register-resident per lane
__global__ void __launch_bounds__(512) k_sinkhorn() {
    if (blockIdx.x >= B * SNB) { stats_work(blockIdx.x - B * SNB); return; }
    extern __shared__ float dsm[];
    float* sc = dsm;
    float* sq = dsm + 1024;
    int b = blockIdx.x >> 4, sub = blockIdx.x & 15;
    const float* Mblk = g_scrA + (size_t)(b * 1024 + sub * 64) * N;
    int tid = threadIdx.x, warp = tid >> 5, lane = tid & 31;
    sc[tid] = 0.f;
    sc[tid + 512] = 0.f;
    __syncthreads();

    float rprev[4];
    unsigned bar_t = 0;

    for (int it = 0; it < 30; it++) {
        int par = it & 1;
        float2 cc[16];
        #pragma unroll
        for (int j = 0; j < 16; j++) cc[j] = *(float2*)&sc[2 * lane + 64 * j];
        float2 q[16];
        #pragma unroll
        for (int j = 0; j < 16; j++) q[j] = make_float2(0.f, 0.f);

        #pragma unroll
        for (int ri = 0; ri < 4; ri++) {
            const float2* rowp = (const float2*)(Mblk + (size_t)(warp * 4 + ri) * N);
            float2 e[16];
            float lg;
            if (it == 0) {
                float m = -1e30f;
                #pragma unroll
                for (int j = 0; j < 16; j++) {
                    float2 y = rowp[lane + 32 * j];
                    e[j].x = fmaf(y.x, K2, cc[j].x);
                    e[j].y = fmaf(y.y, K2, cc[j].y);
                    m = fmaxf(m, fmaxf(e[j].x, e[j].y));
                }
                #pragma unroll
                for (int o = 16; o; o >>= 1)
                    m = fmaxf(m, __shfl_xor_sync(0xffffffffu, m, o));
                float s = 0.f;
                #pragma unroll
                for (int j = 0; j < 16; j++) {
                    e[j].x = fex2(e[j].x - m);
                    e[j].y = fex2(e[j].y - m);
                    s += e[j].x + e[j].y;
                }
                #pragma unroll
                for (int o = 16; o; o >>= 1) s += __shfl_xor_sync(0xffffffffu, s, o);
                lg = flg2(s);
                rprev[ri] = -(m + lg);
            } else {
                float rp = rprev[ri];
                float s = 0.f;
                #pragma unroll
                for (int j = 0; j < 16; j++) {
                    float2 y = rowp[lane + 32 * j];
                    e[j].x = fex2(fmaf(y.x, K2, cc[j].x) + rp);
                    e[j].y = fex2(fmaf(y.y, K2, cc[j].y) + rp);
                    s += e[j].x + e[j].y;
                }
                #pragma unroll
                for (int o = 16; o; o >>= 1) s += __shfl_xor_sync(0xffffffffu, s, o);
                lg = flg2(fmaxf(s, 1e-30f));
                rprev[ri] = rp - lg;
            }
            float is = fex2(-lg);
            #pragma unroll
            for (int j = 0; j < 16; j++) {
                q[j].x = fmaf(e[j].x, is, q[j].x);
                q[j].y = fmaf(e[j].y, is, q[j].y);
            }
        }

        #pragma unroll
        for (int j = 0; j < 16; j++)
            *(float2*)&sq[warp * 1024 + 2 * lane + 64 * j] = q[j];
        __syncthreads();
        float s0 = 0.f, s1 = 0.f;
        #pragma unroll
        for (int k = 0; k < 16; k++) {
            float2 t2 = *(float2*)&sq[k * 1024 + 2 * tid];
            s0 += t2.x; s1 += t2.y;
        }
        float* cp = g_cpf + (size_t)par * (B * SNB * N) + (size_t)(b * 16 + sub) * N;
        *(float2*)&cp[2 * tid] = make_float2(s0, s1);
        bar_t += SNB; batch_bar(b, bar_t);

        const float* base = g_cpf + (size_t)par * (B * SNB * N) + (size_t)b * 16 * N;
        #pragma unroll
        for (int h = 0; h < 2; h++) {
            int col = tid + 512 * h;
            float s = 0.f;
            #pragma unroll
            for (int k = 0; k < 16; k++) s += base[(size_t)k * N + col];
            sc[col] = sc[col] - flg2(fmaxf(s, 1e-30f));
        }
        __syncthreads();
    }

    if (lane == 0) {
        #pragma unroll
        for (int ri = 0; ri < 4; ri++)
            g_r[b * N + sub * 64 + warp * 4 + ri] = rprev[ri];
    }
    if (tid < 64) g_c[b * N + sub * 64 + tid] = sc[sub * 64 + tid];
}

// ---------------------------------------------------------------------------
// fused final pass: 4 rows per block
__global__ void __launch_bounds__(256) k_final(const float* __restrict__ pc0) {
    int quad = blockIdx.x;             // 0..2047
    int b = quad >> 8;
    int n0 = (quad & 255) * 4;
    int tid = threadIdx.x, lane = tid & 31, warp = tid >> 5;

    __shared__ float spc[3 * 1024];
    __shared__ float scv[1024];
    __shared__ float s1[8], s2[8], s3[8];
    const float* pc = pc0 + (size_t)b * N * 3;
    for (int i = tid; i < 3 * 1024; i += 256) spc[i] = pc[i];
    for (int i = tid; i < 1024; i += 256) scv[i] = g_c[b * N + i];
    __syncthreads();

    #pragma unroll
    for (int rr = 0; rr < 4; rr++) {
        int n = n0 + rr;
        size_t row = (size_t)b * N + n;
        const float* pA = g_scrA + row * N;
        const float* pB = g_scrB + row * N;
        float mA = g_maxA[row], iA = 1.0f / g_sumA[row];
        float mB = g_maxB[row], iB = 1.0f / g_sumB[row];
        float rn = g_r[row];
        float px = spc[3 * n], py = spc[3 * n + 1], pz = spc[3 * n + 2];
        float aL = 0.f, aC = 0.f, aP = 0.f;
        #pragma unroll
        for (int t = 0; t < 4; t++) {
            int m = tid + 256 * t;
            float xA = pA[m], xB = pB[m];
            float smA = fex2((xA - mA) * LOG2E) * iA;
            float smB = fex2((xB - mB) * LOG2E) * iB;
            float dx = px - spc[3 * m], dy = py - spc[3 * m + 1], dz = pz - spc[3 * m + 2];
            float d2 = dx * dx + dy * dy + dz * dz;
            float dist = sqrtf(sqrtf(d2));
            aL += dist * (smA + smB);
            float sink = fex2(xA * K2 + rn + scv[m]);
            aC += fabsf(sink - smA);
            aP += (m == n) ? fabsf(1.0f - sink) : sink;
        }
        #pragma unroll
        for (int o = 16; o; o >>= 1) {
            aL += __shfl_xor_sync(0xffffffffu, aL, o);
            aC += __shfl_xor_sync(0xffffffffu, aC, o);
            aP += __shfl_xor_sync(0xffffffffu, aP, o);
        }
        if (lane == 0) { s1[warp] = aL; s2[warp] = aC; s3[warp] = aP; }
        __syncthreads();
        if (tid == 0) {
            float tL = 0.f, tC = 0.f, tP = 0.f;
            #pragma unroll
            for (int q = 0; q < 8; q++) { tL += s1[q]; tC += s2[q]; tP += s3[q]; }
            g_pL[row] = tL; g_pC[row] = tC; g_pP[row] = tP;
        }
        __syncthreads();
    }
}

// ---------------------------------------------------------------------------
__global__ void __launch_bounds__(256) k_out(float* __restrict__ out) {
    int tid = threadIdx.x;
    float sL = 0.f, sC = 0.f, sP = 0.f;
    for (int i = tid; i < B * N; i += 256) {
        sL += g_pL[i]; sC += g_pC[i]; sP += g_pP[i];
    }
    #pragma unroll
    for (int o = 16; o; o >>= 1) {
        sL += __shfl_xor_sync(0xffffffffu, sL, o);
        sC += __shfl_xor_sync(0xffffffffu, sC, o);
        sP += __shfl_xor_sync(0xffffffffu, sP, o);
    }
    __shared__ float s1[8], s2[8], s3[8];
    if ((tid & 31) == 0) { s1[tid >> 5] = sL; s2[tid >> 5] = sC; s3[tid >> 5] = sP; }
    __syncthreads();
    if (tid == 0) {
        float tL = 0.f, tC = 0.f, tP = 0.f;
        #pragma unroll
        for (int q = 0; q < 8; q++) { tL += s1[q]; tC += s2[q]; tP += s3[q]; }
        float invN = 1.0f / (float)N;
        float loss = tL * invN;
        float Lc = 3.0f * tC * invN;
        float perm = 3.0f * tP * invN;
        float corr = (float)g_correct;
        float invB = 1.0f / (float)B;
        out[0] = (loss + Lc) * invB;
        out[1] = loss * invB;
        out[2] = Lc * invB;
        out[3] = corr * invB;
        out[4] = perm * invB;
    }
}

// ---------------------------------------------------------------------------
extern "C" void kernel_launch(void* const* d_in, const int* in_sizes, int n_in,
                              void* d_out, int out_size) {
    const float* feats = (const float*)d_in[0];
    const float* pc0 = (const float*)d_in[1];
    float* out = (float*)d_out;

    const int nt_smem = 4 * TSZ * sizeof(__nv_bfloat16);
    const int nt12_smem = 6 * TSZ * sizeof(__nv_bfloat16);   // 208896
    const int nn_smem = NN_ELEMS * sizeof(__nv_bfloat16);
    static bool attr_done = false;
    if (!attr_done) {
        cudaFuncSetAttribute(k_hmma_nt0, cudaFuncAttributeMaxDynamicSharedMemorySize,
                             nt_smem);
        cudaFuncSetAttribute(k_hmma_nt12, cudaFuncAttributeMaxDynamicSharedMemorySize,
                             nt12_smem);
        cudaFuncSetAttribute(k_hmma_nn, cudaFuncAttributeMaxDynamicSharedMemorySize,
                             nn_smem);
        cudaFuncSetAttribute(k_sinkhorn, cudaFuncAttributeMaxDynamicSharedMemorySize,
                             SINK_SMEM);
        attr_done = true;
    }

    k_norm<<<2 * B * N, 128>>>(feats);                 // + state reset
    k_hmma_nt0<<<dim3(8, 8, 8), 256, nt_smem>>>();     // corr_1a -> scrA
    k_rowsoftmax<<<B * N, 256>>>();                    // smcorr hi/lo bf16
    k_hmma_nn<<<dim3(16, 8), 256, nn_smem>>>();        // via hi/lo
    k_hmma_nt12<<<dim3(8, 8, 8), 256, nt12_smem>>>();  // corr_1a2 + corr_12 fused
    k_sinkhorn<<<B * SNB + STATS_BLKS, 512, SINK_SMEM>>>();
    k_final<<<B * N / 4, 256>>>(pc0);
    k_out<<<1, 256>>>(out);
}

// round 16
// speedup vs baseline: 1.7431x; 1.0119x over previous
#include <cuda_runtime.h>
#include <cuda_bf16.h>
#include <cstdint>

namespace {
constexpr int B = 8;
constexpr int N = 1024;
constexpr int C = 128;
constexpr float SCALEF = 20.0f;
constexpr float EPSF = 1e-12f;
constexpr float LOG2E = 1.4426950408889634f;
constexpr float K2 = 4.808983469629878f;   // log2(e)/0.3
constexpr int SNB = 16;                    // sinkhorn blocks per batch
constexpr int STATS_BLKS = 20;             // extra stats blocks
constexpr int TPAD = 136;
constexpr int TSZ = 128 * TPAD;
constexpr int APAD = 72;
constexpr int VPAD = 136;
// NN smem (64-row A tiles)
constexpr int AH_O = 0;
constexpr int AL_O = 64 * APAD;
constexpr int VH_O = 2 * 64 * APAD;
constexpr int VL_O = VH_O + 64 * VPAD;
constexpr int NN_ELEMS = VL_O + 64 * VPAD;
constexpr int SINK_SMEM = (1024 + 16 * 1024) * 4;
// fused 1a2+12 smem tile offsets (elements)
constexpr int T_VIAH = 0;
constexpr int T_VIAL = TSZ;
constexpr int T_F1H = 2 * TSZ;
constexpr int T_F1L = 3 * TSZ;
constexpr int T_BH = 4 * TSZ;
constexpr int T_BL = 5 * TSZ;
}

__device__ float g_scrA[(size_t)B * N * N];
__device__ float g_scrB[(size_t)B * N * N];
__device__ __nv_bfloat16 g_FnH[2 * B * N * C];
__device__ __nv_bfloat16 g_FnL[2 * B * N * C];
__device__ __nv_bfloat16 g_viaH[B * N * C];
__device__ __nv_bfloat16 g_viaL[B * N * C];
__device__ float g_viaP[4][B * N * C];     // K-split fp32 partials
__device__ __nv_bfloat16 g_smH[(size_t)B * N * N];
__device__ __nv_bfloat16 g_smL[(size_t)B * N * N];
__device__ float g_cpf[2 * B * SNB * N];
__device__ float g_r[B * N];
__device__ float g_c[B * N];
__device__ float g_maxA[B * N], g_sumA[B * N];
__device__ float g_maxB[B * N], g_sumB[B * N];
__device__ unsigned g_bar[B];
__device__ int g_correct;
__device__ float g_pL[B * N], g_pC[B * N], g_pP[B * N];

__device__ __forceinline__ float fex2(float x) {
    float y; asm("ex2.approx.ftz.f32 %0, %1;" : "=f"(y) : "f"(x)); return y;
}
__device__ __forceinline__ float flg2(float x) {
    float y; asm("lg2.approx.ftz.f32 %0, %1;" : "=f"(y) : "f"(x)); return y;
}
__device__ __forceinline__ uint32_t smem_u32(const void* p) {
    uint32_t a;
    asm("{ .reg .u64 t; cvta.to.shared.u64 t, %1; cvt.u32.u64 %0, t; }"
        : "=r"(a) : "l"(p));
    return a;
}
__device__ __forceinline__ void ldm4(uint32_t& r0, uint32_t& r1, uint32_t& r2,
                                     uint32_t& r3, uint32_t addr) {
    asm volatile("ldmatrix.sync.aligned.m8n8.x4.shared.b16 {%0,%1,%2,%3}, [%4];"
                 : "=r"(r0), "=r"(r1), "=r"(r2), "=r"(r3) : "r"(addr));
}
__device__ __forceinline__ void ldm4t(uint32_t& r0, uint32_t& r1, uint32_t& r2,
                                      uint32_t& r3, uint32_t addr) {
    asm volatile("ldmatrix.sync.aligned.m8n8.x4.trans.shared.b16 {%0,%1,%2,%3}, [%4];"
                 : "=r"(r0), "=r"(r1), "=r"(r2), "=r"(r3) : "r"(addr));
}
__device__ __forceinline__ void mma16816(float* c, const uint32_t* a,
                                         uint32_t b0, uint32_t b1) {
    asm volatile(
        "mma.sync.aligned.m16n8k16.row.col.f32.bf16.bf16.f32 "
        "{%0,%1,%2,%3}, {%4,%5,%6,%7}, {%8,%9}, {%0,%1,%2,%3};"
        : "+f"(c[0]), "+f"(c[1]), "+f"(c[2]), "+f"(c[3])
        : "r"(a[0]), "r"(a[1]), "r"(a[2]), "r"(a[3]), "r"(b0), "r"(b1));
}
__device__ __forceinline__ void hilo(float v, __nv_bfloat16& h, __nv_bfloat16& l) {
    h = __float2bfloat16(v);
    l = __float2bfloat16(v - __bfloat162float(h));
}

// ---------------------------------------------------------------------------
// norm (+ global state reset in block 0)
__global__ void __launch_bounds__(128) k_norm(const float* __restrict__ feats) {
    if (blockIdx.x == 0 && threadIdx.x < 32) {
        if (threadIdx.x < B) g_bar[threadIdx.x] = 0u;
        if (threadIdx.x == 0) g_correct = 0;
    }
    int row = blockIdx.x;
    const float* p = feats + (size_t)row * C;
    float v = p[threadIdx.x];
    float s = v * v;
    #pragma unroll
    for (int o = 16; o; o >>= 1) s += __shfl_xor_sync(0xffffffffu, s, o);
    __shared__ float sh[4];
    if ((threadIdx.x & 31) == 0) sh[threadIdx.x >> 5] = s;
    __syncthreads();
    s = sh[0] + sh[1] + sh[2] + sh[3];
    float scl = SCALEF / fmaxf(sqrtf(s), EPSF);
    float val = v * scl;
    size_t idx = (size_t)row * C + threadIdx.x;
    __nv_bfloat16 h, l;
    hilo(val, h, l);
    g_FnH[idx] = h;
    g_FnL[idx] = l;
}

// ---------------------------------------------------------------------------
// HMMA NT gemm for corr_1a only (f1 @ fa^T), bf16-split 3 terms.
__global__ void __launch_bounds__(256) k_hmma_nt0() {
    extern __shared__ __nv_bfloat16 smem[];
    int ia = blockIdx.x, ib = blockIdx.y, b = blockIdx.z;
    int tid = threadIdx.x, wid = tid >> 5, lane = tid & 31;

    const __nv_bfloat16* aHg = g_FnH + (size_t)(2 * b) * N * C + (size_t)ia * 128 * C;
    const __nv_bfloat16* aLg = g_FnL + (size_t)(2 * b) * N * C + (size_t)ia * 128 * C;
    int fsB = 2 * ((b + 1) & 7);
    const __nv_bfloat16* bHg = g_FnH + (size_t)fsB * N * C + (size_t)ib * 128 * C;
    const __nv_bfloat16* bLg = g_FnL + (size_t)fsB * N * C + (size_t)ib * 128 * C;

    {
        const uint4* src[4] = {(const uint4*)aHg, (const uint4*)aLg,
                               (const uint4*)bHg, (const uint4*)bLg};
        #pragma unroll
        for (int t4 = 0; t4 < 4; t4++) {
            __nv_bfloat16* dtile = smem + t4 * TSZ;
            #pragma unroll
            for (int i = 0; i < 8; i++) {
                int idx = tid + 256 * i;
                int row = idx >> 4, c8 = idx & 15;
                *(uint4*)(dtile + row * TPAD + c8 * 8) = src[t4][idx];
            }
        }
    }
    __syncthreads();

    int wm = wid & 3, wn = wid >> 2;
    float acc[2][8][4];
    #pragma unroll
    for (int mi = 0; mi < 2; mi++)
        #pragma unroll
        for (int nj = 0; nj < 8; nj++)
            #pragma unroll
            for (int q = 0; q < 4; q++) acc[mi][nj][q] = 0.f;

    uint32_t sbase = smem_u32(smem);
    const int selA[3] = {0, 0, 1};
    const int selB[3] = {2, 3, 2};
    int a_r = lane & 15, a_c = (lane >> 4) << 3;
    int b_r = (lane & 7) + ((lane >> 4) << 3);
    int b_c = ((lane >> 3) & 1) << 3;

    #pragma unroll
    for (int t = 0; t < 3; t++) {
        uint32_t aB = sbase + selA[t] * TSZ * 2;
        uint32_t bBs = sbase + selB[t] * TSZ * 2;
        #pragma unroll
        for (int k8 = 0; k8 < 8; k8++) {
            int kc = k8 * 16;
            uint32_t af[2][4];
            #pragma unroll
            for (int mi = 0; mi < 2; mi++) {
                int row = wm * 32 + mi * 16 + a_r;
                ldm4(af[mi][0], af[mi][1], af[mi][2], af[mi][3],
                     aB + (row * TPAD + kc + a_c) * 2);
            }
            uint32_t bf[4][4];
            #pragma unroll
            for (int nj = 0; nj < 4; nj++) {
                int row = wn * 64 + nj * 16 + b_r;
                ldm4(bf[nj][0], bf[nj][1], bf[nj][2], bf[nj][3],
                     bBs + (row * TPAD + kc + b_c) * 2);
            }
            #pragma unroll
            for (int mi = 0; mi < 2; mi++)
                #pragma unroll
                for (int nj = 0; nj < 4; nj++) {
                    mma16816(acc[mi][2 * nj], af[mi], bf[nj][0], bf[nj][1]);
                    mma16816(acc[mi][2 * nj + 1], af[mi], bf[nj][2], bf[nj][3]);
                }
        }
    }

    {
        int rbase = b * 1024 + ia * 128 + wm * 32 + (lane >> 2);
        int cbase = ib * 128 + wn * 64 + 2 * (lane & 3);
        #pragma unroll
        for (int mi = 0; mi < 2; mi++)
            #pragma unroll
            for (int nj = 0; nj < 8; nj++) {
                float* d0 = g_scrA + (size_t)(rbase + mi * 16) * 1024 + cbase + nj * 8;
                *(float2*)d0 = make_float2(acc[mi][nj][0], acc[mi][nj][1]);
                float* d1 = d0 + 8 * 1024;
                *(float2*)d1 = make_float2(acc[mi][nj][2], acc[mi][nj][3]);
            }
    }
}

// ---------------------------------------------------------------------------
// Fused NT gemms sharing B = f2: corr_1a2 -> scrA, corr_12 -> scrB.
__global__ void __launch_bounds__(256) k_hmma_nt12() {
    extern __shared__ __nv_bfloat16 smem[];
    int ia = blockIdx.x, ib = blockIdx.y, b = blockIdx.z;
    int tid = threadIdx.x, wid = tid >> 5, lane = tid & 31;

    {
        const uint4* src[6] = {
            (const uint4*)(g_viaH + (size_t)b * N * C + (size_t)ia * 128 * C),
            (const uint4*)(g_viaL + (size_t)b * N * C + (size_t)ia * 128 * C),
            (const uint4*)(g_FnH + (size_t)(2 * b) * N * C + (size_t)ia * 128 * C),
            (const uint4*)(g_FnL + (size_t)(2 * b) * N * C + (size_t)ia * 128 * C),
            (const uint4*)(g_FnH + (size_t)(2 * b + 1) * N * C + (size_t)ib * 128 * C),
            (const uint4*)(g_FnL + (size_t)(2 * b + 1) * N * C + (size_t)ib * 128 * C)};
        #pragma unroll
        for (int t6 = 0; t6 < 6; t6++) {
            __nv_bfloat16* dtile = smem + t6 * TSZ;
            #pragma unroll
            for (int i = 0; i < 8; i++) {
                int idx = tid + 256 * i;
                int row = idx >> 4, c8 = idx & 15;
                *(uint4*)(dtile + row * TPAD + c8 * 8) = src[t6][idx];
            }
        }
    }
    __syncthreads();

    int wm = wid & 3, wn = wid >> 2;
    float accA[2][8][4], accB[2][8][4];
    #pragma unroll
    for (int mi = 0; mi < 2; mi++)
        #pragma unroll
        for (int nj = 0; nj < 8; nj++)
            #pragma unroll
            for (int q = 0; q < 4; q++) { accA[mi][nj][q] = 0.f; accB[mi][nj][q] = 0.f; }

    uint32_t sbase = smem_u32(smem);
    int a_r = lane & 15, a_c = (lane >> 4) << 3;
    int b_r = (lane & 7) + ((lane >> 4) << 3);
    int b_c = ((lane >> 3) & 1) << 3;

    #pragma unroll
    for (int k8 = 0; k8 < 8; k8++) {
        int kc = k8 * 16;
        uint32_t bh[4][4], bl[4][4];
        #pragma unroll
        for (int nj = 0; nj < 4; nj++) {
            int row = wn * 64 + nj * 16 + b_r;
            ldm4(bh[nj][0], bh[nj][1], bh[nj][2], bh[nj][3],
                 sbase + (T_BH + row * TPAD + kc + b_c) * 2);
            ldm4(bl[nj][0], bl[nj][1], bl[nj][2], bl[nj][3],
                 sbase + (T_BL + row * TPAD + kc + b_c) * 2);
        }
        #pragma unroll
        for (int out = 0; out < 2; out++) {
            int aH_off = out ? T_F1H : T_VIAH;
            int aL_off = out ? T_F1L : T_VIAL;
            uint32_t ah[2][4], al[2][4];
            #pragma unroll
            for (int mi = 0; mi < 2; mi++) {
                int row = wm * 32 + mi * 16 + a_r;
                ldm4(ah[mi][0], ah[mi][1], ah[mi][2], ah[mi][3],
                     sbase + (aH_off + row * TPAD + kc + a_c) * 2);
                ldm4(al[mi][0], al[mi][1], al[mi][2], al[mi][3],
                     sbase + (aL_off + row * TPAD + kc + a_c) * 2);
            }
            float (*acc)[8][4] = out ? accB : accA;
            #pragma unroll
            for (int mi = 0; mi < 2; mi++)
                #pragma unroll
                for (int nj = 0; nj < 4; nj++) {
                    mma16816(acc[mi][2 * nj], ah[mi], bh[nj][0], bh[nj][1]);
                    mma16816(acc[mi][2 * nj + 1], ah[mi], bh[nj][2], bh[nj][3]);
                    mma16816(acc[mi][2 * nj], ah[mi], bl[nj][0], bl[nj][1]);
                    mma16816(acc[mi][2 * nj + 1], ah[mi], bl[nj][2], bl[nj][3]);
                    mma16816(acc[mi][2 * nj], al[mi], bh[nj][0], bh[nj][1]);
                    mma16816(acc[mi][2 * nj + 1], al[mi], bh[nj][2], bh[nj][3]);
                }
        }
    }

    {
        int rbase = b * 1024 + ia * 128 + wm * 32 + (lane >> 2);
        int cbase = ib * 128 + wn * 64 + 2 * (lane & 3);
        #pragma unroll
        for (int mi = 0; mi < 2; mi++)
            #pragma unroll
            for (int nj = 0; nj < 8; nj++) {
                size_t o0 = (size_t)(rbase + mi * 16) * 1024 + cbase + nj * 8;
                *(float2*)(g_scrA + o0) = make_float2(accA[mi][nj][0], accA[mi][nj][1]);
                *(float2*)(g_scrA + o0 + 8 * 1024) = make_float2(accA[mi][nj][2], accA[mi][nj][3]);
                *(float2*)(g_scrB + o0) = make_float2(accB[mi][nj][0], accB[mi][nj][1]);
                *(float2*)(g_scrB + o0 + 8 * 1024) = make_float2(accB[mi][nj][2], accB[mi][nj][3]);
            }
    }
}

// ---------------------------------------------------------------------------
// row softmax of corr_1a (fp32 in scrA) -> bf16 hi/lo smcorr
__global__ void __launch_bounds__(256) k_rowsoftmax() {
    size_t row = blockIdx.x;
    const float4* p = (const float4*)(g_scrA + row * N);
    int tid = threadIdx.x, lane = tid & 31;
    float4 v = p[tid];
    float mx = fmaxf(fmaxf(v.x, v.y), fmaxf(v.z, v.w));
    #pragma unroll
    for (int o = 16; o; o >>= 1) mx = fmaxf(mx, __shfl_xor_sync(0xffffffffu, mx, o));
    __shared__ float shm[8], shs[8];
    if (lane == 0) shm[tid >> 5] = mx;
    __syncthreads();
    mx = fmaxf(fmaxf(fmaxf(shm[0], shm[1]), fmaxf(shm[2], shm[3])),
               fmaxf(fmaxf(shm[4], shm[5]), fmaxf(shm[6], shm[7])));
    float4 e;
    e.x = fex2((v.x - mx) * LOG2E);
    e.y = fex2((v.y - mx) * LOG2E);
    e.z = fex2((v.z - mx) * LOG2E);
    e.w = fex2((v.w - mx) * LOG2E);
    float s = e.x + e.y + e.z + e.w;
    #pragma unroll
    for (int o = 16; o; o >>= 1) s += __shfl_xor_sync(0xffffffffu, s, o);
    if (lane == 0) shs[tid >> 5] = s;
    __syncthreads();
    s = shs[0] + shs[1] + shs[2] + shs[3] + shs[4] + shs[5] + shs[6] + shs[7];
    float inv = 1.0f / s;
    float f[4] = {e.x * inv, e.y * inv, e.z * inv, e.w * inv};
    __nv_bfloat16 h[4], l[4];
    #pragma unroll
    for (int q = 0; q < 4; q++) hilo(f[q], h[q], l[q]);
    __nv_bfloat162* dH = (__nv_bfloat162*)(g_smH + row * N + 4 * tid);
    __nv_bfloat162* dL = (__nv_bfloat162*)(g_smL + row * N + 4 * tid);
    dH[0] = __nv_bfloat162{h[0], h[1]};
    dH[1] = __nv_bfloat162{h[2], h[3]};
    dL[0] = __nv_bfloat162{l[0], l[1]};
    dL[1] = __nv_bfloat162{l[2], l[3]};
}

// ---------------------------------------------------------------------------
// HMMA NN gemm, K-split x4: via partial[ks] = smcorr[:, ks*256:+256] @ fa chunk
// grid (16 rb, 4 ks, 8 b) = 512 CTAs; fp32 partials to g_viaP.
__global__ void __launch_bounds__(256) k_hmma_nn() {
    extern __shared__ __nv_bfloat16 smem[];
    int rb = blockIdx.x, ks = blockIdx.y, b = blockIdx.z;
    int tid = threadIdx.x, wid = tid >> 5, lane = tid & 31;
    int fs = 2 * ((b + 1) & 7);

    int wm = wid & 1, wn = wid >> 1;
    float acc[2][4][4];
    #pragma unroll
    for (int mi = 0; mi < 2; mi++)
        #pragma unroll
        for (int nj = 0; nj < 4; nj++)
            #pragma unroll
            for (int q = 0; q < 4; q++) acc[mi][nj][q] = 0.f;

    uint32_t sbase = smem_u32(smem);
    const int AOFF[3] = {AH_O, AH_O, AL_O};
    const int VOFF[3] = {VH_O, VL_O, VH_O};
    int a_r = lane & 15, a_c = (lane >> 4) << 3;
    int bt_r = (lane & 7) + (((lane >> 3) & 1) << 3);
    int bt_c = (lane >> 4) << 3;

    for (int kc = 0; kc < 4; kc++) {
        int kb = ks * 256 + kc * 64;
        if (kc) __syncthreads();
        #pragma unroll
        for (int i = 0; i < 2; i++) {
            int idx = tid + 256 * i;
            int r = idx >> 3, c8 = idx & 7;
            size_t so = (size_t)(b * 1024 + rb * 64 + r) * 1024 + kb + c8 * 8;
            *(uint4*)(smem + AH_O + r * APAD + c8 * 8) = *(const uint4*)(g_smH + so);
            *(uint4*)(smem + AL_O + r * APAD + c8 * 8) = *(const uint4*)(g_smL + so);
        }
        #pragma unroll
        for (int i = 0; i < 4; i++) {
            int idx = tid + 256 * i;
            int r = idx >> 4, c8 = idx & 15;
            size_t so = (size_t)(fs * 1024 + kb + r) * 128 + c8 * 8;
            *(uint4*)(smem + VH_O + r * VPAD + c8 * 8) = *(const uint4*)(g_FnH + so);
            *(uint4*)(smem + VL_O + r * VPAD + c8 * 8) = *(const uint4*)(g_FnL + so);
        }
        __syncthreads();

        #pragma unroll
        for (int t = 0; t < 3; t++) {
            #pragma unroll
            for (int k16 = 0; k16 < 4; k16++) {
                int kk = k16 * 16;
                uint32_t af[2][4];
                #pragma unroll
                for (int mi = 0; mi < 2; mi++) {
                    int row = wm * 32 + mi * 16 + a_r;
                    ldm4(af[mi][0], af[mi][1], af[mi][2], af[mi][3],
                         sbase + (AOFF[t] + row * APAD + kk + a_c) * 2);
                }
                uint32_t bf[2][4];
                #pragma unroll
                for (int nj = 0; nj < 2; nj++) {
                    int krow = kk + bt_r;
                    int ccol = wn * 32 + nj * 16 + bt_c;
                    ldm4t(bf[nj][0], bf[nj][1], bf[nj][2], bf[nj][3],
                          sbase + (VOFF[t] + krow * VPAD + ccol) * 2);
                }
                #pragma unroll
                for (int mi = 0; mi < 2; mi++)
                    #pragma unroll
                    for (int nj = 0; nj < 2; nj++) {
                        mma16816(acc[mi][2 * nj], af[mi], bf[nj][0], bf[nj][1]);
                        mma16816(acc[mi][2 * nj + 1], af[mi], bf[nj][2], bf[nj][3]);
                    }
            }
        }
    }

    {
        float* dst = g_viaP[ks];
        int rbase = b * 1024 + rb * 64 + wm * 32 + (lane >> 2);
        int cbase = wn * 32 + 2 * (lane & 3);
        #pragma unroll
        for (int mi = 0; mi < 2; mi++)
            #pragma unroll
            for (int nj = 0; nj < 4; nj++) {
                #pragma unroll
                for (int half = 0; half < 2; half++) {
                    int row = rbase + mi * 16 + half * 8;
                    int col = cbase + nj * 8;
                    *(float2*)(dst + (size_t)row * C + col) =
                        make_float2(acc[mi][nj][2 * half], acc[mi][nj][2 * half + 1]);
                }
            }
    }
}

// combine the 4 K-split partials -> bf16 hi/lo via
__global__ void __launch_bounds__(256) k_via_combine() {
    int idx = blockIdx.x * 256 + threadIdx.x;   // 0 .. B*N*C-1
    float s = (g_viaP[0][idx] + g_viaP[1][idx]) + (g_viaP[2][idx] + g_viaP[3][idx]);
    __nv_bfloat16 h, l;
    hilo(s, h, l);
    g_viaH[idx] = h;
    g_viaL[idx] = l;
}

// ---------------------------------------------------------------------------
__device__ __forceinline__ void batch_bar(int b, unsigned target) {
    __syncthreads();
    if (threadIdx.x == 0) {
        unsigned v;
        asm volatile("red.release.gpu.add.u32 [%0], %1;"
                     :: "l"(&g_bar[b]), "r"(1u) : "memory");
        do {
            asm volatile("ld.acquire.gpu.u32 %0, [%1];"
                         : "=r"(v) : "l"(&g_bar[b]) : "memory");
        } while (v < target);
    }
    __syncthreads();
}

// ---------------------------------------------------------------------------
__device__ void stats_work(int sbid) {
    int tid = threadIdx.x, wid = tid >> 5, lane = tid & 31;
    int w = sbid * 16 + wid;
    for (int row = w; row < B * N; row += STATS_BLKS * 16) {
        const float* pA = g_scrA + (size_t)row * N;
        const float* pB = g_scrB + (size_t)row * N;
        float vv[32];
        #pragma unroll
        for (int j = 0; j < 8; j++) {
            float4 f = *(const float4*)(pA + lane * 4 + 128 * j);
            vv[4 * j] = f.x; vv[4 * j + 1] = f.y; vv[4 * j + 2] = f.z; vv[4 * j + 3] = f.w;
        }
        float mx = -1e30f; int arg = 0;
        #pragma unroll
        for (int j = 0; j < 32; j++) {
            int idx = lane * 4 + 128 * (j >> 2) + (j & 3);
            if (vv[j] > mx) { mx = vv[j]; arg = idx; }
        }
        #pragma unroll
        for (int o = 16; o; o >>= 1) {
            float m2 = __shfl_xor_sync(0xffffffffu, mx, o);
            int a2 = __shfl_xor_sync(0xffffffffu, arg, o);
            if (m2 > mx || (m2 == mx && a2 < arg)) { mx = m2; arg = a2; }
        }
        float s = 0.f;
        #pragma unroll
        for (int j = 0; j < 32; j++) s += fex2((vv[j] - mx) * LOG2E);
        #pragma unroll
        for (int o = 16; o; o >>= 1) s += __shfl_xor_sync(0xffffffffu, s, o);
        if (lane == 0) {
            g_maxA[row] = mx; g_sumA[row] = s;
            if (arg == (row & 1023)) atomicAdd(&g_correct, 1);
        }
        #pragma unroll
        for (int j = 0; j < 8; j++) {
            float4 f = *(const float4*)(pB + lane * 4 + 128 * j);
            vv[4 * j] = f.x; vv[4 * j + 1] = f.y; vv[4 * j + 2] = f.z; vv[4 * j + 3] = f.w;
        }
        mx = -1e30f;
        #pragma unroll
        for (int j = 0; j < 32; j++) mx = fmaxf(mx, vv[j]);
        #pragma unroll
        for (int o = 16; o; o >>= 1) mx = fmaxf(mx, __shfl_xor_sync(0xffffffffu, mx, o));
        s = 0.f;
        #pragma unroll
        for (int j = 0; j < 32; j++) s += fex2((vv[j] - mx) * LOG2E);
        #pragma unroll
        for (int o = 16; o; o >>= 1) s += __shfl_xor_sync(0xffffffffu, s, o);
        if (lane == 0) { g_maxB[row] = mx; g_sumB[row] = s; }
    }
}

// persistent sinkhorn, warp-autonomous rows; c register-resident per lane
__global__ void __launch_bounds__(512) k_sinkhorn() {
    if (blockIdx.x >= B * SNB) { stats_work(blockIdx.x - B * SNB); return; }
    extern __shared__ float dsm[];
    float* sc = dsm;
    float* sq = dsm + 1024;
    int b = blockIdx.x >> 4, sub = blockIdx.x & 15;
    const float* Mblk = g_scrA + (size_t)(b * 1024 + sub * 64) * N;
    int tid = threadIdx.x, warp = tid >> 5, lane = tid & 31;
    sc[tid] = 0.f;
    sc[tid + 512] = 0.f;
    __syncthreads();

    float rprev[4];
    unsigned bar_t = 0;

    for (int it = 0; it < 30; it++) {
        int par = it & 1;
        float2 cc[16];
        #pragma unroll
        for (int j = 0; j < 16; j++) cc[j] = *(float2*)&sc[2 * lane + 64 * j];
        float2 q[16];
        #pragma unroll
        for (int j = 0; j < 16; j++) q[j] = make_float2(0.f, 0.f);

        #pragma unroll
        for (int ri = 0; ri < 4; ri++) {
            const float2* rowp = (const float2*)(Mblk + (size_t)(warp * 4 + ri) * N);
            float2 e[16];
            float lg;
            if (it == 0) {
                float m = -1e30f;
                #pragma unroll
                for (int j = 0; j < 16; j++) {
                    float2 y = rowp[lane + 32 * j];
                    e[j].x = fmaf(y.x, K2, cc[j].x);
                    e[j].y = fmaf(y.y, K2, cc[j].y);
                    m = fmaxf(m, fmaxf(e[j].x, e[j].y));
                }
                #pragma unroll
                for (int o = 16; o; o >>= 1)
                    m = fmaxf(m, __shfl_xor_sync(0xffffffffu, m, o));
                float s = 0.f;
                #pragma unroll
                for (int j = 0; j < 16; j++) {
                    e[j].x = fex2(e[j].x - m);
                    e[j].y = fex2(e[j].y - m);
                    s += e[j].x + e[j].y;
                }
                #pragma unroll
                for (int o = 16; o; o >>= 1) s += __shfl_xor_sync(0xffffffffu, s, o);
                lg = flg2(s);
                rprev[ri] = -(m + lg);
            } else {
                float rp = rprev[ri];
                float s = 0.f;
                #pragma unroll
                for (int j = 0; j < 16; j++) {
                    float2 y = rowp[lane + 32 * j];
                    e[j].x = fex2(fmaf(y.x, K2, cc[j].x) + rp);
                    e[j].y = fex2(fmaf(y.y, K2, cc[j].y) + rp);
                    s += e[j].x + e[j].y;
                }
                #pragma unroll
                for (int o = 16; o; o >>= 1) s += __shfl_xor_sync(0xffffffffu, s, o);
                lg = flg2(fmaxf(s, 1e-30f));
                rprev[ri] = rp - lg;
            }
            float is = fex2(-lg);
            #pragma unroll
            for (int j = 0; j < 16; j++) {
                q[j].x = fmaf(e[j].x, is, q[j].x);
                q[j].y = fmaf(e[j].y, is, q[j].y);
            }
        }

        #pragma unroll
        for (int j = 0; j < 16; j++)
            *(float2*)&sq[warp * 1024 + 2 * lane + 64 * j] = q[j];
        __syncthreads();
        float s0 = 0.f, s1 = 0.f;
        #pragma unroll
        for (int k = 0; k < 16; k++) {
            float2 t2 = *(float2*)&sq[k * 1024 + 2 * tid];
            s0 += t2.x; s1 += t2.y;
        }
        float* cp = g_cpf + (size_t)par * (B * SNB * N) + (size_t)(b * 16 + sub) * N;
        *(float2*)&cp[2 * tid] = make_float2(s0, s1);
        bar_t += SNB; batch_bar(b, bar_t);

        const float* base = g_cpf + (size_t)par * (B * SNB * N) + (size_t)b * 16 * N;
        #pragma unroll
        for (int h = 0; h < 2; h++) {
            int col = tid + 512 * h;
            float s = 0.f;
            #pragma unroll
            for (int k = 0; k < 16; k++) s += base[(size_t)k * N + col];
            sc[col] = sc[col] - flg2(fmaxf(s, 1e-30f));
        }
        __syncthreads();
    }

    if (lane == 0) {
        #pragma unroll
        for (int ri = 0; ri < 4; ri++)
            g_r[b * N + sub * 64 + warp * 4 + ri] = rprev[ri];
    }
    if (tid < 64) g_c[b * N + sub * 64 + tid] = sc[sub * 64 + tid];
}

// ---------------------------------------------------------------------------
// fused final pass: 4 rows per block
__global__ void __launch_bounds__(256) k_final(const float* __restrict__ pc0) {
    int quad = blockIdx.x;
    int b = quad >> 8;
    int n0 = (quad & 255) * 4;
    int tid = threadIdx.x, lane = tid & 31, warp = tid >> 5;

    __shared__ float spc[3 * 1024];
    __shared__ float scv[1024];
    __shared__ float s1[8], s2[8], s3[8];
    const float* pc = pc0 + (size_t)b * N * 3;
    for (int i = tid; i < 3 * 1024; i += 256) spc[i] = pc[i];
    for (int i = tid; i < 1024; i += 256) scv[i] = g_c[b * N + i];
    __syncthreads();

    #pragma unroll
    for (int rr = 0; rr < 4; rr++) {
        int n = n0 + rr;
        size_t row = (size_t)b * N + n;
        const float* pA = g_scrA + row * N;
        const float* pB = g_scrB + row * N;
        float mA = g_maxA[row], iA = 1.0f / g_sumA[row];
        float mB = g_maxB[row], iB = 1.0f / g_sumB[row];
        float rn = g_r[row];
        float px = spc[3 * n], py = spc[3 * n + 1], pz = spc[3 * n + 2];
        float aL = 0.f, aC = 0.f, aP = 0.f;
        #pragma unroll
        for (int t = 0; t < 4; t++) {
            int m = tid + 256 * t;
            float xA = pA[m], xB = pB[m];
            float smA = fex2((xA - mA) * LOG2E) * iA;
            float smB = fex2((xB - mB) * LOG2E) * iB;
            float dx = px - spc[3 * m], dy = py - spc[3 * m + 1], dz = pz - spc[3 * m + 2];
            float d2 = dx * dx + dy * dy + dz * dz;
            float dist = sqrtf(sqrtf(d2));
            aL += dist * (smA + smB);
            float sink = fex2(xA * K2 + rn + scv[m]);
            aC += fabsf(sink - smA);
            aP += (m == n) ? fabsf(1.0f - sink) : sink;
        }
        #pragma unroll
        for (int o = 16; o; o >>= 1) {
            aL += __shfl_xor_sync(0xffffffffu, aL, o);
            aC += __shfl_xor_sync(0xffffffffu, aC, o);
            aP += __shfl_xor_sync(0xffffffffu, aP, o);
        }
        if (lane == 0) { s1[warp] = aL; s2[warp] = aC; s3[warp] = aP; }
        __syncthreads();
        if (tid == 0) {
            float tL = 0.f, tC = 0.f, tP = 0.f;
            #pragma unroll
            for (int q = 0; q < 8; q++) { tL += s1[q]; tC += s2[q]; tP += s3[q]; }
            g_pL[row] = tL; g_pC[row] = tC; g_pP[row] = tP;
        }
        __syncthreads();
    }
}

// ---------------------------------------------------------------------------
__global__ void __launch_bounds__(256) k_out(float* __restrict__ out) {
    int tid = threadIdx.x;
    float sL = 0.f, sC = 0.f, sP = 0.f;
    for (int i = tid; i < B * N; i += 256) {
        sL += g_pL[i]; sC += g_pC[i]; sP += g_pP[i];
    }
    #pragma unroll
    for (int o = 16; o; o >>= 1) {
        sL += __shfl_xor_sync(0xffffffffu, sL, o);
        sC += __shfl_xor_sync(0xffffffffu, sC, o);
        sP += __shfl_xor_sync(0xffffffffu, sP, o);
    }
    __shared__ float s1[8], s2[8], s3[8];
    if ((tid & 31) == 0) { s1[tid >> 5] = sL; s2[tid >> 5] = sC; s3[tid >> 5] = sP; }
    __syncthreads();
    if (tid == 0) {
        float tL = 0.f, tC = 0.f, tP = 0.f;
        #pragma unroll
        for (int q = 0; q < 8; q++) { tL += s1[q]; tC += s2[q]; tP += s3[q]; }
        float invN = 1.0f / (float)N;
        float loss = tL * invN;
        float Lc = 3.0f * tC * invN;
        float perm = 3.0f * tP * invN;
        float corr = (float)g_correct;
        float invB = 1.0f / (float)B;
        out[0] = (loss + Lc) * invB;
        out[1] = loss * invB;
        out[2] = Lc * invB;
        out[3] = corr * invB;
        out[4] = perm * invB;
    }
}

// ---------------------------------------------------------------------------
extern "C" void kernel_launch(void* const* d_in, const int* in_sizes, int n_in,
                              void* d_out, int out_size) {
    const float* feats = (const float*)d_in[0];
    const float* pc0 = (const float*)d_in[1];
    float* out = (float*)d_out;

    const int nt_smem = 4 * TSZ * sizeof(__nv_bfloat16);
    const int nt12_smem = 6 * TSZ * sizeof(__nv_bfloat16);
    const int nn_smem = NN_ELEMS * sizeof(__nv_bfloat16);
    static bool attr_done = false;
    if (!attr_done) {
        cudaFuncSetAttribute(k_hmma_nt0, cudaFuncAttributeMaxDynamicSharedMemorySize,
                             nt_smem);
        cudaFuncSetAttribute(k_hmma_nt12, cudaFuncAttributeMaxDynamicSharedMemorySize,
                             nt12_smem);
        cudaFuncSetAttribute(k_hmma_nn, cudaFuncAttributeMaxDynamicSharedMemorySize,
                             nn_smem);
        cudaFuncSetAttribute(k_sinkhorn, cudaFuncAttributeMaxDynamicSharedMemorySize,
                             SINK_SMEM);
        attr_done = true;
    }

    k_norm<<<2 * B * N, 128>>>(feats);                  // + state reset
    k_hmma_nt0<<<dim3(8, 8, 8), 256, nt_smem>>>();      // corr_1a -> scrA
    k_rowsoftmax<<<B * N, 256>>>();                     // smcorr hi/lo bf16
    k_hmma_nn<<<dim3(16, 4, 8), 256, nn_smem>>>();      // via partials (512 CTAs)
    k_via_combine<<<B * N * C / 256, 256>>>();          // partials -> hi/lo
    k_hmma_nt12<<<dim3(8, 8, 8), 256, nt12_smem>>>();   // corr_1a2 + corr_12 fused
    k_sinkhorn<<<B * SNB + STATS_BLKS, 512, SINK_SMEM>>>();
    k_final<<<B * N / 4, 256>>>(pc0);
    k_out<<<1, 256>>>(out);
}

// round 17
// speedup vs baseline: 1.7553x; 1.0070x over previous
#include <cuda_runtime.h>
#include <cuda_bf16.h>
#include <cstdint>

namespace {
constexpr int B = 8;
constexpr int N = 1024;
constexpr int C = 128;
constexpr float SCALEF = 20.0f;
constexpr float EPSF = 1e-12f;
constexpr float LOG2E = 1.4426950408889634f;
constexpr float K2 = 4.808983469629878f;   // log2(e)/0.3
constexpr int SNB = 16;                    // sinkhorn blocks per batch
constexpr int STATS_BLKS = 20;             // extra stats blocks
constexpr int TPAD = 136;
constexpr int TSZ = 128 * TPAD;
constexpr int APAD = 72;
constexpr int VPAD = 136;
// NN smem (64-row A tiles), double buffered
constexpr int AH_O = 0;
constexpr int AL_O = 64 * APAD;
constexpr int VH_O = 2 * 64 * APAD;
constexpr int VL_O = VH_O + 64 * VPAD;
constexpr int NN_ELEMS = VL_O + 64 * VPAD;     // 26624 elems / buffer
constexpr int SINK_SMEM = (1024 + 16 * 1024) * 4;
// nt12 K-chunked tiles: 6 tiles of 128 x 72 (64 cols + pad)
constexpr int CPAD = 72;
constexpr int CTSZ = 128 * CPAD;               // 9216 elems per tile
constexpr int T_VIAH = 0;
constexpr int T_VIAL = CTSZ;
constexpr int T_F1H = 2 * CTSZ;
constexpr int T_F1L = 3 * CTSZ;
constexpr int T_BH = 4 * CTSZ;
constexpr int T_BL = 5 * CTSZ;
constexpr int NT12_ELEMS = 6 * CTSZ;           // 55296 elems = 110592 B
}

__device__ float g_scrA[(size_t)B * N * N];
__device__ float g_scrB[(size_t)B * N * N];
__device__ __nv_bfloat16 g_FnH[2 * B * N * C];
__device__ __nv_bfloat16 g_FnL[2 * B * N * C];
__device__ __nv_bfloat16 g_viaH[B * N * C];
__device__ __nv_bfloat16 g_viaL[B * N * C];
__device__ float g_viaP[4][B * N * C];
__device__ __nv_bfloat16 g_smH[(size_t)B * N * N];
__device__ __nv_bfloat16 g_smL[(size_t)B * N * N];
__device__ float g_cpf[2 * B * SNB * N];
__device__ float g_r[B * N];
__device__ float g_c[B * N];
__device__ float g_maxA[B * N], g_sumA[B * N];
__device__ float g_maxB[B * N], g_sumB[B * N];
__device__ unsigned g_bar[B];
__device__ int g_correct;
__device__ float g_pL[B * N], g_pC[B * N], g_pP[B * N];

__device__ __forceinline__ float fex2(float x) {
    float y; asm("ex2.approx.ftz.f32 %0, %1;" : "=f"(y) : "f"(x)); return y;
}
__device__ __forceinline__ float flg2(float x) {
    float y; asm("lg2.approx.ftz.f32 %0, %1;" : "=f"(y) : "f"(x)); return y;
}
__device__ __forceinline__ uint32_t smem_u32(const void* p) {
    uint32_t a;
    asm("{ .reg .u64 t; cvta.to.shared.u64 t, %1; cvt.u32.u64 %0, t; }"
        : "=r"(a) : "l"(p));
    return a;
}
__device__ __forceinline__ void cpa16(uint32_t saddr, const void* g) {
    asm volatile("cp.async.cg.shared.global [%0], [%1], 16;"
                 :: "r"(saddr), "l"(g) : "memory");
}
__device__ __forceinline__ void cpa_commit() {
    asm volatile("cp.async.commit_group;" ::: "memory");
}
template <int Nw>
__device__ __forceinline__ void cpa_wait() {
    asm volatile("cp.async.wait_group %0;" :: "n"(Nw) : "memory");
}
__device__ __forceinline__ void ldm4(uint32_t& r0, uint32_t& r1, uint32_t& r2,
                                     uint32_t& r3, uint32_t addr) {
    asm volatile("ldmatrix.sync.aligned.m8n8.x4.shared.b16 {%0,%1,%2,%3}, [%4];"
                 : "=r"(r0), "=r"(r1), "=r"(r2), "=r"(r3) : "r"(addr));
}
__device__ __forceinline__ void ldm4t(uint32_t& r0, uint32_t& r1, uint32_t& r2,
                                      uint32_t& r3, uint32_t addr) {
    asm volatile("ldmatrix.sync.aligned.m8n8.x4.trans.shared.b16 {%0,%1,%2,%3}, [%4];"
                 : "=r"(r0), "=r"(r1), "=r"(r2), "=r"(r3) : "r"(addr));
}
__device__ __forceinline__ void mma16816(float* c, const uint32_t* a,
                                         uint32_t b0, uint32_t b1) {
    asm volatile(
        "mma.sync.aligned.m16n8k16.row.col.f32.bf16.bf16.f32 "
        "{%0,%1,%2,%3}, {%4,%5,%6,%7}, {%8,%9}, {%0,%1,%2,%3};"
        : "+f"(c[0]), "+f"(c[1]), "+f"(c[2]), "+f"(c[3])
        : "r"(a[0]), "r"(a[1]), "r"(a[2]), "r"(a[3]), "r"(b0), "r"(b1));
}
__device__ __forceinline__ void hilo(float v, __nv_bfloat16& h, __nv_bfloat16& l) {
    h = __float2bfloat16(v);
    l = __float2bfloat16(v - __bfloat162float(h));
}

// ---------------------------------------------------------------------------
__global__ void __launch_bounds__(128) k_norm(const float* __restrict__ feats) {
    if (blockIdx.x == 0 && threadIdx.x < 32) {
        if (threadIdx.x < B) g_bar[threadIdx.x] = 0u;
        if (threadIdx.x == 0) g_correct = 0;
    }
    int row = blockIdx.x;
    const float* p = feats + (size_t)row * C;
    float v = p[threadIdx.x];
    float s = v * v;
    #pragma unroll
    for (int o = 16; o; o >>= 1) s += __shfl_xor_sync(0xffffffffu, s, o);
    __shared__ float sh[4];
    if ((threadIdx.x & 31) == 0) sh[threadIdx.x >> 5] = s;
    __syncthreads();
    s = sh[0] + sh[1] + sh[2] + sh[3];
    float scl = SCALEF / fmaxf(sqrtf(s), EPSF);
    float val = v * scl;
    size_t idx = (size_t)row * C + threadIdx.x;
    __nv_bfloat16 h, l;
    hilo(val, h, l);
    g_FnH[idx] = h;
    g_FnL[idx] = l;
}

// ---------------------------------------------------------------------------
// HMMA NT gemm for corr_1a only (f1 @ fa^T), bf16-split 3 terms.
__global__ void __launch_bounds__(256) k_hmma_nt0() {
    extern __shared__ __nv_bfloat16 smem[];
    int ia = blockIdx.x, ib = blockIdx.y, b = blockIdx.z;
    int tid = threadIdx.x, wid = tid >> 5, lane = tid & 31;

    const __nv_bfloat16* aHg = g_FnH + (size_t)(2 * b) * N * C + (size_t)ia * 128 * C;
    const __nv_bfloat16* aLg = g_FnL + (size_t)(2 * b) * N * C + (size_t)ia * 128 * C;
    int fsB = 2 * ((b + 1) & 7);
    const __nv_bfloat16* bHg = g_FnH + (size_t)fsB * N * C + (size_t)ib * 128 * C;
    const __nv_bfloat16* bLg = g_FnL + (size_t)fsB * N * C + (size_t)ib * 128 * C;

    {
        const uint4* src[4] = {(const uint4*)aHg, (const uint4*)aLg,
                               (const uint4*)bHg, (const uint4*)bLg};
        #pragma unroll
        for (int t4 = 0; t4 < 4; t4++) {
            __nv_bfloat16* dtile = smem + t4 * TSZ;
            #pragma unroll
            for (int i = 0; i < 8; i++) {
                int idx = tid + 256 * i;
                int row = idx >> 4, c8 = idx & 15;
                *(uint4*)(dtile + row * TPAD + c8 * 8) = src[t4][idx];
            }
        }
    }
    __syncthreads();

    int wm = wid & 3, wn = wid >> 2;
    float acc[2][8][4];
    #pragma unroll
    for (int mi = 0; mi < 2; mi++)
        #pragma unroll
        for (int nj = 0; nj < 8; nj++)
            #pragma unroll
            for (int q = 0; q < 4; q++) acc[mi][nj][q] = 0.f;

    uint32_t sbase = smem_u32(smem);
    const int selA[3] = {0, 0, 1};
    const int selB[3] = {2, 3, 2};
    int a_r = lane & 15, a_c = (lane >> 4) << 3;
    int b_r = (lane & 7) + ((lane >> 4) << 3);
    int b_c = ((lane >> 3) & 1) << 3;

    #pragma unroll
    for (int t = 0; t < 3; t++) {
        uint32_t aB = sbase + selA[t] * TSZ * 2;
        uint32_t bBs = sbase + selB[t] * TSZ * 2;
        #pragma unroll
        for (int k8 = 0; k8 < 8; k8++) {
            int kc = k8 * 16;
            uint32_t af[2][4];
            #pragma unroll
            for (int mi = 0; mi < 2; mi++) {
                int row = wm * 32 + mi * 16 + a_r;
                ldm4(af[mi][0], af[mi][1], af[mi][2], af[mi][3],
                     aB + (row * TPAD + kc + a_c) * 2);
            }
            uint32_t bf[4][4];
            #pragma unroll
            for (int nj = 0; nj < 4; nj++) {
                int row = wn * 64 + nj * 16 + b_r;
                ldm4(bf[nj][0], bf[nj][1], bf[nj][2], bf[nj][3],
                     bBs + (row * TPAD + kc + b_c) * 2);
            }
            #pragma unroll
            for (int mi = 0; mi < 2; mi++)
                #pragma unroll
                for (int nj = 0; nj < 4; nj++) {
                    mma16816(acc[mi][2 * nj], af[mi], bf[nj][0], bf[nj][1]);
                    mma16816(acc[mi][2 * nj + 1], af[mi], bf[nj][2], bf[nj][3]);
                }
        }
    }

    {
        int rbase = b * 1024 + ia * 128 + wm * 32 + (lane >> 2);
        int cbase = ib * 128 + wn * 64 + 2 * (lane & 3);
        #pragma unroll
        for (int mi = 0; mi < 2; mi++)
            #pragma unroll
            for (int nj = 0; nj < 8; nj++) {
                float* d0 = g_scrA + (size_t)(rbase + mi * 16) * 1024 + cbase + nj * 8;
                *(float2*)d0 = make_float2(acc[mi][nj][0], acc[mi][nj][1]);
                float* d1 = d0 + 8 * 1024;
                *(float2*)d1 = make_float2(acc[mi][nj][2], acc[mi][nj][3]);
            }
    }
}

// ---------------------------------------------------------------------------
// Fused NT gemms sharing B = f2, K-chunked (2 x 64) for 2 CTAs/SM:
// corr_1a2 = via@f2^T -> scrA, corr_12 = f1@f2^T -> scrB.
__global__ void __launch_bounds__(256) k_hmma_nt12() {
    extern __shared__ __nv_bfloat16 smem[];
    int ia = blockIdx.x, ib = blockIdx.y, b = blockIdx.z;
    int tid = threadIdx.x, wid = tid >> 5, lane = tid & 31;

    int wm = wid & 3, wn = wid >> 2;
    float accA[2][8][4], accB[2][8][4];
    #pragma unroll
    for (int mi = 0; mi < 2; mi++)
        #pragma unroll
        for (int nj = 0; nj < 8; nj++)
            #pragma unroll
            for (int q = 0; q < 4; q++) { accA[mi][nj][q] = 0.f; accB[mi][nj][q] = 0.f; }

    uint32_t sbase = smem_u32(smem);
    int a_r = lane & 15, a_c = (lane >> 4) << 3;
    int b_r = (lane & 7) + ((lane >> 4) << 3);
    int b_c = ((lane >> 3) & 1) << 3;

    const __nv_bfloat16* srcs[6] = {
        g_viaH + (size_t)b * N * C + (size_t)ia * 128 * C,
        g_viaL + (size_t)b * N * C + (size_t)ia * 128 * C,
        g_FnH + (size_t)(2 * b) * N * C + (size_t)ia * 128 * C,
        g_FnL + (size_t)(2 * b) * N * C + (size_t)ia * 128 * C,
        g_FnH + (size_t)(2 * b + 1) * N * C + (size_t)ib * 128 * C,
        g_FnL + (size_t)(2 * b + 1) * N * C + (size_t)ib * 128 * C};

    for (int ch = 0; ch < 2; ch++) {
        if (ch) __syncthreads();
        // load chunk: 6 tiles x 128 rows x 64 cols (8 uint4/row)
        #pragma unroll
        for (int t6 = 0; t6 < 6; t6++) {
            __nv_bfloat16* dtile = smem + t6 * CTSZ;
            const __nv_bfloat16* g = srcs[t6] + ch * 64;
            #pragma unroll
            for (int i = 0; i < 4; i++) {
                int idx = tid + 256 * i;       // 0..1023
                int row = idx >> 3, c8 = idx & 7;
                *(uint4*)(dtile + row * CPAD + c8 * 8) =
                    *(const uint4*)(g + (size_t)row * C + c8 * 8);
            }
        }
        __syncthreads();

        #pragma unroll
        for (int k8 = 0; k8 < 4; k8++) {
            int kc = k8 * 16;
            uint32_t bh[4][4], bl[4][4];
            #pragma unroll
            for (int nj = 0; nj < 4; nj++) {
                int row = wn * 64 + nj * 16 + b_r;
                ldm4(bh[nj][0], bh[nj][1], bh[nj][2], bh[nj][3],
                     sbase + (T_BH + row * CPAD + kc + b_c) * 2);
                ldm4(bl[nj][0], bl[nj][1], bl[nj][2], bl[nj][3],
                     sbase + (T_BL + row * CPAD + kc + b_c) * 2);
            }
            #pragma unroll
            for (int out = 0; out < 2; out++) {
                int aH_off = out ? T_F1H : T_VIAH;
                int aL_off = out ? T_F1L : T_VIAL;
                uint32_t ah[2][4], al[2][4];
                #pragma unroll
                for (int mi = 0; mi < 2; mi++) {
                    int row = wm * 32 + mi * 16 + a_r;
                    ldm4(ah[mi][0], ah[mi][1], ah[mi][2], ah[mi][3],
                         sbase + (aH_off + row * CPAD + kc + a_c) * 2);
                    ldm4(al[mi][0], al[mi][1], al[mi][2], al[mi][3],
                         sbase + (aL_off + row * CPAD + kc + a_c) * 2);
                }
                float (*acc)[8][4] = out ? accB : accA;
                #pragma unroll
                for (int mi = 0; mi < 2; mi++)
                    #pragma unroll
                    for (int nj = 0; nj < 4; nj++) {
                        mma16816(acc[mi][2 * nj], ah[mi], bh[nj][0], bh[nj][1]);
                        mma16816(acc[mi][2 * nj + 1], ah[mi], bh[nj][2], bh[nj][3]);
                        mma16816(acc[mi][2 * nj], ah[mi], bl[nj][0], bl[nj][1]);
                        mma16816(acc[mi][2 * nj + 1], ah[mi], bl[nj][2], bl[nj][3]);
                        mma16816(acc[mi][2 * nj], al[mi], bh[nj][0], bh[nj][1]);
                        mma16816(acc[mi][2 * nj + 1], al[mi], bh[nj][2], bh[nj][3]);
                    }
            }
        }
    }

    {
        int rbase = b * 1024 + ia * 128 + wm * 32 + (lane >> 2);
        int cbase = ib * 128 + wn * 64 + 2 * (lane & 3);
        #pragma unroll
        for (int mi = 0; mi < 2; mi++)
            #pragma unroll
            for (int nj = 0; nj < 8; nj++) {
                size_t o0 = (size_t)(rbase + mi * 16) * 1024 + cbase + nj * 8;
                *(float2*)(g_scrA + o0) = make_float2(accA[mi][nj][0], accA[mi][nj][1]);
                *(float2*)(g_scrA + o0 + 8 * 1024) = make_float2(accA[mi][nj][2], accA[mi][nj][3]);
                *(float2*)(g_scrB + o0) = make_float2(accB[mi][nj][0], accB[mi][nj][1]);
                *(float2*)(g_scrB + o0 + 8 * 1024) = make_float2(accB[mi][nj][2], accB[mi][nj][3]);
            }
    }
}

// ---------------------------------------------------------------------------
// row softmax of corr_1a (fp32 in scrA) -> bf16 hi/lo smcorr
__global__ void __launch_bounds__(256) k_rowsoftmax() {
    size_t row = blockIdx.x;
    const float4* p = (const float4*)(g_scrA + row * N);
    int tid = threadIdx.x, lane = tid & 31;
    float4 v = p[tid];
    float mx = fmaxf(fmaxf(v.x, v.y), fmaxf(v.z, v.w));
    #pragma unroll
    for (int o = 16; o; o >>= 1) mx = fmaxf(mx, __shfl_xor_sync(0xffffffffu, mx, o));
    __shared__ float shm[8], shs[8];
    if (lane == 0) shm[tid >> 5] = mx;
    __syncthreads();
    mx = fmaxf(fmaxf(fmaxf(shm[0], shm[1]), fmaxf(shm[2], shm[3])),
               fmaxf(fmaxf(shm[4], shm[5]), fmaxf(shm[6], shm[7])));
    float4 e;
    e.x = fex2((v.x - mx) * LOG2E);
    e.y = fex2((v.y - mx) * LOG2E);
    e.z = fex2((v.z - mx) * LOG2E);
    e.w = fex2((v.w - mx) * LOG2E);
    float s = e.x + e.y + e.z + e.w;
    #pragma unroll
    for (int o = 16; o; o >>= 1) s += __shfl_xor_sync(0xffffffffu, s, o);
    if (lane == 0) shs[tid >> 5] = s;
    __syncthreads();
    s = shs[0] + shs[1] + shs[2] + shs[3] + shs[4] + shs[5] + shs[6] + shs[7];
    float inv = 1.0f / s;
    float f[4] = {e.x * inv, e.y * inv, e.z * inv, e.w * inv};
    __nv_bfloat16 h[4], l[4];
    #pragma unroll
    for (int q = 0; q < 4; q++) hilo(f[q], h[q], l[q]);
    __nv_bfloat162* dH = (__nv_bfloat162*)(g_smH + row * N + 4 * tid);
    __nv_bfloat162* dL = (__nv_bfloat162*)(g_smL + row * N + 4 * tid);
    dH[0] = __nv_bfloat162{h[0], h[1]};
    dH[1] = __nv_bfloat162{h[2], h[3]};
    dL[0] = __nv_bfloat162{l[0], l[1]};
    dL[1] = __nv_bfloat162{l[2], l[3]};
}

// ---------------------------------------------------------------------------
// HMMA NN gemm, K-split x4, cp.async double-buffered.
// via partial[ks] = smcorr[:, ks*256:+256] @ fa chunk; fp32 -> g_viaP.
__global__ void __launch_bounds__(256) k_hmma_nn() {
    extern __shared__ __nv_bfloat16 smem[];
    int rb = blockIdx.x, ks = blockIdx.y, b = blockIdx.z;
    int tid = threadIdx.x, wid = tid >> 5, lane = tid & 31;
    int fs = 2 * ((b + 1) & 7);
    uint32_t sbase = smem_u32(smem);

    int wm = wid & 1, wn = wid >> 1;
    float acc[2][4][4];
    #pragma unroll
    for (int mi = 0; mi < 2; mi++)
        #pragma unroll
        for (int nj = 0; nj < 4; nj++)
            #pragma unroll
            for (int q = 0; q < 4; q++) acc[mi][nj][q] = 0.f;

    // issue cp.async loads for chunk kc into buffer buf
    auto issue = [&](int kc, int buf) {
        int kb = ks * 256 + kc * 64;
        uint32_t bb = sbase + (uint32_t)buf * NN_ELEMS * 2;
        #pragma unroll
        for (int i = 0; i < 2; i++) {
            int idx = tid + 256 * i;
            int r = idx >> 3, c8 = idx & 7;
            size_t so = (size_t)(b * 1024 + rb * 64 + r) * 1024 + kb + c8 * 8;
            cpa16(bb + (AH_O + r * APAD + c8 * 8) * 2, g_smH + so);
            cpa16(bb + (AL_O + r * APAD + c8 * 8) * 2, g_smL + so);
        }
        #pragma unroll
        for (int i = 0; i < 4; i++) {
            int idx = tid + 256 * i;
            int r = idx >> 4, c8 = idx & 15;
            size_t so = (size_t)(fs * 1024 + kb + r) * 128 + c8 * 8;
            cpa16(bb + (VH_O + r * VPAD + c8 * 8) * 2, g_FnH + so);
            cpa16(bb + (VL_O + r * VPAD + c8 * 8) * 2, g_FnL + so);
        }
        cpa_commit();
    };

    const int AOFF[3] = {AH_O, AH_O, AL_O};
    const int VOFF[3] = {VH_O, VL_O, VH_O};
    int a_r = lane & 15, a_c = (lane >> 4) << 3;
    int bt_r = (lane & 7) + (((lane >> 3) & 1) << 3);
    int bt_c = (lane >> 4) << 3;

    issue(0, 0);
    for (int kc = 0; kc < 4; kc++) {
        if (kc < 3) issue(kc + 1, (kc + 1) & 1);
        if (kc < 3) cpa_wait<1>(); else cpa_wait<0>();
        __syncthreads();
        uint32_t bb = sbase + (uint32_t)(kc & 1) * NN_ELEMS * 2;

        #pragma unroll
        for (int t = 0; t < 3; t++) {
            #pragma unroll
            for (int k16 = 0; k16 < 4; k16++) {
                int kk = k16 * 16;
                uint32_t af[2][4];
                #pragma unroll
                for (int mi = 0; mi < 2; mi++) {
                    int row = wm * 32 + mi * 16 + a_r;
                    ldm4(af[mi][0], af[mi][1], af[mi][2], af[mi][3],
                         bb + (AOFF[t] + row * APAD + kk + a_c) * 2);
                }
                uint32_t bf[2][4];
                #pragma unroll
                for (int nj = 0; nj < 2; nj++) {
                    int krow = kk + bt_r;
                    int ccol = wn * 32 + nj * 16 + bt_c;
                    ldm4t(bf[nj][0], bf[nj][1], bf[nj][2], bf[nj][3],
                          bb + (VOFF[t] + krow * VPAD + ccol) * 2);
                }
                #pragma unroll
                for (int mi = 0; mi < 2; mi++)
                    #pragma unroll
                    for (int nj = 0; nj < 2; nj++) {
                        mma16816(acc[mi][2 * nj], af[mi], bf[nj][0], bf[nj][1]);
                        mma16816(acc[mi][2 * nj + 1], af[mi], bf[nj][2], bf[nj][3]);
                    }
            }
        }
        __syncthreads();
    }

    {
        float* dst = g_viaP[ks];
        int rbase = b * 1024 + rb * 64 + wm * 32 + (lane >> 2);
        int cbase = wn * 32 + 2 * (lane & 3);
        #pragma unroll
        for (int mi = 0; mi < 2; mi++)
            #pragma unroll
            for (int nj = 0; nj < 4; nj++) {
                #pragma unroll
                for (int half = 0; half < 2; half++) {
                    int row = rbase + mi * 16 + half * 8;
                    int col = cbase + nj * 8;
                    *(float2*)(dst + (size_t)row * C + col) =
                        make_float2(acc[mi][nj][2 * half], acc[mi][nj][2 * half + 1]);
                }
            }
    }
}

// combine the 4 K-split partials -> bf16 hi/lo via
__global__ void __launch_bounds__(256) k_via_combine() {
    int idx = blockIdx.x * 256 + threadIdx.x;
    float s = (g_viaP[0][idx] + g_viaP[1][idx]) + (g_viaP[2][idx] + g_viaP[3][idx]);
    __nv_bfloat16 h, l;
    hilo(s, h, l);
    g_viaH[idx] = h;
    g_viaL[idx] = l;
}

// ---------------------------------------------------------------------------
__device__ __forceinline__ void batch_bar(int b, unsigned target) {
    __syncthreads();
    if (threadIdx.x == 0) {
        unsigned v;
        asm volatile("red.release.gpu.add.u32 [%0], %1;"
                     :: "l"(&g_bar[b]), "r"(1u) : "memory");
        do {
            asm volatile("ld.acquire.gpu.u32 %0, [%1];"
                         : "=r"(v) : "l"(&g_bar[b]) : "memory");
        } while (v < target);
    }
    __syncthreads();
}

// ---------------------------------------------------------------------------
__device__ void stats_work(int sbid) {
    int tid = threadIdx.x, wid = tid >> 5, lane = tid & 31;
    int w = sbid * 16 + wid;
    for (int row = w; row < B * N; row += STATS_BLKS * 16) {
        const float* pA = g_scrA + (size_t)row * N;
        const float* pB = g_scrB + (size_t)row * N;
        float vv[32];
        #pragma unroll
        for (int j = 0; j < 8; j++) {
            float4 f = *(const float4*)(pA + lane * 4 + 128 * j);
            vv[4 * j] = f.x; vv[4 * j + 1] = f.y; vv[4 * j + 2] = f.z; vv[4 * j + 3] = f.w;
        }
        float mx = -1e30f; int arg = 0;
        #pragma unroll
        for (int j = 0; j < 32; j++) {
            int idx = lane * 4 + 128 * (j >> 2) + (j & 3);
            if (vv[j] > mx) { mx = vv[j]; arg = idx; }
        }
        #pragma unroll
        for (int o = 16; o; o >>= 1) {
            float m2 = __shfl_xor_sync(0xffffffffu, mx, o);
            int a2 = __shfl_xor_sync(0xffffffffu, arg, o);
            if (m2 > mx || (m2 == mx && a2 < arg)) { mx = m2; arg = a2; }
        }
        float s = 0.f;
        #pragma unroll
        for (int j = 0; j < 32; j++) s += fex2((vv[j] - mx) * LOG2E);
        #pragma unroll
        for (int o = 16; o; o >>= 1) s += __shfl_xor_sync(0xffffffffu, s, o);
        if (lane == 0) {
            g_maxA[row] = mx; g_sumA[row] = s;
            if (arg == (row & 1023)) atomicAdd(&g_correct, 1);
        }
        #pragma unroll
        for (int j = 0; j < 8; j++) {
            float4 f = *(const float4*)(pB + lane * 4 + 128 * j);
            vv[4 * j] = f.x; vv[4 * j + 1] = f.y; vv[4 * j + 2] = f.z; vv[4 * j + 3] = f.w;
        }
        mx = -1e30f;
        #pragma unroll
        for (int j = 0; j < 32; j++) mx = fmaxf(mx, vv[j]);
        #pragma unroll
        for (int o = 16; o; o >>= 1) mx = fmaxf(mx, __shfl_xor_sync(0xffffffffu, mx, o));
        s = 0.f;
        #pragma unroll
        for (int j = 0; j < 32; j++) s += fex2((vv[j] - mx) * LOG2E);
        #pragma unroll
        for (int o = 16; o; o >>= 1) s += __shfl_xor_sync(0xffffffffu, s, o);
        if (lane == 0) { g_maxB[row] = mx; g_sumB[row] = s; }
    }
}

// persistent sinkhorn, warp-autonomous rows; c register-resident per lane
__global__ void __launch_bounds__(512) k_sinkhorn() {
    if (blockIdx.x >= B * SNB) { stats_work(blockIdx.x - B * SNB); return; }
    extern __shared__ float dsm[];
    float* sc = dsm;
    float* sq = dsm + 1024;
    int b = blockIdx.x >> 4, sub = blockIdx.x & 15;
    const float* Mblk = g_scrA + (size_t)(b * 1024 + sub * 64) * N;
    int tid = threadIdx.x, warp = tid >> 5, lane = tid & 31;
    sc[tid] = 0.f;
    sc[tid + 512] = 0.f;
    __syncthreads();

    float rprev[4];
    unsigned bar_t = 0;

    for (int it = 0; it < 30; it++) {
        int par = it & 1;
        float2 cc[16];
        #pragma unroll
        for (int j = 0; j < 16; j++) cc[j] = *(float2*)&sc[2 * lane + 64 * j];
        float2 q[16];
        #pragma unroll
        for (int j = 0; j < 16; j++) q[j] = make_float2(0.f, 0.f);

        #pragma unroll
        for (int ri = 0; ri < 4; ri++) {
            const float2* rowp = (const float2*)(Mblk + (size_t)(warp * 4 + ri) * N);
            float2 e[16];
            float lg;
            if (it == 0) {
                float m = -1e30f;
                #pragma unroll
                for (int j = 0; j < 16; j++) {
                    float2 y = rowp[lane + 32 * j];
                    e[j].x = fmaf(y.x, K2, cc[j].x);
                    e[j].y = fmaf(y.y, K2, cc[j].y);
                    m = fmaxf(m, fmaxf(e[j].x, e[j].y));
                }
                #pragma unroll
                for (int o = 16; o; o >>= 1)
                    m = fmaxf(m, __shfl_xor_sync(0xffffffffu, m, o));
                float s = 0.f;
                #pragma unroll
                for (int j = 0; j < 16; j++) {
                    e[j].x = fex2(e[j].x - m);
                    e[j].y = fex2(e[j].y - m);
                    s += e[j].x + e[j].y;
                }
                #pragma unroll
                for (int o = 16; o; o >>= 1) s += __shfl_xor_sync(0xffffffffu, s, o);
                lg = flg2(s);
                rprev[ri] = -(m + lg);
            } else {
                float rp = rprev[ri];
                float s = 0.f;
                #pragma unroll
                for (int j = 0; j < 16; j++) {
                    float2 y = rowp[lane + 32 * j];
                    e[j].x = fex2(fmaf(y.x, K2, cc[j].x) + rp);
                    e[j].y = fex2(fmaf(y.y, K2, cc[j].y) + rp);
                    s += e[j].x + e[j].y;
                }
                #pragma unroll
                for (int o = 16; o; o >>= 1) s += __shfl_xor_sync(0xffffffffu, s, o);
                lg = flg2(fmaxf(s, 1e-30f));
                rprev[ri] = rp - lg;
            }
            float is = fex2(-lg);
            #pragma unroll
            for (int j = 0; j < 16; j++) {
                q[j].x = fmaf(e[j].x, is, q[j].x);
                q[j].y = fmaf(e[j].y, is, q[j].y);
            }
        }

        #pragma unroll
        for (int j = 0; j < 16; j++)
            *(float2*)&sq[warp * 1024 + 2 * lane + 64 * j] = q[j];
        __syncthreads();
        float s0 = 0.f, s1 = 0.f;
        #pragma unroll
        for (int k = 0; k < 16; k++) {
            float2 t2 = *(float2*)&sq[k * 1024 + 2 * tid];
            s0 += t2.x; s1 += t2.y;
        }
        float* cp = g_cpf + (size_t)par * (B * SNB * N) + (size_t)(b * 16 + sub) * N;
        *(float2*)&cp[2 * tid] = make_float2(s0, s1);
        bar_t += SNB; batch_bar(b, bar_t);

        const float* base = g_cpf + (size_t)par * (B * SNB * N) + (size_t)b * 16 * N;
        #pragma unroll
        for (int h = 0; h < 2; h++) {
            int col = tid + 512 * h;
            float s = 0.f;
            #pragma unroll
            for (int k = 0; k < 16; k++) s += base[(size_t)k * N + col];
            sc[col] = sc[col] - flg2(fmaxf(s, 1e-30f));
        }
        __syncthreads();
    }

    if (lane == 0) {
        #pragma unroll
        for (int ri = 0; ri < 4; ri++)
            g_r[b * N + sub * 64 + warp * 4 + ri] = rprev[ri];
    }
    if (tid < 64) g_c[b * N + sub * 64 + tid] = sc[sub * 64 + tid];
}

// ---------------------------------------------------------------------------
// fused final pass: 4 rows per block
__global__ void __launch_bounds__(256) k_final(const float* __restrict__ pc0) {
    int quad = blockIdx.x;
    int b = quad >> 8;
    int n0 = (quad & 255) * 4;
    int tid = threadIdx.x, lane = tid & 31, warp = tid >> 5;

    __shared__ float spc[3 * 1024];
    __shared__ float scv[1024];
    __shared__ float s1[8], s2[8], s3[8];
    const float* pc = pc0 + (size_t)b * N * 3;
    for (int i = tid; i < 3 * 1024; i += 256) spc[i] = pc[i];
    for (int i = tid; i < 1024; i += 256) scv[i] = g_c[b * N + i];
    __syncthreads();

    #pragma unroll
    for (int rr = 0; rr < 4; rr++) {
        int n = n0 + rr;
        size_t row = (size_t)b * N + n;
        const float* pA = g_scrA + row * N;
        const float* pB = g_scrB + row * N;
        float mA = g_maxA[row], iA = 1.0f / g_sumA[row];
        float mB = g_maxB[row], iB = 1.0f / g_sumB[row];
        float rn = g_r[row];
        float px = spc[3 * n], py = spc[3 * n + 1], pz = spc[3 * n + 2];
        float aL = 0.f, aC = 0.f, aP = 0.f;
        #pragma unroll
        for (int t = 0; t < 4; t++) {
            int m = tid + 256 * t;
            float xA = pA[m], xB = pB[m];
            float smA = fex2((xA - mA) * LOG2E) * iA;
            float smB = fex2((xB - mB) * LOG2E) * iB;
            float dx = px - spc[3 * m], dy = py - spc[3 * m + 1], dz = pz - spc[3 * m + 2];
            float d2 = dx * dx + dy * dy + dz * dz;
            float dist = sqrtf(sqrtf(d2));
            aL += dist * (smA + smB);
            float sink = fex2(xA * K2 + rn + scv[m]);
            aC += fabsf(sink - smA);
            aP += (m == n) ? fabsf(1.0f - sink) : sink;
        }
        #pragma unroll
        for (int o = 16; o; o >>= 1) {
            aL += __shfl_xor_sync(0xffffffffu, aL, o);
            aC += __shfl_xor_sync(0xffffffffu, aC, o);
            aP += __shfl_xor_sync(0xffffffffu, aP, o);
        }
        if (lane == 0) { s1[warp] = aL; s2[warp] = aC; s3[warp] = aP; }
        __syncthreads();
        if (tid == 0) {
            float tL = 0.f, tC = 0.f, tP = 0.f;
            #pragma unroll
            for (int q = 0; q < 8; q++) { tL += s1[q]; tC += s2[q]; tP += s3[q]; }
            g_pL[row] = tL; g_pC[row] = tC; g_pP[row] = tP;
        }
        __syncthreads();
    }
}

// ---------------------------------------------------------------------------
__global__ void __launch_bounds__(256) k_out(float* __restrict__ out) {
    int tid = threadIdx.x;
    float sL = 0.f, sC = 0.f, sP = 0.f;
    for (int i = tid; i < B * N; i += 256) {
        sL += g_pL[i]; sC += g_pC[i]; sP += g_pP[i];
    }
    #pragma unroll
    for (int o = 16; o; o >>= 1) {
        sL += __shfl_xor_sync(0xffffffffu, sL, o);
        sC += __shfl_xor_sync(0xffffffffu, sC, o);
        sP += __shfl_xor_sync(0xffffffffu, sP, o);
    }
    __shared__ float s1[8], s2[8], s3[8];
    if ((tid & 31) == 0) { s1[tid >> 5] = sL; s2[tid >> 5] = sC; s3[tid >> 5] = sP; }
    __syncthreads();
    if (tid == 0) {
        float tL = 0.f, tC = 0.f, tP = 0.f;
        #pragma unroll
        for (int q = 0; q < 8; q++) { tL += s1[q]; tC += s2[q]; tP += s3[q]; }
        float invN = 1.0f / (float)N;
        float loss = tL * invN;
        float Lc = 3.0f * tC * invN;
        float perm = 3.0f * tP * invN;
        float corr = (float)g_correct;
        float invB = 1.0f / (float)B;
        out[0] = (loss + Lc) * invB;
        out[1] = loss * invB;
        out[2] = Lc * invB;
        out[3] = corr * invB;
        out[4] = perm * invB;
    }
}

// ---------------------------------------------------------------------------
extern "C" void kernel_launch(void* const* d_in, const int* in_sizes, int n_in,
                              void* d_out, int out_size) {
    const float* feats = (const float*)d_in[0];
    const float* pc0 = (const float*)d_in[1];
    float* out = (float*)d_out;

    const int nt_smem = 4 * TSZ * sizeof(__nv_bfloat16);
    const int nt12_smem = NT12_ELEMS * sizeof(__nv_bfloat16);    // 110592
    const int nn_smem = 2 * NN_ELEMS * sizeof(__nv_bfloat16);    // 106496
    static bool attr_done = false;
    if (!attr_done) {
        cudaFuncSetAttribute(k_hmma_nt0, cudaFuncAttributeMaxDynamicSharedMemorySize,
                             nt_smem);
        cudaFuncSetAttribute(k_hmma_nt12, cudaFuncAttributeMaxDynamicSharedMemorySize,
                             nt12_smem);
        cudaFuncSetAttribute(k_hmma_nn, cudaFuncAttributeMaxDynamicSharedMemorySize,
                             nn_smem);
        cudaFuncSetAttribute(k_sinkhorn, cudaFuncAttributeMaxDynamicSharedMemorySize,
                             SINK_SMEM);
        attr_done = true;
    }

    k_norm<<<2 * B * N, 128>>>(feats);                  // + state reset
    k_hmma_nt0<<<dim3(8, 8, 8), 256, nt_smem>>>();      // corr_1a -> scrA
    k_rowsoftmax<<<B * N, 256>>>();                     // smcorr hi/lo bf16
    k_hmma_nn<<<dim3(16, 4, 8), 256, nn_smem>>>();      // via partials
    k_via_combine<<<B * N * C / 256, 256>>>();          // partials -> hi/lo
    k_hmma_nt12<<<dim3(8, 8, 8), 256, nt12_smem>>>();   // corr_1a2 + corr_12
    k_sinkhorn<<<B * SNB + STATS_BLKS, 512, SINK_SMEM>>>();
    k_final<<<B * N / 4, 256>>>(pc0);
    k_out<<<1, 256>>>(out);
}